// round 1
// baseline (speedup 1.0000x reference)
#include <cuda_runtime.h>
#include <math.h>
#include <stdint.h>

#define BB 8
#define SS 1024
#define HID 768
#define NH 12
#define HD 64
#define MROWS (BB*SS)   // 8192

// ---------------- scratch (device globals; no allocation allowed) ----------------
__device__ float g_Q[(size_t)MROWS*HID];
__device__ float g_K[(size_t)MROWS*HID];
__device__ float g_V[(size_t)MROWS*HID];
__device__ float g_att[(size_t)MROWS*HID];   // attention @ V, [B,S,NH*HD] layout
__device__ float g_xo[(size_t)MROWS*HID];    // after Wo projection

// ---------------- generic tiled GEMM:  C[M,N] = A[M,K] @ W[K,N] + bias ----------------
// TILE 64x64x16, 256 threads, 4x4 register blocking per thread.
__global__ __launch_bounds__(256) void gemm_bias_kernel(
    const float* __restrict__ A, const float* __restrict__ W,
    const float* __restrict__ bias, float* __restrict__ C,
    int M, int N, int K)
{
    __shared__ float As[64][17];   // [row][k]  (pad 17 -> conflict-free writes)
    __shared__ float Ws[16][64];   // [k][col]

    int tid = threadIdx.x;
    int tx = tid & 15;        // 16 col-groups of 4
    int ty = tid >> 4;        // 16 row-groups of 4
    int m0 = blockIdx.y * 64;
    int n0 = blockIdx.x * 64;

    float acc[4][4];
    #pragma unroll
    for (int i = 0; i < 4; i++)
        #pragma unroll
        for (int j = 0; j < 4; j++) acc[i][j] = 0.f;

    for (int k0 = 0; k0 < K; k0 += 16) {
        #pragma unroll
        for (int i = 0; i < 4; i++) {
            int idx = tid + i * 256;
            int r = idx >> 4, c = idx & 15;
            As[r][c] = A[(size_t)(m0 + r) * K + k0 + c];
        }
        #pragma unroll
        for (int i = 0; i < 4; i++) {
            int idx = tid + i * 256;
            int r = idx & 63, c = idx >> 6;   // c: 0..15
            Ws[c][r] = W[(size_t)(k0 + c) * N + n0 + r];
        }
        __syncthreads();
        #pragma unroll
        for (int kk = 0; kk < 16; kk++) {
            float4 b4 = *(const float4*)&Ws[kk][tx * 4];
            float a0 = As[ty * 4 + 0][kk];
            float a1 = As[ty * 4 + 1][kk];
            float a2 = As[ty * 4 + 2][kk];
            float a3 = As[ty * 4 + 3][kk];
            acc[0][0] += a0 * b4.x; acc[0][1] += a0 * b4.y; acc[0][2] += a0 * b4.z; acc[0][3] += a0 * b4.w;
            acc[1][0] += a1 * b4.x; acc[1][1] += a1 * b4.y; acc[1][2] += a1 * b4.z; acc[1][3] += a1 * b4.w;
            acc[2][0] += a2 * b4.x; acc[2][1] += a2 * b4.y; acc[2][2] += a2 * b4.z; acc[2][3] += a2 * b4.w;
            acc[3][0] += a3 * b4.x; acc[3][1] += a3 * b4.y; acc[3][2] += a3 * b4.z; acc[3][3] += a3 * b4.w;
        }
        __syncthreads();
    }

    #pragma unroll
    for (int i = 0; i < 4; i++) {
        int m = m0 + ty * 4 + i;
        #pragma unroll
        for (int j = 0; j < 4; j++) {
            int n = n0 + tx * 4 + j;
            C[(size_t)m * N + n] = acc[i][j] + bias[n];
        }
    }
}

// ---------------- fused attention ----------------
// One CTA per (b, h, 32-query tile). Scores [32][1024] live in dynamic smem.
// Phase 1: energy = (Q/8) @ K^T, masked.  Phase 2: softmax (+write attention
// rows to gmem output).  Phase 3: x = P @ V.
__global__ __launch_bounds__(256) void attn_kernel(
    const float* __restrict__ Q, const float* __restrict__ Km,
    const float* __restrict__ V, const int* __restrict__ mask,
    float* __restrict__ attn_out, float* __restrict__ x_out)
{
    extern __shared__ float sm[];
    float* scores = sm;                  // 32*1024
    float* Qs     = sm + 32 * 1024;      // 32*64
    float* KVs    = Qs + 32 * 64;        // 64*68

    int tid = threadIdx.x;
    int tn = tid & 15;    // -> 4 key/val cols each
    int tm = tid >> 4;    // -> 2 query rows each
    int q0 = blockIdx.x * 32;
    int h  = blockIdx.y;
    int b  = blockIdx.z;

    // load Q tile (pre-scaled by 1/sqrt(64))
    for (int idx = tid; idx < 32 * 64; idx += 256) {
        int r = idx >> 6, c = idx & 63;
        Qs[idx] = Q[(size_t)(b * SS + q0 + r) * HID + h * HD + c] * 0.125f;
    }

    // ---- Phase 1: QK^T ----
    for (int kt = 0; kt < SS; kt += 64) {
        __syncthreads();
        // K tile transposed: KVs[d][key], stride 68
        for (int idx = tid; idx < 64 * 64; idx += 256) {
            int kk = idx >> 6, c = idx & 63;
            KVs[c * 68 + kk] = Km[(size_t)(b * SS + kt + kk) * HID + h * HD + c];
        }
        __syncthreads();

        float acc[2][4];
        acc[0][0]=acc[0][1]=acc[0][2]=acc[0][3]=0.f;
        acc[1][0]=acc[1][1]=acc[1][2]=acc[1][3]=0.f;
        #pragma unroll 8
        for (int d = 0; d < 64; d++) {
            float4 kb = *(const float4*)(KVs + d * 68 + tn * 4);
            float a0 = Qs[(tm * 2 + 0) * 64 + d];
            float a1 = Qs[(tm * 2 + 1) * 64 + d];
            acc[0][0] += a0 * kb.x; acc[0][1] += a0 * kb.y; acc[0][2] += a0 * kb.z; acc[0][3] += a0 * kb.w;
            acc[1][0] += a1 * kb.x; acc[1][1] += a1 * kb.y; acc[1][2] += a1 * kb.z; acc[1][3] += a1 * kb.w;
        }
        #pragma unroll
        for (int i = 0; i < 2; i++)
            #pragma unroll
            for (int j = 0; j < 4; j++) {
                int k = kt + tn * 4 + j;
                float v = (mask[b * SS + k] == 0) ? -1e10f : acc[i][j];
                scores[(tm * 2 + i) * SS + k] = v;
            }
    }
    __syncthreads();

    // ---- Phase 2: softmax per row, write attention to gmem ----
    int lane = tid & 31, warp = tid >> 5;
    for (int r = warp * 4; r < warp * 4 + 4; r++) {
        float* row = scores + r * SS;
        float mx = -3.4e38f;
        for (int k = lane; k < SS; k += 32) mx = fmaxf(mx, row[k]);
        #pragma unroll
        for (int o = 16; o > 0; o >>= 1) mx = fmaxf(mx, __shfl_xor_sync(0xffffffffu, mx, o));
        float sum = 0.f;
        for (int k = lane; k < SS; k += 32) { float e = __expf(row[k] - mx); row[k] = e; sum += e; }
        #pragma unroll
        for (int o = 16; o > 0; o >>= 1) sum += __shfl_xor_sync(0xffffffffu, sum, o);
        float inv = 1.f / sum;
        float* orow = attn_out + ((size_t)((b * NH + h) * SS + q0 + r)) * SS;
        for (int k = lane; k < SS; k += 32) { float p = row[k] * inv; row[k] = p; orow[k] = p; }
    }

    // ---- Phase 3: x = P @ V ----
    float xacc[2][4];
    xacc[0][0]=xacc[0][1]=xacc[0][2]=xacc[0][3]=0.f;
    xacc[1][0]=xacc[1][1]=xacc[1][2]=xacc[1][3]=0.f;
    for (int kt = 0; kt < SS; kt += 64) {
        __syncthreads();   // also orders softmax completion before first use
        // V tile natural: KVs[key][d], stride 68
        for (int idx = tid; idx < 64 * 64; idx += 256) {
            int kk = idx >> 6, c = idx & 63;
            KVs[kk * 68 + c] = V[(size_t)(b * SS + kt + kk) * HID + h * HD + c];
        }
        __syncthreads();
        #pragma unroll 8
        for (int k = 0; k < 64; k++) {
            float4 vb = *(const float4*)(KVs + k * 68 + tn * 4);
            float p0 = scores[(tm * 2 + 0) * SS + kt + k];
            float p1 = scores[(tm * 2 + 1) * SS + kt + k];
            xacc[0][0] += p0 * vb.x; xacc[0][1] += p0 * vb.y; xacc[0][2] += p0 * vb.z; xacc[0][3] += p0 * vb.w;
            xacc[1][0] += p1 * vb.x; xacc[1][1] += p1 * vb.y; xacc[1][2] += p1 * vb.z; xacc[1][3] += p1 * vb.w;
        }
    }
    #pragma unroll
    for (int i = 0; i < 2; i++)
        #pragma unroll
        for (int j = 0; j < 4; j++)
            x_out[(size_t)(b * SS + q0 + tm * 2 + i) * HID + h * HD + tn * 4 + j] = xacc[i][j];
}

// ---------------- fused FFN: concat([xo, query]) -> dual GEMM -> sigmoid gate ----------------
__global__ __launch_bounds__(256) void ffn_kernel(
    const float* __restrict__ X, const float* __restrict__ Qin,
    const float* __restrict__ W1, const float* __restrict__ b1,
    const float* __restrict__ W2, const float* __restrict__ b2,
    float* __restrict__ Out)
{
    __shared__ float As[64][17];
    __shared__ float W1s[16][64];
    __shared__ float W2s[16][64];

    const int N = HID, K = 2 * HID;
    int tid = threadIdx.x;
    int tx = tid & 15, ty = tid >> 4;
    int m0 = blockIdx.y * 64;
    int n0 = blockIdx.x * 64;

    float acc1[4][4], acc2[4][4];
    #pragma unroll
    for (int i = 0; i < 4; i++)
        #pragma unroll
        for (int j = 0; j < 4; j++) { acc1[i][j] = 0.f; acc2[i][j] = 0.f; }

    for (int k0 = 0; k0 < K; k0 += 16) {
        const float* Asrc = (k0 < HID) ? X : Qin;
        int kk0 = (k0 < HID) ? k0 : (k0 - HID);
        #pragma unroll
        for (int i = 0; i < 4; i++) {
            int idx = tid + i * 256;
            int r = idx >> 4, c = idx & 15;
            As[r][c] = Asrc[(size_t)(m0 + r) * HID + kk0 + c];
        }
        #pragma unroll
        for (int i = 0; i < 4; i++) {
            int idx = tid + i * 256;
            int r = idx & 63, c = idx >> 6;
            W1s[c][r] = W1[(size_t)(k0 + c) * N + n0 + r];
            W2s[c][r] = W2[(size_t)(k0 + c) * N + n0 + r];
        }
        __syncthreads();
        #pragma unroll
        for (int kk = 0; kk < 16; kk++) {
            float4 u4 = *(const float4*)&W1s[kk][tx * 4];
            float4 v4 = *(const float4*)&W2s[kk][tx * 4];
            #pragma unroll
            for (int i = 0; i < 4; i++) {
                float a = As[ty * 4 + i][kk];
                acc1[i][0] += a * u4.x; acc1[i][1] += a * u4.y; acc1[i][2] += a * u4.z; acc1[i][3] += a * u4.w;
                acc2[i][0] += a * v4.x; acc2[i][1] += a * v4.y; acc2[i][2] += a * v4.z; acc2[i][3] += a * v4.w;
            }
        }
        __syncthreads();
    }

    #pragma unroll
    for (int i = 0; i < 4; i++) {
        int m = m0 + ty * 4 + i;
        #pragma unroll
        for (int j = 0; j < 4; j++) {
            int n = n0 + tx * 4 + j;
            float g = acc1[i][j] + b1[n];
            float v = acc2[i][j] + b2[n];
            float s = 1.f / (1.f + __expf(-g));
            Out[(size_t)m * N + n] = s * v;
        }
    }
}

// ---------------- launch ----------------
extern "C" void kernel_launch(void* const* d_in, const int* in_sizes, int n_in,
                              void* d_out, int out_size)
{
    const float* query = (const float*)d_in[0];
    const float* key_t = (const float*)d_in[1];
    const float* value = (const float*)d_in[2];
    const int*   mask  = (const int*)d_in[3];
    const float* Wq = (const float*)d_in[4];  const float* bq = (const float*)d_in[5];
    const float* Wk = (const float*)d_in[6];  const float* bk = (const float*)d_in[7];
    const float* Wv = (const float*)d_in[8];  const float* bv = (const float*)d_in[9];
    const float* Wo = (const float*)d_in[10]; const float* bo = (const float*)d_in[11];
    const float* W1 = (const float*)d_in[12]; const float* b1 = (const float*)d_in[13];
    const float* W2 = (const float*)d_in[14]; const float* b2 = (const float*)d_in[15];

    float* out       = (float*)d_out;
    float* out_gated = out;                                   // [B,S,HID]
    float* out_attn  = out + (size_t)MROWS * HID;             // [B,NH,S,S]

    float *Qb, *Kb, *Vb, *Ab, *Xo;
    cudaGetSymbolAddress((void**)&Qb, g_Q);
    cudaGetSymbolAddress((void**)&Kb, g_K);
    cudaGetSymbolAddress((void**)&Vb, g_V);
    cudaGetSymbolAddress((void**)&Ab, g_att);
    cudaGetSymbolAddress((void**)&Xo, g_xo);

    dim3 ggrid(HID / 64, MROWS / 64);   // (12, 128)

    gemm_bias_kernel<<<ggrid, 256>>>(query, Wq, bq, Qb, MROWS, HID, HID);
    gemm_bias_kernel<<<ggrid, 256>>>(key_t, Wk, bk, Kb, MROWS, HID, HID);
    gemm_bias_kernel<<<ggrid, 256>>>(value, Wv, bv, Vb, MROWS, HID, HID);

    size_t smem = (32 * 1024 + 32 * 64 + 64 * 68) * sizeof(float);  // 156,672 B
    cudaFuncSetAttribute(attn_kernel, cudaFuncAttributeMaxDynamicSharedMemorySize, 160 * 1024);
    attn_kernel<<<dim3(SS / 32, NH, BB), 256, smem>>>(Qb, Kb, Vb, mask, out_attn, Ab);

    gemm_bias_kernel<<<ggrid, 256>>>(Ab, Wo, bo, Xo, MROWS, HID, HID);

    ffn_kernel<<<ggrid, 256>>>(Xo, query, W1, b1, W2, b2, out_gated);
}

// round 3
// speedup vs baseline: 1.4292x; 1.4292x over previous
#include <cuda_runtime.h>
#include <cuda_bf16.h>
#include <math.h>
#include <stdint.h>

#define BB 8
#define SS 1024
#define HID 768
#define NH 12
#define HD 64
#define MROWS (BB*SS)   // 8192

// ---------------- scratch (device globals; no allocation allowed) ----------------
__device__ __align__(256) float g_Q [(size_t)MROWS*HID];
__device__ __align__(256) float g_K [(size_t)MROWS*HID];
__device__ __align__(256) float g_V [(size_t)MROWS*HID];
__device__ __align__(256) float g_att[(size_t)MROWS*HID];
__device__ __align__(256) float g_xo [(size_t)MROWS*HID];
__device__ __align__(256) float g_f1 [(size_t)MROWS*HID];

__device__ __align__(256) __nv_bfloat16 g_ahi[(size_t)MROWS*2*HID];
__device__ __align__(256) __nv_bfloat16 g_alo[(size_t)MROWS*2*HID];
__device__ __align__(256) __nv_bfloat16 g_whi[(size_t)2*HID*HID];   // [N][K] transposed
__device__ __align__(256) __nv_bfloat16 g_wlo[(size_t)2*HID*HID];

// ================= helpers =================
__device__ __forceinline__ uint32_t smem_u32(const void* p) {
    uint32_t a;
    asm("{ .reg .u64 t; cvta.to.shared.u64 t, %1; cvt.u32.u64 %0, t; }" : "=r"(a) : "l"(p));
    return a;
}
__device__ __forceinline__ void ldsm_x4(uint32_t* r, uint32_t addr) {
    asm volatile("ldmatrix.sync.aligned.m8n8.x4.shared.b16 {%0,%1,%2,%3}, [%4];"
                 : "=r"(r[0]), "=r"(r[1]), "=r"(r[2]), "=r"(r[3]) : "r"(addr));
}
__device__ __forceinline__ void mma16816(float* c, const uint32_t* a, uint32_t b0, uint32_t b1) {
    asm volatile("mma.sync.aligned.m16n8k16.row.col.f32.bf16.bf16.f32 "
                 "{%0,%1,%2,%3}, {%4,%5,%6,%7}, {%8,%9}, {%0,%1,%2,%3};"
                 : "+f"(c[0]), "+f"(c[1]), "+f"(c[2]), "+f"(c[3])
                 : "r"(a[0]), "r"(a[1]), "r"(a[2]), "r"(a[3]), "r"(b0), "r"(b1));
}

// ================= split kernels =================
__global__ void split_act(const float* __restrict__ src, int M, int Ksrc,
                          __nv_bfloat16* __restrict__ hi, __nv_bfloat16* __restrict__ lo,
                          int dstStride, int colOff)
{
    size_t total = (size_t)M * Ksrc / 4;
    for (size_t i = (size_t)blockIdx.x * blockDim.x + threadIdx.x; i < total;
         i += (size_t)gridDim.x * blockDim.x) {
        size_t e = i * 4;
        int m = (int)(e / Ksrc), c = (int)(e % Ksrc);
        float4 v = *(const float4*)(src + e);
        __nv_bfloat16 h0 = __float2bfloat16(v.x), h1 = __float2bfloat16(v.y);
        __nv_bfloat16 h2 = __float2bfloat16(v.z), h3 = __float2bfloat16(v.w);
        __nv_bfloat16 l0 = __float2bfloat16(v.x - __bfloat162float(h0));
        __nv_bfloat16 l1 = __float2bfloat16(v.y - __bfloat162float(h1));
        __nv_bfloat16 l2 = __float2bfloat16(v.z - __bfloat162float(h2));
        __nv_bfloat16 l3 = __float2bfloat16(v.w - __bfloat162float(h3));
        size_t d = (size_t)m * dstStride + colOff + c;
        *(__nv_bfloat162*)(hi + d)     = __nv_bfloat162(h0, h1);
        *(__nv_bfloat162*)(hi + d + 2) = __nv_bfloat162(h2, h3);
        *(__nv_bfloat162*)(lo + d)     = __nv_bfloat162(l0, l1);
        *(__nv_bfloat162*)(lo + d + 2) = __nv_bfloat162(l2, l3);
    }
}

__global__ void split_w(const float* __restrict__ W, int K, int N,
                        __nv_bfloat16* __restrict__ hi, __nv_bfloat16* __restrict__ lo)
{
    __shared__ float t[32][33];
    int n0 = blockIdx.x * 32, k0 = blockIdx.y * 32;
    int tx = threadIdx.x, ty = threadIdx.y;
    for (int j = ty; j < 32; j += 8)
        t[j][tx] = W[(size_t)(k0 + j) * N + n0 + tx];
    __syncthreads();
    for (int j = ty; j < 32; j += 8) {
        float x = t[tx][j];
        __nv_bfloat16 h = __float2bfloat16(x);
        __nv_bfloat16 l = __float2bfloat16(x - __bfloat162float(h));
        size_t d = (size_t)(n0 + j) * K + k0 + tx;
        hi[d] = h; lo[d] = l;
    }
}

// ================= mma.sync bf16x3 GEMM =================
// C[M][768], CTA tile 128x128, K-chunk 64. A(hi/lo) [M][K], B(hi/lo) [N][K].
// smem: 4 buffers of 128 rows x 72 bf16 (pad 64->72 => conflict-free ldmatrix)
#define GSTRIDE 72
#define GBUF (128 * GSTRIDE)   // elements per buffer

__global__ __launch_bounds__(256) void gemm_mma(
    const __nv_bfloat16* __restrict__ Ahi, const __nv_bfloat16* __restrict__ Alo,
    const __nv_bfloat16* __restrict__ Bhi, const __nv_bfloat16* __restrict__ Blo,
    int Kdim, const float* __restrict__ bias, const float* __restrict__ prev,
    float* __restrict__ C, int mode)
{
    extern __shared__ __nv_bfloat16 sm[];
    __nv_bfloat16* sAhi = sm;
    __nv_bfloat16* sAlo = sm + GBUF;
    __nv_bfloat16* sBhi = sm + 2 * GBUF;
    __nv_bfloat16* sBlo = sm + 3 * GBUF;

    const int tid = threadIdx.x;
    const int w = tid >> 5, l = tid & 31;
    const int m0 = blockIdx.y * 128;
    const int n0 = blockIdx.x * 128;
    const int wm = (w >> 2) * 64;    // warp row offset within tile
    const int wn = (w & 3) * 32;     // warp col offset within tile

    float c[4][4][4];
    #pragma unroll
    for (int i = 0; i < 4; i++)
        #pragma unroll
        for (int j = 0; j < 4; j++)
            #pragma unroll
            for (int q = 0; q < 4; q++) c[i][j][q] = 0.f;

    // ldmatrix lane address components
    const int aRow = wm + (l & 15);
    const int aKof = (l >> 4) * 8;
    const int bRow = wn + (l >> 4) * 8 + (l & 7);
    const int bKof = ((l >> 3) & 1) * 8;

    const uint32_t aHiB = smem_u32(sAhi) + (uint32_t)(aRow * GSTRIDE + aKof) * 2;
    const uint32_t aLoB = smem_u32(sAlo) + (uint32_t)(aRow * GSTRIDE + aKof) * 2;
    const uint32_t bHiB = smem_u32(sBhi) + (uint32_t)(bRow * GSTRIDE + bKof) * 2;
    const uint32_t bLoB = smem_u32(sBlo) + (uint32_t)(bRow * GSTRIDE + bKof) * 2;

    const int nChunks = Kdim >> 6;
    for (int ch = 0; ch < nChunks; ch++) {
        const int k0 = ch << 6;
        // ---- global -> smem: 128 rows x 64 cols per buffer ----
        #pragma unroll
        for (int i = 0; i < 4; i++) {
            int t = tid + i * 256;        // 0..1023
            int row = t >> 3, c8 = (t & 7) * 8;
            size_t ga = (size_t)(m0 + row) * Kdim + k0 + c8;
            size_t gb = (size_t)(n0 + row) * Kdim + k0 + c8;
            int d = row * GSTRIDE + c8;
            *(uint4*)(sAhi + d) = *(const uint4*)(Ahi + ga);
            *(uint4*)(sAlo + d) = *(const uint4*)(Alo + ga);
            *(uint4*)(sBhi + d) = *(const uint4*)(Bhi + gb);
            *(uint4*)(sBlo + d) = *(const uint4*)(Blo + gb);
        }
        __syncthreads();

        #pragma unroll
        for (int ks = 0; ks < 4; ks++) {
            const uint32_t kb = (uint32_t)(ks * 16 * 2);   // byte offset for this kstep
            uint32_t ah[4][4], al[4][4], bh[2][4], bl[2][4];
            #pragma unroll
            for (int mi = 0; mi < 4; mi++) {
                ldsm_x4(ah[mi], aHiB + (uint32_t)(mi * 16 * GSTRIDE * 2) + kb);
                ldsm_x4(al[mi], aLoB + (uint32_t)(mi * 16 * GSTRIDE * 2) + kb);
            }
            #pragma unroll
            for (int p = 0; p < 2; p++) {
                ldsm_x4(bh[p], bHiB + (uint32_t)(p * 16 * GSTRIDE * 2) + kb);
                ldsm_x4(bl[p], bLoB + (uint32_t)(p * 16 * GSTRIDE * 2) + kb);
            }
            #pragma unroll
            for (int mi = 0; mi < 4; mi++) {
                #pragma unroll
                for (int nj = 0; nj < 4; nj++) {
                    const int p = nj >> 1, s = (nj & 1) * 2;
                    mma16816(c[mi][nj], ah[mi], bh[p][s], bh[p][s + 1]);
                    mma16816(c[mi][nj], ah[mi], bl[p][s], bl[p][s + 1]);
                    mma16816(c[mi][nj], al[mi], bh[p][s], bh[p][s + 1]);
                }
            }
        }
        __syncthreads();
    }

    // ---- epilogue: bias (+ optional sigmoid gate), direct stores ----
    const int Nn = HID;
    #pragma unroll
    for (int mi = 0; mi < 4; mi++) {
        int r0 = m0 + wm + mi * 16 + (l >> 2);
        #pragma unroll
        for (int nj = 0; nj < 4; nj++) {
            int col = n0 + wn + nj * 8 + (l & 3) * 2;
            float b0 = bias[col], b1 = bias[col + 1];
            #pragma unroll
            for (int half = 0; half < 2; half++) {
                int r = r0 + half * 8;
                float v0 = c[mi][nj][half * 2 + 0] + b0;
                float v1 = c[mi][nj][half * 2 + 1] + b1;
                if (mode == 1) {
                    float g0 = prev[(size_t)r * Nn + col];
                    float g1 = prev[(size_t)r * Nn + col + 1];
                    v0 *= 1.f / (1.f + __expf(-g0));
                    v1 *= 1.f / (1.f + __expf(-g1));
                }
                *(float2*)(C + (size_t)r * Nn + col) = make_float2(v0, v1);
            }
        }
    }
}

// ================= fused attention (SIMT) =================
__global__ __launch_bounds__(256) void attn_kernel(
    const float* __restrict__ Q, const float* __restrict__ Km,
    const float* __restrict__ V, const int* __restrict__ mask,
    float* __restrict__ attn_out, float* __restrict__ x_out)
{
    extern __shared__ float smf[];
    float* scores = smf;
    float* Qs     = smf + 32 * 1024;
    float* KVs    = Qs + 32 * 64;

    int tid = threadIdx.x;
    int tn = tid & 15;
    int tm = tid >> 4;
    int q0 = blockIdx.x * 32;
    int h  = blockIdx.y;
    int b  = blockIdx.z;

    for (int idx = tid; idx < 32 * 64; idx += 256) {
        int r = idx >> 6, c = idx & 63;
        Qs[idx] = Q[(size_t)(b * SS + q0 + r) * HID + h * HD + c] * 0.125f;
    }

    for (int kt = 0; kt < SS; kt += 64) {
        __syncthreads();
        for (int idx = tid; idx < 64 * 64; idx += 256) {
            int kk = idx >> 6, c = idx & 63;
            KVs[c * 68 + kk] = Km[(size_t)(b * SS + kt + kk) * HID + h * HD + c];
        }
        __syncthreads();

        float acc[2][4];
        acc[0][0]=acc[0][1]=acc[0][2]=acc[0][3]=0.f;
        acc[1][0]=acc[1][1]=acc[1][2]=acc[1][3]=0.f;
        #pragma unroll 8
        for (int d = 0; d < 64; d++) {
            float4 kb = *(const float4*)(KVs + d * 68 + tn * 4);
            float a0 = Qs[(tm * 2 + 0) * 64 + d];
            float a1 = Qs[(tm * 2 + 1) * 64 + d];
            acc[0][0] += a0 * kb.x; acc[0][1] += a0 * kb.y; acc[0][2] += a0 * kb.z; acc[0][3] += a0 * kb.w;
            acc[1][0] += a1 * kb.x; acc[1][1] += a1 * kb.y; acc[1][2] += a1 * kb.z; acc[1][3] += a1 * kb.w;
        }
        #pragma unroll
        for (int i = 0; i < 2; i++)
            #pragma unroll
            for (int j = 0; j < 4; j++) {
                int k = kt + tn * 4 + j;
                float v = (mask[b * SS + k] == 0) ? -1e10f : acc[i][j];
                scores[(tm * 2 + i) * SS + k] = v;
            }
    }
    __syncthreads();

    int lane = tid & 31, warp = tid >> 5;
    for (int r = warp * 4; r < warp * 4 + 4; r++) {
        float* row = scores + r * SS;
        float mx = -3.4e38f;
        for (int k = lane; k < SS; k += 32) mx = fmaxf(mx, row[k]);
        #pragma unroll
        for (int o = 16; o > 0; o >>= 1) mx = fmaxf(mx, __shfl_xor_sync(0xffffffffu, mx, o));
        float sum = 0.f;
        for (int k = lane; k < SS; k += 32) { float e = __expf(row[k] - mx); row[k] = e; sum += e; }
        #pragma unroll
        for (int o = 16; o > 0; o >>= 1) sum += __shfl_xor_sync(0xffffffffu, sum, o);
        float inv = 1.f / sum;
        float* orow = attn_out + ((size_t)((b * NH + h) * SS + q0 + r)) * SS;
        for (int k = lane; k < SS; k += 32) { float p = row[k] * inv; row[k] = p; orow[k] = p; }
    }

    float xacc[2][4];
    xacc[0][0]=xacc[0][1]=xacc[0][2]=xacc[0][3]=0.f;
    xacc[1][0]=xacc[1][1]=xacc[1][2]=xacc[1][3]=0.f;
    for (int kt = 0; kt < SS; kt += 64) {
        __syncthreads();
        for (int idx = tid; idx < 64 * 64; idx += 256) {
            int kk = idx >> 6, c = idx & 63;
            KVs[kk * 68 + c] = V[(size_t)(b * SS + kt + kk) * HID + h * HD + c];
        }
        __syncthreads();
        #pragma unroll 8
        for (int k = 0; k < 64; k++) {
            float4 vb = *(const float4*)(KVs + k * 68 + tn * 4);
            float p0 = scores[(tm * 2 + 0) * SS + kt + k];
            float p1 = scores[(tm * 2 + 1) * SS + kt + k];
            xacc[0][0] += p0 * vb.x; xacc[0][1] += p0 * vb.y; xacc[0][2] += p0 * vb.z; xacc[0][3] += p0 * vb.w;
            xacc[1][0] += p1 * vb.x; xacc[1][1] += p1 * vb.y; xacc[1][2] += p1 * vb.z; xacc[1][3] += p1 * vb.w;
        }
    }
    #pragma unroll
    for (int i = 0; i < 2; i++)
        #pragma unroll
        for (int j = 0; j < 4; j++)
            x_out[(size_t)(b * SS + q0 + tm * 2 + i) * HID + h * HD + tn * 4 + j] = xacc[i][j];
}

// ================= launch =================
extern "C" void kernel_launch(void* const* d_in, const int* in_sizes, int n_in,
                              void* d_out, int out_size)
{
    const float* query = (const float*)d_in[0];
    const float* key_t = (const float*)d_in[1];
    const float* value = (const float*)d_in[2];
    const int*   mask  = (const int*)d_in[3];
    const float* Wq = (const float*)d_in[4];  const float* bq = (const float*)d_in[5];
    const float* Wk = (const float*)d_in[6];  const float* bk = (const float*)d_in[7];
    const float* Wv = (const float*)d_in[8];  const float* bv = (const float*)d_in[9];
    const float* Wo = (const float*)d_in[10]; const float* bo = (const float*)d_in[11];
    const float* W1 = (const float*)d_in[12]; const float* b1 = (const float*)d_in[13];
    const float* W2 = (const float*)d_in[14]; const float* b2 = (const float*)d_in[15];

    float* out       = (float*)d_out;
    float* out_gated = out;
    float* out_attn  = out + (size_t)MROWS * HID;

    float *Qb, *Kb, *Vb, *Ab, *Xo, *F1;
    __nv_bfloat16 *ahi, *alo, *whi, *wlo;
    cudaGetSymbolAddress((void**)&Qb, g_Q);
    cudaGetSymbolAddress((void**)&Kb, g_K);
    cudaGetSymbolAddress((void**)&Vb, g_V);
    cudaGetSymbolAddress((void**)&Ab, g_att);
    cudaGetSymbolAddress((void**)&Xo, g_xo);
    cudaGetSymbolAddress((void**)&F1, g_f1);
    cudaGetSymbolAddress((void**)&ahi, g_ahi);
    cudaGetSymbolAddress((void**)&alo, g_alo);
    cudaGetSymbolAddress((void**)&whi, g_whi);
    cudaGetSymbolAddress((void**)&wlo, g_wlo);

    cudaFuncSetAttribute(attn_kernel, cudaFuncAttributeMaxDynamicSharedMemorySize, 160 * 1024);
    cudaFuncSetAttribute(gemm_mma, cudaFuncAttributeMaxDynamicSharedMemorySize, 4 * GBUF * 2);

    const int actBlocks = (MROWS * HID / 4 + 255) / 256;
    dim3 wgrid(HID / 32, HID / 32);
    dim3 wgrid2(HID / 32, 2 * HID / 32);
    dim3 wblk(32, 8);
    dim3 ggrid(HID / 128, MROWS / 128);        // (6, 64)
    size_t gsmem = (size_t)4 * GBUF * 2;       // 73728 B

    // --- Q projection ---
    split_w<<<wgrid, wblk>>>(Wq, HID, HID, whi, wlo);
    split_act<<<actBlocks, 256>>>(query, MROWS, HID, ahi, alo, HID, 0);
    gemm_mma<<<ggrid, 256, gsmem>>>(ahi, alo, whi, wlo, HID, bq, nullptr, Qb, 0);
    // --- K projection ---
    split_w<<<wgrid, wblk>>>(Wk, HID, HID, whi, wlo);
    split_act<<<actBlocks, 256>>>(key_t, MROWS, HID, ahi, alo, HID, 0);
    gemm_mma<<<ggrid, 256, gsmem>>>(ahi, alo, whi, wlo, HID, bk, nullptr, Kb, 0);
    // --- V projection ---
    split_w<<<wgrid, wblk>>>(Wv, HID, HID, whi, wlo);
    split_act<<<actBlocks, 256>>>(value, MROWS, HID, ahi, alo, HID, 0);
    gemm_mma<<<ggrid, 256, gsmem>>>(ahi, alo, whi, wlo, HID, bv, nullptr, Vb, 0);

    // --- attention ---
    size_t smem = (32 * 1024 + 32 * 64 + 64 * 68) * sizeof(float);
    attn_kernel<<<dim3(SS / 32, NH, BB), 256, smem>>>(Qb, Kb, Vb, mask, out_attn, Ab);

    // --- Wo projection ---
    split_w<<<wgrid, wblk>>>(Wo, HID, HID, whi, wlo);
    split_act<<<actBlocks, 256>>>(Ab, MROWS, HID, ahi, alo, HID, 0);
    gemm_mma<<<ggrid, 256, gsmem>>>(ahi, alo, whi, wlo, HID, bo, nullptr, Xo, 0);

    // --- FFN: A = concat(xo, query), K = 1536 ---
    split_act<<<actBlocks, 256>>>(Xo,    MROWS, HID, ahi, alo, 2 * HID, 0);
    split_act<<<actBlocks, 256>>>(query, MROWS, HID, ahi, alo, 2 * HID, HID);
    split_w<<<wgrid2, wblk>>>(W1, 2 * HID, HID, whi, wlo);
    gemm_mma<<<ggrid, 256, gsmem>>>(ahi, alo, whi, wlo, 2 * HID, b1, nullptr, F1, 0);
    split_w<<<wgrid2, wblk>>>(W2, 2 * HID, HID, whi, wlo);
    gemm_mma<<<ggrid, 256, gsmem>>>(ahi, alo, whi, wlo, 2 * HID, b2, F1, out_gated, 1);
}

// round 4
// speedup vs baseline: 2.8763x; 2.0126x over previous
#include <cuda_runtime.h>
#include <cuda_bf16.h>
#include <math.h>
#include <stdint.h>

#define BB 8
#define SS 1024
#define HID 768
#define NH 12
#define HD 64
#define MROWS (BB*SS)   // 8192

// ---------------- scratch (device globals; no allocation allowed) ----------------
__device__ __align__(256) float g_Q [(size_t)MROWS*HID];
__device__ __align__(256) float g_K [(size_t)MROWS*HID];
__device__ __align__(256) float g_V [(size_t)MROWS*HID];
__device__ __align__(256) float g_xo [(size_t)MROWS*HID];
__device__ __align__(256) float g_f1 [(size_t)MROWS*HID];

__device__ __align__(256) __nv_bfloat16 g_ahi[(size_t)MROWS*2*HID];
__device__ __align__(256) __nv_bfloat16 g_alo[(size_t)MROWS*2*HID];
__device__ __align__(256) __nv_bfloat16 g_whi[(size_t)2*HID*HID];   // [N][K] transposed
__device__ __align__(256) __nv_bfloat16 g_wlo[(size_t)2*HID*HID];

__device__ __align__(256) __nv_bfloat16 g_qhi[(size_t)MROWS*HID];
__device__ __align__(256) __nv_bfloat16 g_qlo[(size_t)MROWS*HID];
__device__ __align__(256) __nv_bfloat16 g_khi[(size_t)MROWS*HID];
__device__ __align__(256) __nv_bfloat16 g_klo[(size_t)MROWS*HID];
__device__ __align__(256) __nv_bfloat16 g_vhi[(size_t)MROWS*HID];
__device__ __align__(256) __nv_bfloat16 g_vlo[(size_t)MROWS*HID];
__device__ __align__(256) __nv_bfloat16 g_xhi[(size_t)MROWS*HID];
__device__ __align__(256) __nv_bfloat16 g_xlo[(size_t)MROWS*HID];

// ================= helpers =================
__device__ __forceinline__ uint32_t smem_u32(const void* p) {
    uint32_t a;
    asm("{ .reg .u64 t; cvta.to.shared.u64 t, %1; cvt.u32.u64 %0, t; }" : "=r"(a) : "l"(p));
    return a;
}
__device__ __forceinline__ void ldsm_x4(uint32_t* r, uint32_t addr) {
    asm volatile("ldmatrix.sync.aligned.m8n8.x4.shared.b16 {%0,%1,%2,%3}, [%4];"
                 : "=r"(r[0]), "=r"(r[1]), "=r"(r[2]), "=r"(r[3]) : "r"(addr));
}
__device__ __forceinline__ void ldsm_x4_t(uint32_t* r, uint32_t addr) {
    asm volatile("ldmatrix.sync.aligned.m8n8.x4.trans.shared.b16 {%0,%1,%2,%3}, [%4];"
                 : "=r"(r[0]), "=r"(r[1]), "=r"(r[2]), "=r"(r[3]) : "r"(addr));
}
__device__ __forceinline__ void mma16816(float* c, const uint32_t* a, uint32_t b0, uint32_t b1) {
    asm volatile("mma.sync.aligned.m16n8k16.row.col.f32.bf16.bf16.f32 "
                 "{%0,%1,%2,%3}, {%4,%5,%6,%7}, {%8,%9}, {%0,%1,%2,%3};"
                 : "+f"(c[0]), "+f"(c[1]), "+f"(c[2]), "+f"(c[3])
                 : "r"(a[0]), "r"(a[1]), "r"(a[2]), "r"(a[3]), "r"(b0), "r"(b1));
}
__device__ __forceinline__ void cp16(uint32_t dst, const void* src) {
    asm volatile("cp.async.cg.shared.global [%0], [%1], 16;" :: "r"(dst), "l"(src));
}
#define CP_COMMIT() asm volatile("cp.async.commit_group;" ::: "memory")
#define CP_WAIT1()  asm volatile("cp.async.wait_group 1;" ::: "memory")
#define CP_WAIT0()  asm volatile("cp.async.wait_group 0;" ::: "memory")

// ================= split kernels =================
__global__ void split_act(const float* __restrict__ src, int M, int Ksrc,
                          __nv_bfloat16* __restrict__ hi, __nv_bfloat16* __restrict__ lo,
                          int dstStride, int colOff, float scale)
{
    size_t total = (size_t)M * Ksrc / 4;
    for (size_t i = (size_t)blockIdx.x * blockDim.x + threadIdx.x; i < total;
         i += (size_t)gridDim.x * blockDim.x) {
        size_t e = i * 4;
        int m = (int)(e / Ksrc), c = (int)(e % Ksrc);
        float4 v = *(const float4*)(src + e);
        v.x *= scale; v.y *= scale; v.z *= scale; v.w *= scale;
        __nv_bfloat16 h0 = __float2bfloat16(v.x), h1 = __float2bfloat16(v.y);
        __nv_bfloat16 h2 = __float2bfloat16(v.z), h3 = __float2bfloat16(v.w);
        __nv_bfloat16 l0 = __float2bfloat16(v.x - __bfloat162float(h0));
        __nv_bfloat16 l1 = __float2bfloat16(v.y - __bfloat162float(h1));
        __nv_bfloat16 l2 = __float2bfloat16(v.z - __bfloat162float(h2));
        __nv_bfloat16 l3 = __float2bfloat16(v.w - __bfloat162float(h3));
        size_t d = (size_t)m * dstStride + colOff + c;
        *(__nv_bfloat162*)(hi + d)     = __nv_bfloat162(h0, h1);
        *(__nv_bfloat162*)(hi + d + 2) = __nv_bfloat162(h2, h3);
        *(__nv_bfloat162*)(lo + d)     = __nv_bfloat162(l0, l1);
        *(__nv_bfloat162*)(lo + d + 2) = __nv_bfloat162(l2, l3);
    }
}

__global__ void split_w(const float* __restrict__ W, int K, int N,
                        __nv_bfloat16* __restrict__ hi, __nv_bfloat16* __restrict__ lo)
{
    __shared__ float t[32][33];
    int n0 = blockIdx.x * 32, k0 = blockIdx.y * 32;
    int tx = threadIdx.x, ty = threadIdx.y;
    for (int j = ty; j < 32; j += 8)
        t[j][tx] = W[(size_t)(k0 + j) * N + n0 + tx];
    __syncthreads();
    for (int j = ty; j < 32; j += 8) {
        float x = t[tx][j];
        __nv_bfloat16 h = __float2bfloat16(x);
        __nv_bfloat16 l = __float2bfloat16(x - __bfloat162float(h));
        size_t d = (size_t)(n0 + j) * K + k0 + tx;
        hi[d] = h; lo[d] = l;
    }
}

// ================= mma.sync bf16x3 GEMM (cp.async 2-stage pipeline) =================
#define GSTRIDE 72
#define GBUF (128 * GSTRIDE)     // elems per buffer (9216)
#define GSTAGE (4 * GBUF)        // elems per stage

__global__ __launch_bounds__(256) void gemm_mma(
    const __nv_bfloat16* __restrict__ Ahi, const __nv_bfloat16* __restrict__ Alo,
    const __nv_bfloat16* __restrict__ Bhi, const __nv_bfloat16* __restrict__ Blo,
    int Kdim, const float* __restrict__ bias, const float* __restrict__ prev,
    float* __restrict__ C, int mode)
{
    extern __shared__ __nv_bfloat16 smg[];
    const int tid = threadIdx.x;
    const int w = tid >> 5, l = tid & 31;
    const int m0 = blockIdx.y * 128;
    const int n0 = blockIdx.x * 128;
    const int wm = (w >> 2) * 64;
    const int wn = (w & 3) * 32;

    float c[4][4][4];
    #pragma unroll
    for (int i = 0; i < 4; i++)
        #pragma unroll
        for (int j = 0; j < 4; j++)
            #pragma unroll
            for (int q = 0; q < 4; q++) c[i][j][q] = 0.f;

    const uint32_t sbase = smem_u32(smg);
    const int aRow = wm + (l & 15), aKof = (l >> 4) * 8;
    const int bRow = wn + (l >> 4) * 8 + (l & 7), bKof = ((l >> 3) & 1) * 8;
    const int nChunks = Kdim >> 6;

    auto issue = [&](int ch) {
        const int st = ch & 1;
        const uint32_t dstBase = sbase + (uint32_t)(st * GSTAGE * 2);
        const int k0 = ch << 6;
        #pragma unroll
        for (int i = 0; i < 4; i++) {
            int t = tid + i * 256;
            int row = t >> 3, c8 = (t & 7) * 8;
            uint32_t d = dstBase + (uint32_t)((row * GSTRIDE + c8) * 2);
            size_t ga = (size_t)(m0 + row) * Kdim + k0 + c8;
            size_t gb = (size_t)(n0 + row) * Kdim + k0 + c8;
            cp16(d,                Ahi + ga);
            cp16(d + GBUF * 2,     Alo + ga);
            cp16(d + 2 * GBUF * 2, Bhi + gb);
            cp16(d + 3 * GBUF * 2, Blo + gb);
        }
    };

    issue(0); CP_COMMIT();
    for (int ch = 0; ch < nChunks; ch++) {
        if (ch + 1 < nChunks) { issue(ch + 1); CP_COMMIT(); CP_WAIT1(); }
        else                  { CP_WAIT0(); }
        __syncthreads();

        const uint32_t sb = sbase + (uint32_t)((ch & 1) * GSTAGE * 2);
        const uint32_t aHiB = sb + (uint32_t)((aRow * GSTRIDE + aKof) * 2);
        const uint32_t aLoB = aHiB + GBUF * 2;
        const uint32_t bHiB = sb + 2 * GBUF * 2 + (uint32_t)((bRow * GSTRIDE + bKof) * 2);
        const uint32_t bLoB = bHiB + GBUF * 2;

        #pragma unroll
        for (int ks = 0; ks < 4; ks++) {
            const uint32_t kb = (uint32_t)(ks * 16 * 2);
            uint32_t ah[4][4], al[4][4], bh[2][4], bl[2][4];
            #pragma unroll
            for (int mi = 0; mi < 4; mi++) {
                ldsm_x4(ah[mi], aHiB + (uint32_t)(mi * 16 * GSTRIDE * 2) + kb);
                ldsm_x4(al[mi], aLoB + (uint32_t)(mi * 16 * GSTRIDE * 2) + kb);
            }
            #pragma unroll
            for (int p = 0; p < 2; p++) {
                ldsm_x4(bh[p], bHiB + (uint32_t)(p * 16 * GSTRIDE * 2) + kb);
                ldsm_x4(bl[p], bLoB + (uint32_t)(p * 16 * GSTRIDE * 2) + kb);
            }
            #pragma unroll
            for (int mi = 0; mi < 4; mi++) {
                #pragma unroll
                for (int nj = 0; nj < 4; nj++) {
                    const int p = nj >> 1, s = (nj & 1) * 2;
                    mma16816(c[mi][nj], ah[mi], bh[p][s], bh[p][s + 1]);
                    mma16816(c[mi][nj], ah[mi], bl[p][s], bl[p][s + 1]);
                    mma16816(c[mi][nj], al[mi], bh[p][s], bh[p][s + 1]);
                }
            }
        }
        __syncthreads();
    }

    const int Nn = HID;
    #pragma unroll
    for (int mi = 0; mi < 4; mi++) {
        int r0 = m0 + wm + mi * 16 + (l >> 2);
        #pragma unroll
        for (int nj = 0; nj < 4; nj++) {
            int col = n0 + wn + nj * 8 + (l & 3) * 2;
            float b0 = bias[col], b1 = bias[col + 1];
            #pragma unroll
            for (int half = 0; half < 2; half++) {
                int r = r0 + half * 8;
                float v0 = c[mi][nj][half * 2 + 0] + b0;
                float v1 = c[mi][nj][half * 2 + 1] + b1;
                if (mode == 1) {
                    float g0 = prev[(size_t)r * Nn + col];
                    float g1 = prev[(size_t)r * Nn + col + 1];
                    v0 *= 1.f / (1.f + __expf(-g0));
                    v1 *= 1.f / (1.f + __expf(-g1));
                }
                *(float2*)(C + (size_t)r * Nn + col) = make_float2(v0, v1);
            }
        }
    }
}

// ================= tensor-core attention =================
// CTA = (32 queries, full 1024 keys) for one (b,h). 256 threads / 8 warps.
// smem layout (bytes):
//   sQh 0..4608, sQl 4608..9216        : 32 x 72 bf16 each
//   sKh 9216..46080, sKl 46080..82944  : 256 x 72 bf16 each (K then V chunks)
//   sEh 82944..148992, sEl ..215040    : 32 x 1032 bf16 each (scores -> e)
//   sInv 215040..215168                : 32 fp32
#define EST 1032
#define KVST 72
#define ATTN_SMEM 215168

__global__ __launch_bounds__(256) void attn_mma(
    const __nv_bfloat16* __restrict__ qhi, const __nv_bfloat16* __restrict__ qlo,
    const __nv_bfloat16* __restrict__ khi, const __nv_bfloat16* __restrict__ klo,
    const __nv_bfloat16* __restrict__ vhi, const __nv_bfloat16* __restrict__ vlo,
    const int* __restrict__ mask, float* __restrict__ attn_out,
    __nv_bfloat16* __restrict__ xhi, __nv_bfloat16* __restrict__ xlo)
{
    extern __shared__ char sab[];
    __nv_bfloat16* sQh = (__nv_bfloat16*)(sab);
    __nv_bfloat16* sQl = (__nv_bfloat16*)(sab + 4608);
    __nv_bfloat16* sKh = (__nv_bfloat16*)(sab + 9216);
    __nv_bfloat16* sKl = (__nv_bfloat16*)(sab + 46080);
    __nv_bfloat16* sEh = (__nv_bfloat16*)(sab + 82944);
    __nv_bfloat16* sEl = (__nv_bfloat16*)(sab + 148992);
    float* sInv  = (float*)(sab + 215040);
    float* sPart = (float*)(sab + 9216);   // overlays sKh after final sync

    const int tid = threadIdx.x, w = tid >> 5, l = tid & 31;
    const int q0 = blockIdx.x * 32, h = blockIdx.y, b = blockIdx.z;

    const uint32_t uQh = smem_u32(sQh), uQl = smem_u32(sQl);
    const uint32_t uKh = smem_u32(sKh), uKl = smem_u32(sKl);
    const uint32_t uEh = smem_u32(sEh), uEl = smem_u32(sEl);

    // load Q tile (32 rows x 64 d), hi/lo
    {
        int r = tid >> 3, c8 = (tid & 7) * 8;
        size_t g = ((size_t)(b * SS + q0 + r)) * HID + h * HD + c8;
        *(uint4*)(sQh + r * KVST + c8) = *(const uint4*)(qhi + g);
        *(uint4*)(sQl + r * KVST + c8) = *(const uint4*)(qlo + g);
    }

    const uint32_t aLaneOff = (uint32_t)(((l & 15) * KVST + (l >> 4) * 8) * 2);
    const int bRowL = (l >> 4) * 8 + (l & 7);
    const int bKofL = ((l >> 3) & 1) * 8;

    // ---------- Phase A: raw scores -> sE (bf16 hi/lo) ----------
    for (int ch = 0; ch < 4; ch++) {
        const int kc0 = ch * 256;
        __syncthreads();
        #pragma unroll
        for (int i = 0; i < 8; i++) {
            int t = tid + i * 256;
            int r = t >> 3, c8 = (t & 7) * 8;
            size_t g = ((size_t)(b * SS + kc0 + r)) * HID + h * HD + c8;
            *(uint4*)(sKh + r * KVST + c8) = *(const uint4*)(khi + g);
            *(uint4*)(sKl + r * KVST + c8) = *(const uint4*)(klo + g);
        }
        __syncthreads();

        float c[2][4][4];
        #pragma unroll
        for (int m = 0; m < 2; m++)
            #pragma unroll
            for (int nj = 0; nj < 4; nj++)
                #pragma unroll
                for (int q = 0; q < 4; q++) c[m][nj][q] = 0.f;

        #pragma unroll
        for (int ks = 0; ks < 4; ks++) {
            uint32_t ah[2][4], al[2][4], bh[2][4], bl[2][4];
            #pragma unroll
            for (int m = 0; m < 2; m++) {
                uint32_t off = (uint32_t)((m * 16 * KVST + ks * 16) * 2) + aLaneOff;
                ldsm_x4(ah[m], uQh + off);
                ldsm_x4(al[m], uQl + off);
            }
            #pragma unroll
            for (int p = 0; p < 2; p++) {
                uint32_t off = (uint32_t)(((w * 32 + p * 16 + bRowL) * KVST + ks * 16 + bKofL) * 2);
                ldsm_x4(bh[p], uKh + off);
                ldsm_x4(bl[p], uKl + off);
            }
            #pragma unroll
            for (int m = 0; m < 2; m++) {
                #pragma unroll
                for (int nj = 0; nj < 4; nj++) {
                    const int p = nj >> 1, s = (nj & 1) * 2;
                    mma16816(c[m][nj], ah[m], bh[p][s], bh[p][s + 1]);
                    mma16816(c[m][nj], ah[m], bl[p][s], bl[p][s + 1]);
                    mma16816(c[m][nj], al[m], bh[p][s], bh[p][s + 1]);
                }
            }
        }
        // scatter scores to sE as hi/lo
        #pragma unroll
        for (int m = 0; m < 2; m++) {
            #pragma unroll
            for (int nj = 0; nj < 4; nj++) {
                int kcol = kc0 + w * 32 + nj * 8 + (l & 3) * 2;
                #pragma unroll
                for (int hf = 0; hf < 2; hf++) {
                    int row = m * 16 + (l >> 2) + hf * 8;
                    float s0 = c[m][nj][hf * 2 + 0];
                    float s1 = c[m][nj][hf * 2 + 1];
                    __nv_bfloat16 h0 = __float2bfloat16(s0);
                    __nv_bfloat16 h1 = __float2bfloat16(s1);
                    sEh[row * EST + kcol]     = h0;
                    sEh[row * EST + kcol + 1] = h1;
                    sEl[row * EST + kcol]     = __float2bfloat16(s0 - __bfloat162float(h0));
                    sEl[row * EST + kcol + 1] = __float2bfloat16(s1 - __bfloat162float(h1));
                }
            }
        }
    }
    __syncthreads();

    // ---------- Phase B: masked softmax; probs -> gmem; e (hi/lo) -> sE ----------
    const int* mrow = mask + b * SS;
    for (int r = w * 4; r < w * 4 + 4; r++) {
        __nv_bfloat16* eh = sEh + r * EST;
        __nv_bfloat16* el = sEl + r * EST;
        float mx = -3.4e38f;
        for (int i = 0; i < 32; i++) {
            int k = i * 32 + l;
            float s = __bfloat162float(eh[k]) + __bfloat162float(el[k]);
            if (mrow[k] == 0) s = -1e10f;
            mx = fmaxf(mx, s);
        }
        #pragma unroll
        for (int o = 16; o > 0; o >>= 1) mx = fmaxf(mx, __shfl_xor_sync(0xffffffffu, mx, o));
        float sum = 0.f;
        for (int i = 0; i < 32; i++) {
            int k = i * 32 + l;
            float s = __bfloat162float(eh[k]) + __bfloat162float(el[k]);
            if (mrow[k] == 0) s = -1e10f;
            float e = __expf(s - mx);
            sum += e;
            __nv_bfloat16 hh = __float2bfloat16(e);
            eh[k] = hh;
            el[k] = __float2bfloat16(e - __bfloat162float(hh));
        }
        #pragma unroll
        for (int o = 16; o > 0; o >>= 1) sum += __shfl_xor_sync(0xffffffffu, sum, o);
        float inv = 1.f / sum;
        if (l == 0) sInv[r] = inv;
        float* orow = attn_out + ((size_t)((b * NH + h) * SS + q0 + r)) * SS;
        for (int i = 0; i < 32; i++) {
            int k = i * 32 + l;
            float e = __bfloat162float(eh[k]) + __bfloat162float(el[k]);
            orow[k] = e * inv;
        }
    }

    // ---------- Phase C: x = (e @ V) * inv ----------
    const int dg = (w & 3) * 16;
    const int khalf = w >> 2;
    float cc[2][2][4];
    #pragma unroll
    for (int m = 0; m < 2; m++)
        #pragma unroll
        for (int nt = 0; nt < 2; nt++)
            #pragma unroll
            for (int q = 0; q < 4; q++) cc[m][nt][q] = 0.f;

    for (int ch = 0; ch < 4; ch++) {
        const int kc0 = ch * 256;
        __syncthreads();
        #pragma unroll
        for (int i = 0; i < 8; i++) {
            int t = tid + i * 256;
            int r = t >> 3, c8 = (t & 7) * 8;
            size_t g = ((size_t)(b * SS + kc0 + r)) * HID + h * HD + c8;
            *(uint4*)(sKh + r * KVST + c8) = *(const uint4*)(vhi + g);
            *(uint4*)(sKl + r * KVST + c8) = *(const uint4*)(vlo + g);
        }
        __syncthreads();

        if ((ch >> 1) == khalf) {
            #pragma unroll 4
            for (int ks = 0; ks < 16; ks++) {
                uint32_t ah2[2][4], al2[2][4], bh2[4], bl2[4];
                uint32_t ecol = (uint32_t)((kc0 + ks * 16 + (l >> 4) * 8) * 2);
                #pragma unroll
                for (int m = 0; m < 2; m++) {
                    uint32_t off = (uint32_t)(((m * 16 + (l & 15)) * EST) * 2) + ecol;
                    ldsm_x4(ah2[m], uEh + off);
                    ldsm_x4(al2[m], uEl + off);
                }
                uint32_t voff = (uint32_t)(((ks * 16 + (l & 15)) * KVST + dg + (l >> 4) * 8) * 2);
                ldsm_x4_t(bh2, uKh + voff);
                ldsm_x4_t(bl2, uKl + voff);
                #pragma unroll
                for (int m = 0; m < 2; m++) {
                    #pragma unroll
                    for (int nt = 0; nt < 2; nt++) {
                        mma16816(cc[m][nt], ah2[m], bh2[nt * 2], bh2[nt * 2 + 1]);
                        mma16816(cc[m][nt], ah2[m], bl2[nt * 2], bl2[nt * 2 + 1]);
                        mma16816(cc[m][nt], al2[m], bh2[nt * 2], bh2[nt * 2 + 1]);
                    }
                }
            }
        }
    }
    __syncthreads();

    if (w >= 4) {
        #pragma unroll
        for (int m = 0; m < 2; m++)
            #pragma unroll
            for (int nt = 0; nt < 2; nt++)
                #pragma unroll
                for (int v = 0; v < 4; v++) {
                    int row = m * 16 + (l >> 2) + (v >> 1) * 8;
                    int col = dg + nt * 8 + (l & 3) * 2 + (v & 1);
                    sPart[row * 64 + col] = cc[m][nt][v];
                }
    }
    __syncthreads();
    if (w < 4) {
        #pragma unroll
        for (int m = 0; m < 2; m++) {
            #pragma unroll
            for (int nt = 0; nt < 2; nt++) {
                #pragma unroll
                for (int hf = 0; hf < 2; hf++) {
                    int row = m * 16 + (l >> 2) + hf * 8;
                    int col = dg + nt * 8 + (l & 3) * 2;
                    float inv = sInv[row];
                    float x0 = (cc[m][nt][hf * 2 + 0] + sPart[row * 64 + col])     * inv;
                    float x1 = (cc[m][nt][hf * 2 + 1] + sPart[row * 64 + col + 1]) * inv;
                    __nv_bfloat16 h0 = __float2bfloat16(x0);
                    __nv_bfloat16 h1 = __float2bfloat16(x1);
                    __nv_bfloat16 l0 = __float2bfloat16(x0 - __bfloat162float(h0));
                    __nv_bfloat16 l1 = __float2bfloat16(x1 - __bfloat162float(h1));
                    size_t g = ((size_t)(b * SS + q0 + row)) * HID + h * HD + col;
                    *(__nv_bfloat162*)(xhi + g) = __nv_bfloat162(h0, h1);
                    *(__nv_bfloat162*)(xlo + g) = __nv_bfloat162(l0, l1);
                }
            }
        }
    }
}

// ================= launch =================
extern "C" void kernel_launch(void* const* d_in, const int* in_sizes, int n_in,
                              void* d_out, int out_size)
{
    const float* query = (const float*)d_in[0];
    const float* key_t = (const float*)d_in[1];
    const float* value = (const float*)d_in[2];
    const int*   mask  = (const int*)d_in[3];
    const float* Wq = (const float*)d_in[4];  const float* bq = (const float*)d_in[5];
    const float* Wk = (const float*)d_in[6];  const float* bk = (const float*)d_in[7];
    const float* Wv = (const float*)d_in[8];  const float* bv = (const float*)d_in[9];
    const float* Wo = (const float*)d_in[10]; const float* bo = (const float*)d_in[11];
    const float* W1 = (const float*)d_in[12]; const float* b1 = (const float*)d_in[13];
    const float* W2 = (const float*)d_in[14]; const float* b2 = (const float*)d_in[15];

    float* out       = (float*)d_out;
    float* out_gated = out;
    float* out_attn  = out + (size_t)MROWS * HID;

    float *Qb, *Kb, *Vb, *Xo, *F1;
    __nv_bfloat16 *ahi, *alo, *whi, *wlo;
    __nv_bfloat16 *qhi_, *qlo_, *khi_, *klo_, *vhi_, *vlo_, *xhi_, *xlo_;
    cudaGetSymbolAddress((void**)&Qb, g_Q);
    cudaGetSymbolAddress((void**)&Kb, g_K);
    cudaGetSymbolAddress((void**)&Vb, g_V);
    cudaGetSymbolAddress((void**)&Xo, g_xo);
    cudaGetSymbolAddress((void**)&F1, g_f1);
    cudaGetSymbolAddress((void**)&ahi, g_ahi);
    cudaGetSymbolAddress((void**)&alo, g_alo);
    cudaGetSymbolAddress((void**)&whi, g_whi);
    cudaGetSymbolAddress((void**)&wlo, g_wlo);
    cudaGetSymbolAddress((void**)&qhi_, g_qhi);
    cudaGetSymbolAddress((void**)&qlo_, g_qlo);
    cudaGetSymbolAddress((void**)&khi_, g_khi);
    cudaGetSymbolAddress((void**)&klo_, g_klo);
    cudaGetSymbolAddress((void**)&vhi_, g_vhi);
    cudaGetSymbolAddress((void**)&vlo_, g_vlo);
    cudaGetSymbolAddress((void**)&xhi_, g_xhi);
    cudaGetSymbolAddress((void**)&xlo_, g_xlo);

    size_t gsmem = (size_t)2 * GSTAGE * 2;   // 147456 B
    cudaFuncSetAttribute(gemm_mma, cudaFuncAttributeMaxDynamicSharedMemorySize, (int)gsmem);
    cudaFuncSetAttribute(attn_mma, cudaFuncAttributeMaxDynamicSharedMemorySize, ATTN_SMEM);

    const int actBlocks = (MROWS * HID / 4 + 255) / 256;
    dim3 wgrid(HID / 32, HID / 32);
    dim3 wgrid2(HID / 32, 2 * HID / 32);
    dim3 wblk(32, 8);
    dim3 ggrid(HID / 128, MROWS / 128);

    // --- Q projection + split (Q pre-scaled by 1/sqrt(64)) ---
    split_w<<<wgrid, wblk>>>(Wq, HID, HID, whi, wlo);
    split_act<<<actBlocks, 256>>>(query, MROWS, HID, ahi, alo, HID, 0, 1.f);
    gemm_mma<<<ggrid, 256, gsmem>>>(ahi, alo, whi, wlo, HID, bq, nullptr, Qb, 0);
    split_act<<<actBlocks, 256>>>(Qb, MROWS, HID, qhi_, qlo_, HID, 0, 0.125f);
    // --- K projection + split ---
    split_w<<<wgrid, wblk>>>(Wk, HID, HID, whi, wlo);
    split_act<<<actBlocks, 256>>>(key_t, MROWS, HID, ahi, alo, HID, 0, 1.f);
    gemm_mma<<<ggrid, 256, gsmem>>>(ahi, alo, whi, wlo, HID, bk, nullptr, Kb, 0);
    split_act<<<actBlocks, 256>>>(Kb, MROWS, HID, khi_, klo_, HID, 0, 1.f);
    // --- V projection + split ---
    split_w<<<wgrid, wblk>>>(Wv, HID, HID, whi, wlo);
    split_act<<<actBlocks, 256>>>(value, MROWS, HID, ahi, alo, HID, 0, 1.f);
    gemm_mma<<<ggrid, 256, gsmem>>>(ahi, alo, whi, wlo, HID, bv, nullptr, Vb, 0);
    split_act<<<actBlocks, 256>>>(Vb, MROWS, HID, vhi_, vlo_, HID, 0, 1.f);

    // --- attention (tensor core) ---
    attn_mma<<<dim3(SS / 32, NH, BB), 256, ATTN_SMEM>>>(
        qhi_, qlo_, khi_, klo_, vhi_, vlo_, mask, out_attn, xhi_, xlo_);

    // --- Wo projection (consumes pre-split x from attention) ---
    split_w<<<wgrid, wblk>>>(Wo, HID, HID, whi, wlo);
    gemm_mma<<<ggrid, 256, gsmem>>>(xhi_, xlo_, whi, wlo, HID, bo, nullptr, Xo, 0);

    // --- FFN: A = concat(xo, query), K = 1536 ---
    split_act<<<actBlocks, 256>>>(Xo,    MROWS, HID, ahi, alo, 2 * HID, 0,   1.f);
    split_act<<<actBlocks, 256>>>(query, MROWS, HID, ahi, alo, 2 * HID, HID, 1.f);
    split_w<<<wgrid2, wblk>>>(W1, 2 * HID, HID, whi, wlo);
    gemm_mma<<<ggrid, 256, gsmem>>>(ahi, alo, whi, wlo, 2 * HID, b1, nullptr, F1, 0);
    split_w<<<wgrid2, wblk>>>(W2, 2 * HID, HID, whi, wlo);
    gemm_mma<<<ggrid, 256, gsmem>>>(ahi, alo, whi, wlo, 2 * HID, b2, F1, out_gated, 1);
}

// round 5
// speedup vs baseline: 3.6415x; 1.2660x over previous
#include <cuda_runtime.h>
#include <cuda_bf16.h>
#include <cuda_fp16.h>
#include <math.h>
#include <stdint.h>

#define BB 8
#define SS 1024
#define HID 768
#define NH 12
#define HD 64
#define MROWS (BB*SS)   // 8192

// ---------------- scratch (device globals; no allocation allowed) ----------------
__device__ __align__(256) float g_f1 [(size_t)MROWS*HID];

__device__ __align__(256) __nv_bfloat16 g_ahi[(size_t)MROWS*HID];
__device__ __align__(256) __nv_bfloat16 g_alo[(size_t)MROWS*HID];
__device__ __align__(256) __nv_bfloat16 g_whi[(size_t)HID*HID];
__device__ __align__(256) __nv_bfloat16 g_wlo[(size_t)HID*HID];

__device__ __align__(256) __nv_bfloat16 g_qhi[(size_t)MROWS*HID];
__device__ __align__(256) __nv_bfloat16 g_qlo[(size_t)MROWS*HID];
__device__ __align__(256) __nv_bfloat16 g_khi[(size_t)MROWS*HID];
__device__ __align__(256) __nv_bfloat16 g_klo[(size_t)MROWS*HID];
__device__ __align__(256) __nv_bfloat16 g_vhi[(size_t)MROWS*HID];
__device__ __align__(256) __nv_bfloat16 g_vlo[(size_t)MROWS*HID];

__device__ __align__(256) __half g_xf [(size_t)MROWS*HID];      // attention x (fp16)
__device__ __align__(256) __half g_cat[(size_t)MROWS*2*HID];    // concat(xo, query) fp16
__device__ __align__(256) __half g_wf [(size_t)2*HID*HID];      // fp16 weight [N][K]

// ================= helpers =================
__device__ __forceinline__ uint32_t smem_u32(const void* p) {
    uint32_t a;
    asm("{ .reg .u64 t; cvta.to.shared.u64 t, %1; cvt.u32.u64 %0, t; }" : "=r"(a) : "l"(p));
    return a;
}
__device__ __forceinline__ void ldsm_x4(uint32_t* r, uint32_t addr) {
    asm volatile("ldmatrix.sync.aligned.m8n8.x4.shared.b16 {%0,%1,%2,%3}, [%4];"
                 : "=r"(r[0]), "=r"(r[1]), "=r"(r[2]), "=r"(r[3]) : "r"(addr));
}
__device__ __forceinline__ void ldsm_x4_t(uint32_t* r, uint32_t addr) {
    asm volatile("ldmatrix.sync.aligned.m8n8.x4.trans.shared.b16 {%0,%1,%2,%3}, [%4];"
                 : "=r"(r[0]), "=r"(r[1]), "=r"(r[2]), "=r"(r[3]) : "r"(addr));
}
__device__ __forceinline__ void mma16816(float* c, const uint32_t* a, uint32_t b0, uint32_t b1) {
    asm volatile("mma.sync.aligned.m16n8k16.row.col.f32.bf16.bf16.f32 "
                 "{%0,%1,%2,%3}, {%4,%5,%6,%7}, {%8,%9}, {%0,%1,%2,%3};"
                 : "+f"(c[0]), "+f"(c[1]), "+f"(c[2]), "+f"(c[3])
                 : "r"(a[0]), "r"(a[1]), "r"(a[2]), "r"(a[3]), "r"(b0), "r"(b1));
}
__device__ __forceinline__ void mma16816h(float* c, const uint32_t* a, uint32_t b0, uint32_t b1) {
    asm volatile("mma.sync.aligned.m16n8k16.row.col.f32.f16.f16.f32 "
                 "{%0,%1,%2,%3}, {%4,%5,%6,%7}, {%8,%9}, {%0,%1,%2,%3};"
                 : "+f"(c[0]), "+f"(c[1]), "+f"(c[2]), "+f"(c[3])
                 : "r"(a[0]), "r"(a[1]), "r"(a[2]), "r"(a[3]), "r"(b0), "r"(b1));
}
__device__ __forceinline__ void cp16(uint32_t dst, const void* src) {
    asm volatile("cp.async.cg.shared.global [%0], [%1], 16;" :: "r"(dst), "l"(src));
}
#define CP_COMMIT() asm volatile("cp.async.commit_group;" ::: "memory")
#define CP_WAIT1()  asm volatile("cp.async.wait_group 1;" ::: "memory")
#define CP_WAIT0()  asm volatile("cp.async.wait_group 0;" ::: "memory")

// ================= split / convert kernels =================
__global__ void split_act(const float* __restrict__ src,
                          __nv_bfloat16* __restrict__ hi, __nv_bfloat16* __restrict__ lo)
{
    size_t total = (size_t)MROWS * HID / 4;
    for (size_t i = (size_t)blockIdx.x * blockDim.x + threadIdx.x; i < total;
         i += (size_t)gridDim.x * blockDim.x) {
        size_t e = i * 4;
        float4 v = *(const float4*)(src + e);
        __nv_bfloat16 h0 = __float2bfloat16(v.x), h1 = __float2bfloat16(v.y);
        __nv_bfloat16 h2 = __float2bfloat16(v.z), h3 = __float2bfloat16(v.w);
        *(__nv_bfloat162*)(hi + e)     = __nv_bfloat162(h0, h1);
        *(__nv_bfloat162*)(hi + e + 2) = __nv_bfloat162(h2, h3);
        *(__nv_bfloat162*)(lo + e)     = __nv_bfloat162(__float2bfloat16(v.x - __bfloat162float(h0)),
                                                        __float2bfloat16(v.y - __bfloat162float(h1)));
        *(__nv_bfloat162*)(lo + e + 2) = __nv_bfloat162(__float2bfloat16(v.z - __bfloat162float(h2)),
                                                        __float2bfloat16(v.w - __bfloat162float(h3)));
    }
}

__global__ void split_w(const float* __restrict__ W, int K, int N,
                        __nv_bfloat16* __restrict__ hi, __nv_bfloat16* __restrict__ lo)
{
    __shared__ float t[32][33];
    int n0 = blockIdx.x * 32, k0 = blockIdx.y * 32;
    int tx = threadIdx.x, ty = threadIdx.y;
    for (int j = ty; j < 32; j += 8)
        t[j][tx] = W[(size_t)(k0 + j) * N + n0 + tx];
    __syncthreads();
    for (int j = ty; j < 32; j += 8) {
        float x = t[tx][j];
        __nv_bfloat16 h = __float2bfloat16(x);
        size_t d = (size_t)(n0 + j) * K + k0 + tx;
        hi[d] = h; lo[d] = __float2bfloat16(x - __bfloat162float(h));
    }
}

__global__ void split_w_fp16(const float* __restrict__ W, int K, int N,
                             __half* __restrict__ out)
{
    __shared__ float t[32][33];
    int n0 = blockIdx.x * 32, k0 = blockIdx.y * 32;
    int tx = threadIdx.x, ty = threadIdx.y;
    for (int j = ty; j < 32; j += 8)
        t[j][tx] = W[(size_t)(k0 + j) * N + n0 + tx];
    __syncthreads();
    for (int j = ty; j < 32; j += 8)
        out[(size_t)(n0 + j) * K + k0 + tx] = __float2half(t[tx][j]);
}

// query fp32 [M][768] -> fp16 into cat buffer cols [768,1536)
__global__ void conv_fp16(const float* __restrict__ src, __half* __restrict__ dst)
{
    size_t total = (size_t)MROWS * HID / 4;
    for (size_t i = (size_t)blockIdx.x * blockDim.x + threadIdx.x; i < total;
         i += (size_t)gridDim.x * blockDim.x) {
        size_t e = i * 4;
        int m = (int)(e / HID), c = (int)(e % HID);
        float4 v = *(const float4*)(src + e);
        size_t d = (size_t)m * (2 * HID) + HID + c;
        *(__half2*)(dst + d)     = __halves2half2(__float2half(v.x), __float2half(v.y));
        *(__half2*)(dst + d + 2) = __halves2half2(__float2half(v.z), __float2half(v.w));
    }
}

// ================= bf16x3 GEMM (cp.async pipeline), epilogue -> bf16 hi/lo =================
#define GSTRIDE 72
#define GBUF (128 * GSTRIDE)
#define GSTAGE (4 * GBUF)

__global__ __launch_bounds__(256) void gemm_bf16(
    const __nv_bfloat16* __restrict__ Ahi, const __nv_bfloat16* __restrict__ Alo,
    const __nv_bfloat16* __restrict__ Bhi, const __nv_bfloat16* __restrict__ Blo,
    int Kdim, const float* __restrict__ bias, float scale,
    __nv_bfloat16* __restrict__ outHi, __nv_bfloat16* __restrict__ outLo)
{
    extern __shared__ __nv_bfloat16 smg[];
    const int tid = threadIdx.x;
    const int w = tid >> 5, l = tid & 31;
    const int m0 = blockIdx.y * 128;
    const int n0 = blockIdx.x * 128;
    const int wm = (w >> 2) * 64;
    const int wn = (w & 3) * 32;

    float c[4][4][4];
    #pragma unroll
    for (int i = 0; i < 4; i++)
        #pragma unroll
        for (int j = 0; j < 4; j++)
            #pragma unroll
            for (int q = 0; q < 4; q++) c[i][j][q] = 0.f;

    const uint32_t sbase = smem_u32(smg);
    const int aRow = wm + (l & 15), aKof = (l >> 4) * 8;
    const int bRow = wn + (l >> 4) * 8 + (l & 7), bKof = ((l >> 3) & 1) * 8;
    const int nChunks = Kdim >> 6;

    auto issue = [&](int ch) {
        const uint32_t dstBase = sbase + (uint32_t)((ch & 1) * GSTAGE * 2);
        const int k0 = ch << 6;
        #pragma unroll
        for (int i = 0; i < 4; i++) {
            int t = tid + i * 256;
            int row = t >> 3, c8 = (t & 7) * 8;
            uint32_t d = dstBase + (uint32_t)((row * GSTRIDE + c8) * 2);
            size_t ga = (size_t)(m0 + row) * Kdim + k0 + c8;
            size_t gb = (size_t)(n0 + row) * Kdim + k0 + c8;
            cp16(d,                Ahi + ga);
            cp16(d + GBUF * 2,     Alo + ga);
            cp16(d + 2 * GBUF * 2, Bhi + gb);
            cp16(d + 3 * GBUF * 2, Blo + gb);
        }
    };

    issue(0); CP_COMMIT();
    for (int ch = 0; ch < nChunks; ch++) {
        if (ch + 1 < nChunks) { issue(ch + 1); CP_COMMIT(); CP_WAIT1(); }
        else                  { CP_WAIT0(); }
        __syncthreads();

        const uint32_t sb = sbase + (uint32_t)((ch & 1) * GSTAGE * 2);
        const uint32_t aHiB = sb + (uint32_t)((aRow * GSTRIDE + aKof) * 2);
        const uint32_t aLoB = aHiB + GBUF * 2;
        const uint32_t bHiB = sb + 2 * GBUF * 2 + (uint32_t)((bRow * GSTRIDE + bKof) * 2);
        const uint32_t bLoB = bHiB + GBUF * 2;

        #pragma unroll
        for (int ks = 0; ks < 4; ks++) {
            const uint32_t kb = (uint32_t)(ks * 16 * 2);
            uint32_t ah[4][4], al[4][4], bh[2][4], bl[2][4];
            #pragma unroll
            for (int mi = 0; mi < 4; mi++) {
                ldsm_x4(ah[mi], aHiB + (uint32_t)(mi * 16 * GSTRIDE * 2) + kb);
                ldsm_x4(al[mi], aLoB + (uint32_t)(mi * 16 * GSTRIDE * 2) + kb);
            }
            #pragma unroll
            for (int p = 0; p < 2; p++) {
                ldsm_x4(bh[p], bHiB + (uint32_t)(p * 16 * GSTRIDE * 2) + kb);
                ldsm_x4(bl[p], bLoB + (uint32_t)(p * 16 * GSTRIDE * 2) + kb);
            }
            #pragma unroll
            for (int mi = 0; mi < 4; mi++) {
                #pragma unroll
                for (int nj = 0; nj < 4; nj++) {
                    const int p = nj >> 1, s = (nj & 1) * 2;
                    mma16816(c[mi][nj], ah[mi], bh[p][s], bh[p][s + 1]);
                    mma16816(c[mi][nj], ah[mi], bl[p][s], bl[p][s + 1]);
                    mma16816(c[mi][nj], al[mi], bh[p][s], bh[p][s + 1]);
                }
            }
        }
        __syncthreads();
    }

    #pragma unroll
    for (int mi = 0; mi < 4; mi++) {
        int r0 = m0 + wm + mi * 16 + (l >> 2);
        #pragma unroll
        for (int nj = 0; nj < 4; nj++) {
            int col = n0 + wn + nj * 8 + (l & 3) * 2;
            float b0 = bias[col], b1 = bias[col + 1];
            #pragma unroll
            for (int half = 0; half < 2; half++) {
                int r = r0 + half * 8;
                float v0 = (c[mi][nj][half * 2 + 0] + b0) * scale;
                float v1 = (c[mi][nj][half * 2 + 1] + b1) * scale;
                __nv_bfloat16 h0 = __float2bfloat16(v0);
                __nv_bfloat16 h1 = __float2bfloat16(v1);
                size_t g = (size_t)r * HID + col;
                *(__nv_bfloat162*)(outHi + g) = __nv_bfloat162(h0, h1);
                *(__nv_bfloat162*)(outLo + g) = __nv_bfloat162(
                    __float2bfloat16(v0 - __bfloat162float(h0)),
                    __float2bfloat16(v1 - __bfloat162float(h1)));
            }
        }
    }
}

// ================= fp16 single-term GEMM (cp.async pipeline) =================
#define FSTAGE (2 * GBUF)

__global__ __launch_bounds__(256) void gemm_fp16(
    const __half* __restrict__ A, int lda, const __half* __restrict__ B,
    int Kdim, const float* __restrict__ bias, const float* __restrict__ prev,
    float* __restrict__ Cf, __half* __restrict__ Ch, int ldch, int mode)
{
    extern __shared__ __half smh[];
    const int tid = threadIdx.x;
    const int w = tid >> 5, l = tid & 31;
    const int m0 = blockIdx.y * 128;
    const int n0 = blockIdx.x * 128;
    const int wm = (w >> 2) * 64;
    const int wn = (w & 3) * 32;

    float c[4][4][4];
    #pragma unroll
    for (int i = 0; i < 4; i++)
        #pragma unroll
        for (int j = 0; j < 4; j++)
            #pragma unroll
            for (int q = 0; q < 4; q++) c[i][j][q] = 0.f;

    const uint32_t sbase = smem_u32(smh);
    const int aRow = wm + (l & 15), aKof = (l >> 4) * 8;
    const int bRow = wn + (l >> 4) * 8 + (l & 7), bKof = ((l >> 3) & 1) * 8;
    const int nChunks = Kdim >> 6;

    auto issue = [&](int ch) {
        const uint32_t dstBase = sbase + (uint32_t)((ch & 1) * FSTAGE * 2);
        const int k0 = ch << 6;
        #pragma unroll
        for (int i = 0; i < 4; i++) {
            int t = tid + i * 256;
            int row = t >> 3, c8 = (t & 7) * 8;
            uint32_t d = dstBase + (uint32_t)((row * GSTRIDE + c8) * 2);
            cp16(d,            A + (size_t)(m0 + row) * lda  + k0 + c8);
            cp16(d + GBUF * 2, B + (size_t)(n0 + row) * Kdim + k0 + c8);
        }
    };

    issue(0); CP_COMMIT();
    for (int ch = 0; ch < nChunks; ch++) {
        if (ch + 1 < nChunks) { issue(ch + 1); CP_COMMIT(); CP_WAIT1(); }
        else                  { CP_WAIT0(); }
        __syncthreads();

        const uint32_t sb = sbase + (uint32_t)((ch & 1) * FSTAGE * 2);
        const uint32_t aB = sb + (uint32_t)((aRow * GSTRIDE + aKof) * 2);
        const uint32_t bB = sb + GBUF * 2 + (uint32_t)((bRow * GSTRIDE + bKof) * 2);

        #pragma unroll
        for (int ks = 0; ks < 4; ks++) {
            const uint32_t kb = (uint32_t)(ks * 16 * 2);
            uint32_t ah[4][4], bh[2][4];
            #pragma unroll
            for (int mi = 0; mi < 4; mi++)
                ldsm_x4(ah[mi], aB + (uint32_t)(mi * 16 * GSTRIDE * 2) + kb);
            #pragma unroll
            for (int p = 0; p < 2; p++)
                ldsm_x4(bh[p], bB + (uint32_t)(p * 16 * GSTRIDE * 2) + kb);
            #pragma unroll
            for (int mi = 0; mi < 4; mi++) {
                #pragma unroll
                for (int nj = 0; nj < 4; nj++) {
                    const int p = nj >> 1, s = (nj & 1) * 2;
                    mma16816h(c[mi][nj], ah[mi], bh[p][s], bh[p][s + 1]);
                }
            }
        }
        __syncthreads();
    }

    #pragma unroll
    for (int mi = 0; mi < 4; mi++) {
        int r0 = m0 + wm + mi * 16 + (l >> 2);
        #pragma unroll
        for (int nj = 0; nj < 4; nj++) {
            int col = n0 + wn + nj * 8 + (l & 3) * 2;
            float b0 = bias[col], b1 = bias[col + 1];
            #pragma unroll
            for (int half = 0; half < 2; half++) {
                int r = r0 + half * 8;
                float v0 = c[mi][nj][half * 2 + 0] + b0;
                float v1 = c[mi][nj][half * 2 + 1] + b1;
                if (mode == 2) {
                    *(__half2*)(Ch + (size_t)r * ldch + col) =
                        __halves2half2(__float2half(v0), __float2half(v1));
                } else {
                    if (mode == 1) {
                        float g0 = prev[(size_t)r * HID + col];
                        float g1 = prev[(size_t)r * HID + col + 1];
                        v0 *= 1.f / (1.f + __expf(-g0));
                        v1 *= 1.f / (1.f + __expf(-g1));
                    }
                    *(float2*)(Cf + (size_t)r * HID + col) = make_float2(v0, v1);
                }
            }
        }
    }
}

// ================= tensor-core attention (bf16x3), x out as fp16 =================
#define EST 1032
#define KVST 72
#define ATTN_SMEM 215168

__global__ __launch_bounds__(256) void attn_mma(
    const __nv_bfloat16* __restrict__ qhi, const __nv_bfloat16* __restrict__ qlo,
    const __nv_bfloat16* __restrict__ khi, const __nv_bfloat16* __restrict__ klo,
    const __nv_bfloat16* __restrict__ vhi, const __nv_bfloat16* __restrict__ vlo,
    const int* __restrict__ mask, float* __restrict__ attn_out,
    __half* __restrict__ xf)
{
    extern __shared__ char sab[];
    __nv_bfloat16* sQh = (__nv_bfloat16*)(sab);
    __nv_bfloat16* sQl = (__nv_bfloat16*)(sab + 4608);
    __nv_bfloat16* sKh = (__nv_bfloat16*)(sab + 9216);
    __nv_bfloat16* sKl = (__nv_bfloat16*)(sab + 46080);
    __nv_bfloat16* sEh = (__nv_bfloat16*)(sab + 82944);
    __nv_bfloat16* sEl = (__nv_bfloat16*)(sab + 148992);
    float* sInv  = (float*)(sab + 215040);
    float* sPart = (float*)(sab + 9216);

    const int tid = threadIdx.x, w = tid >> 5, l = tid & 31;
    const int q0 = blockIdx.x * 32, h = blockIdx.y, b = blockIdx.z;

    const uint32_t uQh = smem_u32(sQh), uQl = smem_u32(sQl);
    const uint32_t uKh = smem_u32(sKh), uKl = smem_u32(sKl);
    const uint32_t uEh = smem_u32(sEh), uEl = smem_u32(sEl);

    {
        int r = tid >> 3, c8 = (tid & 7) * 8;
        size_t g = ((size_t)(b * SS + q0 + r)) * HID + h * HD + c8;
        *(uint4*)(sQh + r * KVST + c8) = *(const uint4*)(qhi + g);
        *(uint4*)(sQl + r * KVST + c8) = *(const uint4*)(qlo + g);
    }

    const uint32_t aLaneOff = (uint32_t)(((l & 15) * KVST + (l >> 4) * 8) * 2);
    const int bRowL = (l >> 4) * 8 + (l & 7);
    const int bKofL = ((l >> 3) & 1) * 8;

    // ---------- Phase A ----------
    for (int ch = 0; ch < 4; ch++) {
        const int kc0 = ch * 256;
        __syncthreads();
        #pragma unroll
        for (int i = 0; i < 8; i++) {
            int t = tid + i * 256;
            int r = t >> 3, c8 = (t & 7) * 8;
            size_t g = ((size_t)(b * SS + kc0 + r)) * HID + h * HD + c8;
            *(uint4*)(sKh + r * KVST + c8) = *(const uint4*)(khi + g);
            *(uint4*)(sKl + r * KVST + c8) = *(const uint4*)(klo + g);
        }
        __syncthreads();

        float c[2][4][4];
        #pragma unroll
        for (int m = 0; m < 2; m++)
            #pragma unroll
            for (int nj = 0; nj < 4; nj++)
                #pragma unroll
                for (int q = 0; q < 4; q++) c[m][nj][q] = 0.f;

        #pragma unroll
        for (int ks = 0; ks < 4; ks++) {
            uint32_t ah[2][4], al[2][4], bh[2][4], bl[2][4];
            #pragma unroll
            for (int m = 0; m < 2; m++) {
                uint32_t off = (uint32_t)((m * 16 * KVST + ks * 16) * 2) + aLaneOff;
                ldsm_x4(ah[m], uQh + off);
                ldsm_x4(al[m], uQl + off);
            }
            #pragma unroll
            for (int p = 0; p < 2; p++) {
                uint32_t off = (uint32_t)(((w * 32 + p * 16 + bRowL) * KVST + ks * 16 + bKofL) * 2);
                ldsm_x4(bh[p], uKh + off);
                ldsm_x4(bl[p], uKl + off);
            }
            #pragma unroll
            for (int m = 0; m < 2; m++) {
                #pragma unroll
                for (int nj = 0; nj < 4; nj++) {
                    const int p = nj >> 1, s = (nj & 1) * 2;
                    mma16816(c[m][nj], ah[m], bh[p][s], bh[p][s + 1]);
                    mma16816(c[m][nj], ah[m], bl[p][s], bl[p][s + 1]);
                    mma16816(c[m][nj], al[m], bh[p][s], bh[p][s + 1]);
                }
            }
        }
        #pragma unroll
        for (int m = 0; m < 2; m++) {
            #pragma unroll
            for (int nj = 0; nj < 4; nj++) {
                int kcol = kc0 + w * 32 + nj * 8 + (l & 3) * 2;
                #pragma unroll
                for (int hf = 0; hf < 2; hf++) {
                    int row = m * 16 + (l >> 2) + hf * 8;
                    float s0 = c[m][nj][hf * 2 + 0];
                    float s1 = c[m][nj][hf * 2 + 1];
                    __nv_bfloat16 h0 = __float2bfloat16(s0);
                    __nv_bfloat16 h1 = __float2bfloat16(s1);
                    sEh[row * EST + kcol]     = h0;
                    sEh[row * EST + kcol + 1] = h1;
                    sEl[row * EST + kcol]     = __float2bfloat16(s0 - __bfloat162float(h0));
                    sEl[row * EST + kcol + 1] = __float2bfloat16(s1 - __bfloat162float(h1));
                }
            }
        }
    }
    __syncthreads();

    // ---------- Phase B ----------
    const int* mrow = mask + b * SS;
    for (int r = w * 4; r < w * 4 + 4; r++) {
        __nv_bfloat16* eh = sEh + r * EST;
        __nv_bfloat16* el = sEl + r * EST;
        float mx = -3.4e38f;
        for (int i = 0; i < 32; i++) {
            int k = i * 32 + l;
            float s = __bfloat162float(eh[k]) + __bfloat162float(el[k]);
            if (mrow[k] == 0) s = -1e10f;
            mx = fmaxf(mx, s);
        }
        #pragma unroll
        for (int o = 16; o > 0; o >>= 1) mx = fmaxf(mx, __shfl_xor_sync(0xffffffffu, mx, o));
        float sum = 0.f;
        for (int i = 0; i < 32; i++) {
            int k = i * 32 + l;
            float s = __bfloat162float(eh[k]) + __bfloat162float(el[k]);
            if (mrow[k] == 0) s = -1e10f;
            float e = __expf(s - mx);
            sum += e;
            __nv_bfloat16 hh = __float2bfloat16(e);
            eh[k] = hh;
            el[k] = __float2bfloat16(e - __bfloat162float(hh));
        }
        #pragma unroll
        for (int o = 16; o > 0; o >>= 1) sum += __shfl_xor_sync(0xffffffffu, sum, o);
        float inv = 1.f / sum;
        if (l == 0) sInv[r] = inv;
        float* orow = attn_out + ((size_t)((b * NH + h) * SS + q0 + r)) * SS;
        for (int i = 0; i < 32; i++) {
            int k = i * 32 + l;
            float e = __bfloat162float(eh[k]) + __bfloat162float(el[k]);
            orow[k] = e * inv;
        }
    }

    // ---------- Phase C ----------
    const int dg = (w & 3) * 16;
    const int khalf = w >> 2;
    float cc[2][2][4];
    #pragma unroll
    for (int m = 0; m < 2; m++)
        #pragma unroll
        for (int nt = 0; nt < 2; nt++)
            #pragma unroll
            for (int q = 0; q < 4; q++) cc[m][nt][q] = 0.f;

    for (int ch = 0; ch < 4; ch++) {
        const int kc0 = ch * 256;
        __syncthreads();
        #pragma unroll
        for (int i = 0; i < 8; i++) {
            int t = tid + i * 256;
            int r = t >> 3, c8 = (t & 7) * 8;
            size_t g = ((size_t)(b * SS + kc0 + r)) * HID + h * HD + c8;
            *(uint4*)(sKh + r * KVST + c8) = *(const uint4*)(vhi + g);
            *(uint4*)(sKl + r * KVST + c8) = *(const uint4*)(vlo + g);
        }
        __syncthreads();

        if ((ch >> 1) == khalf) {
            #pragma unroll 4
            for (int ks = 0; ks < 16; ks++) {
                uint32_t ah2[2][4], al2[2][4], bh2[4], bl2[4];
                uint32_t ecol = (uint32_t)((kc0 + ks * 16 + (l >> 4) * 8) * 2);
                #pragma unroll
                for (int m = 0; m < 2; m++) {
                    uint32_t off = (uint32_t)(((m * 16 + (l & 15)) * EST) * 2) + ecol;
                    ldsm_x4(ah2[m], uEh + off);
                    ldsm_x4(al2[m], uEl + off);
                }
                uint32_t voff = (uint32_t)(((ks * 16 + (l & 15)) * KVST + dg + (l >> 4) * 8) * 2);
                ldsm_x4_t(bh2, uKh + voff);
                ldsm_x4_t(bl2, uKl + voff);
                #pragma unroll
                for (int m = 0; m < 2; m++) {
                    #pragma unroll
                    for (int nt = 0; nt < 2; nt++) {
                        mma16816(cc[m][nt], ah2[m], bh2[nt * 2], bh2[nt * 2 + 1]);
                        mma16816(cc[m][nt], ah2[m], bl2[nt * 2], bl2[nt * 2 + 1]);
                        mma16816(cc[m][nt], al2[m], bh2[nt * 2], bh2[nt * 2 + 1]);
                    }
                }
            }
        }
    }
    __syncthreads();

    if (w >= 4) {
        #pragma unroll
        for (int m = 0; m < 2; m++)
            #pragma unroll
            for (int nt = 0; nt < 2; nt++)
                #pragma unroll
                for (int v = 0; v < 4; v++) {
                    int row = m * 16 + (l >> 2) + (v >> 1) * 8;
                    int col = dg + nt * 8 + (l & 3) * 2 + (v & 1);
                    sPart[row * 64 + col] = cc[m][nt][v];
                }
    }
    __syncthreads();
    if (w < 4) {
        #pragma unroll
        for (int m = 0; m < 2; m++) {
            #pragma unroll
            for (int nt = 0; nt < 2; nt++) {
                #pragma unroll
                for (int hf = 0; hf < 2; hf++) {
                    int row = m * 16 + (l >> 2) + hf * 8;
                    int col = dg + nt * 8 + (l & 3) * 2;
                    float inv = sInv[row];
                    float x0 = (cc[m][nt][hf * 2 + 0] + sPart[row * 64 + col])     * inv;
                    float x1 = (cc[m][nt][hf * 2 + 1] + sPart[row * 64 + col + 1]) * inv;
                    size_t g = ((size_t)(b * SS + q0 + row)) * HID + h * HD + col;
                    *(__half2*)(xf + g) = __halves2half2(__float2half(x0), __float2half(x1));
                }
            }
        }
    }
}

// ================= launch =================
extern "C" void kernel_launch(void* const* d_in, const int* in_sizes, int n_in,
                              void* d_out, int out_size)
{
    const float* query = (const float*)d_in[0];
    const float* key_t = (const float*)d_in[1];
    const float* value = (const float*)d_in[2];
    const int*   mask  = (const int*)d_in[3];
    const float* Wq = (const float*)d_in[4];  const float* bq = (const float*)d_in[5];
    const float* Wk = (const float*)d_in[6];  const float* bk = (const float*)d_in[7];
    const float* Wv = (const float*)d_in[8];  const float* bv = (const float*)d_in[9];
    const float* Wo = (const float*)d_in[10]; const float* bo = (const float*)d_in[11];
    const float* W1 = (const float*)d_in[12]; const float* b1 = (const float*)d_in[13];
    const float* W2 = (const float*)d_in[14]; const float* b2 = (const float*)d_in[15];

    float* out       = (float*)d_out;
    float* out_gated = out;
    float* out_attn  = out + (size_t)MROWS * HID;

    float *F1;
    __nv_bfloat16 *ahi, *alo, *whi, *wlo;
    __nv_bfloat16 *qhi_, *qlo_, *khi_, *klo_, *vhi_, *vlo_;
    __half *xf, *cat, *wf;
    cudaGetSymbolAddress((void**)&F1, g_f1);
    cudaGetSymbolAddress((void**)&ahi, g_ahi);
    cudaGetSymbolAddress((void**)&alo, g_alo);
    cudaGetSymbolAddress((void**)&whi, g_whi);
    cudaGetSymbolAddress((void**)&wlo, g_wlo);
    cudaGetSymbolAddress((void**)&qhi_, g_qhi);
    cudaGetSymbolAddress((void**)&qlo_, g_qlo);
    cudaGetSymbolAddress((void**)&khi_, g_khi);
    cudaGetSymbolAddress((void**)&klo_, g_klo);
    cudaGetSymbolAddress((void**)&vhi_, g_vhi);
    cudaGetSymbolAddress((void**)&vlo_, g_vlo);
    cudaGetSymbolAddress((void**)&xf, g_xf);
    cudaGetSymbolAddress((void**)&cat, g_cat);
    cudaGetSymbolAddress((void**)&wf, g_wf);

    size_t gsmem = (size_t)2 * GSTAGE * 2;   // 147456 B
    size_t fsmem = (size_t)2 * FSTAGE * 2;   // 73728 B
    cudaFuncSetAttribute(gemm_bf16, cudaFuncAttributeMaxDynamicSharedMemorySize, (int)gsmem);
    cudaFuncSetAttribute(gemm_fp16, cudaFuncAttributeMaxDynamicSharedMemorySize, (int)fsmem);
    cudaFuncSetAttribute(attn_mma, cudaFuncAttributeMaxDynamicSharedMemorySize, ATTN_SMEM);

    const int actBlocks = (MROWS * HID / 4 + 255) / 256;
    dim3 wgrid(HID / 32, HID / 32);
    dim3 wgrid2(HID / 32, 2 * HID / 32);
    dim3 wblk(32, 8);
    dim3 ggrid(HID / 128, MROWS / 128);

    // --- Q projection -> bf16 hi/lo (pre-scaled 1/8) ---
    split_w<<<wgrid, wblk>>>(Wq, HID, HID, whi, wlo);
    split_act<<<actBlocks, 256>>>(query, ahi, alo);
    gemm_bf16<<<ggrid, 256, gsmem>>>(ahi, alo, whi, wlo, HID, bq, 0.125f, qhi_, qlo_);
    // --- K projection ---
    split_w<<<wgrid, wblk>>>(Wk, HID, HID, whi, wlo);
    split_act<<<actBlocks, 256>>>(key_t, ahi, alo);
    gemm_bf16<<<ggrid, 256, gsmem>>>(ahi, alo, whi, wlo, HID, bk, 1.f, khi_, klo_);
    // --- V projection ---
    split_w<<<wgrid, wblk>>>(Wv, HID, HID, whi, wlo);
    split_act<<<actBlocks, 256>>>(value, ahi, alo);
    gemm_bf16<<<ggrid, 256, gsmem>>>(ahi, alo, whi, wlo, HID, bv, 1.f, vhi_, vlo_);

    // --- attention (x out as fp16) ---
    attn_mma<<<dim3(SS / 32, NH, BB), 256, ATTN_SMEM>>>(
        qhi_, qlo_, khi_, klo_, vhi_, vlo_, mask, out_attn, xf);

    // --- Wo (fp16) -> cat[:, 0:768] ; query -> cat[:, 768:1536] ---
    split_w_fp16<<<wgrid, wblk>>>(Wo, HID, HID, wf);
    conv_fp16<<<actBlocks, 256>>>(query, cat);
    gemm_fp16<<<ggrid, 256, fsmem>>>(xf, HID, wf, HID, bo, nullptr, nullptr, cat, 2 * HID, 2);

    // --- FFN (fp16, K=1536) ---
    split_w_fp16<<<wgrid2, wblk>>>(W1, 2 * HID, HID, wf);
    gemm_fp16<<<ggrid, 256, fsmem>>>(cat, 2 * HID, wf, 2 * HID, b1, nullptr, F1, nullptr, 0, 0);
    split_w_fp16<<<wgrid2, wblk>>>(W2, 2 * HID, HID, wf);
    gemm_fp16<<<ggrid, 256, fsmem>>>(cat, 2 * HID, wf, 2 * HID, b2, F1, out_gated, nullptr, 0, 1);
}

// round 7
// speedup vs baseline: 4.2796x; 1.1752x over previous
#include <cuda_runtime.h>
#include <cuda_bf16.h>
#include <cuda_fp16.h>
#include <math.h>
#include <stdint.h>

#define BB 8
#define SS 1024
#define HID 768
#define NH 12
#define HD 64
#define MROWS (BB*SS)   // 8192
#define MH ((size_t)MROWS*HID)

// ---------------- scratch (device globals; no allocation allowed) ----------------
__device__ __align__(256) float g_f1 [(size_t)MROWS*HID];

__device__ __align__(256) __nv_bfloat16 g_shi[3*MH];            // split qkv inputs hi
__device__ __align__(256) __nv_bfloat16 g_slo[3*MH];
__device__ __align__(256) __nv_bfloat16 g_w3hi[(size_t)3*HID*HID];
__device__ __align__(256) __nv_bfloat16 g_w3lo[(size_t)3*HID*HID];

__device__ __align__(256) __nv_bfloat16 g_phi[3*MH];            // projected Q,K,V hi
__device__ __align__(256) __nv_bfloat16 g_plo[3*MH];

__device__ __align__(256) __half g_xf [MH];                     // attention x (fp16)
__device__ __align__(256) __half g_cat[2*MH];                   // concat(xo, query) fp16
__device__ __align__(256) __half g_wfo[(size_t)HID*HID];        // Wo fp16 [N][K]
__device__ __align__(256) __half g_wf [(size_t)2*2*HID*HID];    // W1,W2 fp16 [N][K]

// ================= helpers =================
__device__ __forceinline__ uint32_t smem_u32(const void* p) {
    uint32_t a;
    asm("{ .reg .u64 t; cvta.to.shared.u64 t, %1; cvt.u32.u64 %0, t; }" : "=r"(a) : "l"(p));
    return a;
}
__device__ __forceinline__ void ldsm_x4(uint32_t* r, uint32_t addr) {
    asm volatile("ldmatrix.sync.aligned.m8n8.x4.shared.b16 {%0,%1,%2,%3}, [%4];"
                 : "=r"(r[0]), "=r"(r[1]), "=r"(r[2]), "=r"(r[3]) : "r"(addr));
}
__device__ __forceinline__ void ldsm_x4_t(uint32_t* r, uint32_t addr) {
    asm volatile("ldmatrix.sync.aligned.m8n8.x4.trans.shared.b16 {%0,%1,%2,%3}, [%4];"
                 : "=r"(r[0]), "=r"(r[1]), "=r"(r[2]), "=r"(r[3]) : "r"(addr));
}
__device__ __forceinline__ void mma16816(float* c, const uint32_t* a, uint32_t b0, uint32_t b1) {
    asm volatile("mma.sync.aligned.m16n8k16.row.col.f32.bf16.bf16.f32 "
                 "{%0,%1,%2,%3}, {%4,%5,%6,%7}, {%8,%9}, {%0,%1,%2,%3};"
                 : "+f"(c[0]), "+f"(c[1]), "+f"(c[2]), "+f"(c[3])
                 : "r"(a[0]), "r"(a[1]), "r"(a[2]), "r"(a[3]), "r"(b0), "r"(b1));
}
__device__ __forceinline__ void mma16816h(float* c, const uint32_t* a, uint32_t b0, uint32_t b1) {
    asm volatile("mma.sync.aligned.m16n8k16.row.col.f32.f16.f16.f32 "
                 "{%0,%1,%2,%3}, {%4,%5,%6,%7}, {%8,%9}, {%0,%1,%2,%3};"
                 : "+f"(c[0]), "+f"(c[1]), "+f"(c[2]), "+f"(c[3])
                 : "r"(a[0]), "r"(a[1]), "r"(a[2]), "r"(a[3]), "r"(b0), "r"(b1));
}
__device__ __forceinline__ void cp16(uint32_t dst, const void* src) {
    asm volatile("cp.async.cg.shared.global [%0], [%1], 16;" :: "r"(dst), "l"(src));
}
#define CP_COMMIT() asm volatile("cp.async.commit_group;" ::: "memory")
#define CP_WAIT1()  asm volatile("cp.async.wait_group 1;" ::: "memory")
#define CP_WAIT0()  asm volatile("cp.async.wait_group 0;" ::: "memory")

// ================= split / convert kernels =================
__global__ void split_qkv(const float* __restrict__ s0, const float* __restrict__ s1,
                          const float* __restrict__ s2,
                          __nv_bfloat16* __restrict__ hi, __nv_bfloat16* __restrict__ lo)
{
    const int z = blockIdx.y;
    const float* src = (z == 0) ? s0 : (z == 1) ? s1 : s2;
    __nv_bfloat16* H = hi + (size_t)z * MH;
    __nv_bfloat16* L = lo + (size_t)z * MH;
    size_t total = MH / 4;
    for (size_t i = (size_t)blockIdx.x * blockDim.x + threadIdx.x; i < total;
         i += (size_t)gridDim.x * blockDim.x) {
        size_t e = i * 4;
        float4 v = *(const float4*)(src + e);
        __nv_bfloat16 h0 = __float2bfloat16(v.x), h1 = __float2bfloat16(v.y);
        __nv_bfloat16 h2 = __float2bfloat16(v.z), h3 = __float2bfloat16(v.w);
        *(__nv_bfloat162*)(H + e)     = __nv_bfloat162(h0, h1);
        *(__nv_bfloat162*)(H + e + 2) = __nv_bfloat162(h2, h3);
        *(__nv_bfloat162*)(L + e)     = __nv_bfloat162(__float2bfloat16(v.x - __bfloat162float(h0)),
                                                       __float2bfloat16(v.y - __bfloat162float(h1)));
        *(__nv_bfloat162*)(L + e + 2) = __nv_bfloat162(__float2bfloat16(v.z - __bfloat162float(h2)),
                                                       __float2bfloat16(v.w - __bfloat162float(h3)));
    }
}

__global__ void split_w3(const float* __restrict__ W0, const float* __restrict__ W1_,
                         const float* __restrict__ W2_,
                         __nv_bfloat16* __restrict__ hi, __nv_bfloat16* __restrict__ lo)
{
    __shared__ float t[32][33];
    const int z = blockIdx.z;
    const float* W = (z == 0) ? W0 : (z == 1) ? W1_ : W2_;
    __nv_bfloat16* H = hi + (size_t)z * HID * HID;
    __nv_bfloat16* L = lo + (size_t)z * HID * HID;
    int n0 = blockIdx.x * 32, k0 = blockIdx.y * 32;
    int tx = threadIdx.x, ty = threadIdx.y;
    for (int j = ty; j < 32; j += 8)
        t[j][tx] = W[(size_t)(k0 + j) * HID + n0 + tx];
    __syncthreads();
    for (int j = ty; j < 32; j += 8) {
        float x = t[tx][j];
        __nv_bfloat16 h = __float2bfloat16(x);
        size_t d = (size_t)(n0 + j) * HID + k0 + tx;
        H[d] = h; L[d] = __float2bfloat16(x - __bfloat162float(h));
    }
}

__global__ void split_w_fp16(const float* __restrict__ W, int K, int N,
                             __half* __restrict__ out)
{
    __shared__ float t[32][33];
    int n0 = blockIdx.x * 32, k0 = blockIdx.y * 32;
    int tx = threadIdx.x, ty = threadIdx.y;
    for (int j = ty; j < 32; j += 8)
        t[j][tx] = W[(size_t)(k0 + j) * N + n0 + tx];
    __syncthreads();
    for (int j = ty; j < 32; j += 8)
        out[(size_t)(n0 + j) * K + k0 + tx] = __float2half(t[tx][j]);
}

__global__ void split_wf2(const float* __restrict__ Wa, const float* __restrict__ Wb,
                          __half* __restrict__ out)
{
    __shared__ float t[32][33];
    const int z = blockIdx.z;
    const float* W = (z == 0) ? Wa : Wb;
    __half* O = out + (size_t)z * 2 * HID * HID;
    int n0 = blockIdx.x * 32, k0 = blockIdx.y * 32;
    int tx = threadIdx.x, ty = threadIdx.y;
    for (int j = ty; j < 32; j += 8)
        t[j][tx] = W[(size_t)(k0 + j) * HID + n0 + tx];
    __syncthreads();
    for (int j = ty; j < 32; j += 8)
        O[(size_t)(n0 + j) * (2 * HID) + k0 + tx] = __float2half(t[tx][j]);
}

__global__ void conv_fp16(const float* __restrict__ src, __half* __restrict__ dst)
{
    size_t total = MH / 4;
    for (size_t i = (size_t)blockIdx.x * blockDim.x + threadIdx.x; i < total;
         i += (size_t)gridDim.x * blockDim.x) {
        size_t e = i * 4;
        int m = (int)(e / HID), c = (int)(e % HID);
        float4 v = *(const float4*)(src + e);
        size_t d = (size_t)m * (2 * HID) + HID + c;
        *(__half2*)(dst + d)     = __halves2half2(__float2half(v.x), __float2half(v.y));
        *(__half2*)(dst + d + 2) = __halves2half2(__float2half(v.z), __float2half(v.w));
    }
}

// ================= bf16x3 GEMM, batched over z (QKV), epilogue -> bf16 hi/lo =================
#define GSTRIDE 72
#define GBUF (128 * GSTRIDE)
#define GSTAGE (4 * GBUF)

__global__ __launch_bounds__(256) void gemm_bf16(
    const __nv_bfloat16* __restrict__ AhiB, const __nv_bfloat16* __restrict__ AloB,
    const __nv_bfloat16* __restrict__ BhiB, const __nv_bfloat16* __restrict__ BloB,
    const float* __restrict__ b0p, const float* __restrict__ b1p, const float* __restrict__ b2p,
    __nv_bfloat16* __restrict__ outHiB, __nv_bfloat16* __restrict__ outLoB)
{
    extern __shared__ __nv_bfloat16 smg[];
    const int tid = threadIdx.x;
    const int w = tid >> 5, l = tid & 31;
    const int z = blockIdx.z;
    const int m0 = blockIdx.y * 128;
    const int n0 = blockIdx.x * 128;
    const int wm = (w >> 2) * 64;
    const int wn = (w & 3) * 32;

    const __nv_bfloat16* Ahi = AhiB + (size_t)z * MH;
    const __nv_bfloat16* Alo = AloB + (size_t)z * MH;
    const __nv_bfloat16* Bhi = BhiB + (size_t)z * HID * HID;
    const __nv_bfloat16* Blo = BloB + (size_t)z * HID * HID;
    const float* bias = (z == 0) ? b0p : (z == 1) ? b1p : b2p;
    const float scale = (z == 0) ? 0.125f : 1.f;
    __nv_bfloat16* outHi = outHiB + (size_t)z * MH;
    __nv_bfloat16* outLo = outLoB + (size_t)z * MH;

    float c[4][4][4];
    #pragma unroll
    for (int i = 0; i < 4; i++)
        #pragma unroll
        for (int j = 0; j < 4; j++)
            #pragma unroll
            for (int q = 0; q < 4; q++) c[i][j][q] = 0.f;

    const uint32_t sbase = smem_u32(smg);
    const int aRow = wm + (l & 15), aKof = (l >> 4) * 8;
    const int bRow = wn + (l >> 4) * 8 + (l & 7), bKof = ((l >> 3) & 1) * 8;
    const int nChunks = HID >> 6;   // 12

    auto issue = [&](int ch) {
        const uint32_t dstBase = sbase + (uint32_t)((ch & 1) * GSTAGE * 2);
        const int k0 = ch << 6;
        #pragma unroll
        for (int i = 0; i < 4; i++) {
            int t = tid + i * 256;
            int row = t >> 3, c8 = (t & 7) * 8;
            uint32_t d = dstBase + (uint32_t)((row * GSTRIDE + c8) * 2);
            size_t ga = (size_t)(m0 + row) * HID + k0 + c8;
            size_t gb = (size_t)(n0 + row) * HID + k0 + c8;
            cp16(d,                Ahi + ga);
            cp16(d + GBUF * 2,     Alo + ga);
            cp16(d + 2 * GBUF * 2, Bhi + gb);
            cp16(d + 3 * GBUF * 2, Blo + gb);
        }
    };

    issue(0); CP_COMMIT();
    for (int ch = 0; ch < nChunks; ch++) {
        if (ch + 1 < nChunks) { issue(ch + 1); CP_COMMIT(); CP_WAIT1(); }
        else                  { CP_WAIT0(); }
        __syncthreads();

        const uint32_t sb = sbase + (uint32_t)((ch & 1) * GSTAGE * 2);
        const uint32_t aHiB2 = sb + (uint32_t)((aRow * GSTRIDE + aKof) * 2);
        const uint32_t aLoB2 = aHiB2 + GBUF * 2;
        const uint32_t bHiB2 = sb + 2 * GBUF * 2 + (uint32_t)((bRow * GSTRIDE + bKof) * 2);
        const uint32_t bLoB2 = bHiB2 + GBUF * 2;

        #pragma unroll
        for (int ks = 0; ks < 4; ks++) {
            const uint32_t kb = (uint32_t)(ks * 16 * 2);
            uint32_t ah[4][4], al[4][4], bh[2][4], bl[2][4];
            #pragma unroll
            for (int mi = 0; mi < 4; mi++) {
                ldsm_x4(ah[mi], aHiB2 + (uint32_t)(mi * 16 * GSTRIDE * 2) + kb);
                ldsm_x4(al[mi], aLoB2 + (uint32_t)(mi * 16 * GSTRIDE * 2) + kb);
            }
            #pragma unroll
            for (int p = 0; p < 2; p++) {
                ldsm_x4(bh[p], bHiB2 + (uint32_t)(p * 16 * GSTRIDE * 2) + kb);
                ldsm_x4(bl[p], bLoB2 + (uint32_t)(p * 16 * GSTRIDE * 2) + kb);
            }
            #pragma unroll
            for (int mi = 0; mi < 4; mi++) {
                #pragma unroll
                for (int nj = 0; nj < 4; nj++) {
                    const int p = nj >> 1, s = (nj & 1) * 2;
                    mma16816(c[mi][nj], ah[mi], bh[p][s], bh[p][s + 1]);
                    mma16816(c[mi][nj], ah[mi], bl[p][s], bl[p][s + 1]);
                    mma16816(c[mi][nj], al[mi], bh[p][s], bh[p][s + 1]);
                }
            }
        }
        __syncthreads();
    }

    #pragma unroll
    for (int mi = 0; mi < 4; mi++) {
        int r0 = m0 + wm + mi * 16 + (l >> 2);
        #pragma unroll
        for (int nj = 0; nj < 4; nj++) {
            int col = n0 + wn + nj * 8 + (l & 3) * 2;
            float b0 = bias[col], b1 = bias[col + 1];
            #pragma unroll
            for (int half = 0; half < 2; half++) {
                int r = r0 + half * 8;
                float v0 = (c[mi][nj][half * 2 + 0] + b0) * scale;
                float v1 = (c[mi][nj][half * 2 + 1] + b1) * scale;
                __nv_bfloat16 h0 = __float2bfloat16(v0);
                __nv_bfloat16 h1 = __float2bfloat16(v1);
                size_t g = (size_t)r * HID + col;
                *(__nv_bfloat162*)(outHi + g) = __nv_bfloat162(h0, h1);
                *(__nv_bfloat162*)(outLo + g) = __nv_bfloat162(
                    __float2bfloat16(v0 - __bfloat162float(h0)),
                    __float2bfloat16(v1 - __bfloat162float(h1)));
            }
        }
    }
}

// ================= fp16 single-term GEMM (cp.async pipeline) =================
#define FSTAGE (2 * GBUF)

__global__ __launch_bounds__(256) void gemm_fp16(
    const __half* __restrict__ A, int lda, const __half* __restrict__ B,
    int Kdim, const float* __restrict__ bias, const float* __restrict__ prev,
    float* __restrict__ Cf, __half* __restrict__ Ch, int ldch, int mode)
{
    extern __shared__ __half smh[];
    const int tid = threadIdx.x;
    const int w = tid >> 5, l = tid & 31;
    const int m0 = blockIdx.y * 128;
    const int n0 = blockIdx.x * 128;
    const int wm = (w >> 2) * 64;
    const int wn = (w & 3) * 32;

    float c[4][4][4];
    #pragma unroll
    for (int i = 0; i < 4; i++)
        #pragma unroll
        for (int j = 0; j < 4; j++)
            #pragma unroll
            for (int q = 0; q < 4; q++) c[i][j][q] = 0.f;

    const uint32_t sbase = smem_u32(smh);
    const int aRow = wm + (l & 15), aKof = (l >> 4) * 8;
    const int bRow = wn + (l >> 4) * 8 + (l & 7), bKof = ((l >> 3) & 1) * 8;
    const int nChunks = Kdim >> 6;

    auto issue = [&](int ch) {
        const uint32_t dstBase = sbase + (uint32_t)((ch & 1) * FSTAGE * 2);
        const int k0 = ch << 6;
        #pragma unroll
        for (int i = 0; i < 4; i++) {
            int t = tid + i * 256;
            int row = t >> 3, c8 = (t & 7) * 8;
            uint32_t d = dstBase + (uint32_t)((row * GSTRIDE + c8) * 2);
            cp16(d,            A + (size_t)(m0 + row) * lda  + k0 + c8);
            cp16(d + GBUF * 2, B + (size_t)(n0 + row) * Kdim + k0 + c8);
        }
    };

    issue(0); CP_COMMIT();
    for (int ch = 0; ch < nChunks; ch++) {
        if (ch + 1 < nChunks) { issue(ch + 1); CP_COMMIT(); CP_WAIT1(); }
        else                  { CP_WAIT0(); }
        __syncthreads();

        const uint32_t sb = sbase + (uint32_t)((ch & 1) * FSTAGE * 2);
        const uint32_t aB = sb + (uint32_t)((aRow * GSTRIDE + aKof) * 2);
        const uint32_t bB = sb + GBUF * 2 + (uint32_t)((bRow * GSTRIDE + bKof) * 2);

        #pragma unroll
        for (int ks = 0; ks < 4; ks++) {
            const uint32_t kb = (uint32_t)(ks * 16 * 2);
            uint32_t ah[4][4], bh[2][4];
            #pragma unroll
            for (int mi = 0; mi < 4; mi++)
                ldsm_x4(ah[mi], aB + (uint32_t)(mi * 16 * GSTRIDE * 2) + kb);
            #pragma unroll
            for (int p = 0; p < 2; p++)
                ldsm_x4(bh[p], bB + (uint32_t)(p * 16 * GSTRIDE * 2) + kb);
            #pragma unroll
            for (int mi = 0; mi < 4; mi++) {
                #pragma unroll
                for (int nj = 0; nj < 4; nj++) {
                    const int p = nj >> 1, s = (nj & 1) * 2;
                    mma16816h(c[mi][nj], ah[mi], bh[p][s], bh[p][s + 1]);
                }
            }
        }
        __syncthreads();
    }

    #pragma unroll
    for (int mi = 0; mi < 4; mi++) {
        int r0 = m0 + wm + mi * 16 + (l >> 2);
        #pragma unroll
        for (int nj = 0; nj < 4; nj++) {
            int col = n0 + wn + nj * 8 + (l & 3) * 2;
            float b0 = bias[col], b1 = bias[col + 1];
            #pragma unroll
            for (int half = 0; half < 2; half++) {
                int r = r0 + half * 8;
                float v0 = c[mi][nj][half * 2 + 0] + b0;
                float v1 = c[mi][nj][half * 2 + 1] + b1;
                if (mode == 2) {
                    *(__half2*)(Ch + (size_t)r * ldch + col) =
                        __halves2half2(__float2half(v0), __float2half(v1));
                } else {
                    if (mode == 1) {
                        float g0 = prev[(size_t)r * HID + col];
                        float g1 = prev[(size_t)r * HID + col + 1];
                        v0 *= 1.f / (1.f + __expf(-g0));
                        v1 *= 1.f / (1.f + __expf(-g1));
                    }
                    *(float2*)(Cf + (size_t)r * HID + col) = make_float2(v0, v1);
                }
            }
        }
    }
}

// ================= tensor-core attention (bf16x3), cp.async pipelined =================
#define EST 1032
#define KVST 72
#define STG_B 36864
#define ATTN_SMEM 215168

__global__ __launch_bounds__(256) void attn_mma(
    const __nv_bfloat16* __restrict__ phi, const __nv_bfloat16* __restrict__ plo,
    const int* __restrict__ mask, float* __restrict__ attn_out,
    __half* __restrict__ xf)
{
    extern __shared__ char sab[];
    __nv_bfloat16* sQh = (__nv_bfloat16*)(sab);
    __nv_bfloat16* sEh = (__nv_bfloat16*)(sab + 82944);
    __nv_bfloat16* sEl = (__nv_bfloat16*)(sab + 148992);
    float* sInv  = (float*)(sab + 215040);
    float* sPart = (float*)(sab + 9216);

    const int tid = threadIdx.x, w = tid >> 5, l = tid & 31;
    const int q0 = blockIdx.x * 32, h = blockIdx.y, b = blockIdx.z;

    const __nv_bfloat16* qhi = phi;
    const __nv_bfloat16* qlo = plo;
    const __nv_bfloat16* khi = phi + MH;
    const __nv_bfloat16* klo = plo + MH;
    const __nv_bfloat16* vhi = phi + 2 * MH;
    const __nv_bfloat16* vlo = plo + 2 * MH;

    const uint32_t uQh = smem_u32(sab);
    const uint32_t uQl = uQh + 4608;
    const uint32_t uK0 = uQh + 9216;
    const uint32_t uEh = uQh + 82944;
    const uint32_t uEl = uQh + 148992;

    {
        int r = tid >> 3, c8 = (tid & 7) * 8;
        size_t g = ((size_t)(b * SS + q0 + r)) * HID + h * HD + c8;
        *(uint4*)(sQh + r * KVST + c8)        = *(const uint4*)(qhi + g);
        *(uint4*)(sQh + 2304 + r * KVST + c8) = *(const uint4*)(qlo + g);
    }

    const uint32_t aLaneOff = (uint32_t)(((l & 15) * KVST + (l >> 4) * 8) * 2);
    const int bRowL = (l >> 4) * 8 + (l & 7);
    const int bKofL = ((l >> 3) & 1) * 8;

    auto issueKV = [&](const __nv_bfloat16* srcHi, const __nv_bfloat16* srcLo, int ch) {
        const uint32_t dst = uK0 + (uint32_t)((ch & 1) * STG_B);
        const int r0 = ch * 128;
        #pragma unroll
        for (int i = 0; i < 4; i++) {
            int t = tid + i * 256;
            int row = t >> 3, c8 = (t & 7) * 8;
            uint32_t d = dst + (uint32_t)((row * KVST + c8) * 2);
            size_t g = ((size_t)(b * SS + r0 + row)) * HID + h * HD + c8;
            cp16(d,         srcHi + g);
            cp16(d + 18432, srcLo + g);
        }
    };

    // ---------- Phase A ----------
    issueKV(khi, klo, 0); CP_COMMIT();
    for (int ch = 0; ch < 8; ch++) {
        if (ch + 1 < 8) { issueKV(khi, klo, ch + 1); CP_COMMIT(); CP_WAIT1(); }
        else            { CP_WAIT0(); }
        __syncthreads();

        const uint32_t sb = uK0 + (uint32_t)((ch & 1) * STG_B);
        const int kc0 = ch * 128;

        float c[2][2][4];
        #pragma unroll
        for (int m = 0; m < 2; m++)
            #pragma unroll
            for (int nj = 0; nj < 2; nj++)
                #pragma unroll
                for (int q = 0; q < 4; q++) c[m][nj][q] = 0.f;

        #pragma unroll
        for (int ks = 0; ks < 4; ks++) {
            uint32_t ah[2][4], al[2][4], bh[4], bl[4];
            #pragma unroll
            for (int m = 0; m < 2; m++) {
                uint32_t off = (uint32_t)((m * 16 * KVST + ks * 16) * 2) + aLaneOff;
                ldsm_x4(ah[m], uQh + off);
                ldsm_x4(al[m], uQl + off);
            }
            {
                uint32_t off = (uint32_t)(((w * 16 + bRowL) * KVST + ks * 16 + bKofL) * 2);
                ldsm_x4(bh, sb + off);
                ldsm_x4(bl, sb + 18432 + off);
            }
            #pragma unroll
            for (int m = 0; m < 2; m++) {
                #pragma unroll
                for (int nj = 0; nj < 2; nj++) {
                    const int s = nj * 2;
                    mma16816(c[m][nj], ah[m], bh[s], bh[s + 1]);
                    mma16816(c[m][nj], ah[m], bl[s], bl[s + 1]);
                    mma16816(c[m][nj], al[m], bh[s], bh[s + 1]);
                }
            }
        }
        #pragma unroll
        for (int m = 0; m < 2; m++) {
            #pragma unroll
            for (int nj = 0; nj < 2; nj++) {
                int kcol = kc0 + w * 16 + nj * 8 + (l & 3) * 2;
                #pragma unroll
                for (int hf = 0; hf < 2; hf++) {
                    int row = m * 16 + (l >> 2) + hf * 8;
                    float s0 = c[m][nj][hf * 2 + 0];
                    float s1 = c[m][nj][hf * 2 + 1];
                    __nv_bfloat16 h0 = __float2bfloat16(s0);
                    __nv_bfloat16 h1 = __float2bfloat16(s1);
                    sEh[row * EST + kcol]     = h0;
                    sEh[row * EST + kcol + 1] = h1;
                    sEl[row * EST + kcol]     = __float2bfloat16(s0 - __bfloat162float(h0));
                    sEl[row * EST + kcol + 1] = __float2bfloat16(s1 - __bfloat162float(h1));
                }
            }
        }
        __syncthreads();
    }

    // prefetch first V chunk; lands during Phase B
    issueKV(vhi, vlo, 0); CP_COMMIT();

    // ---------- Phase B ----------
    const int* mrow = mask + b * SS;
    for (int r = w * 4; r < w * 4 + 4; r++) {
        __nv_bfloat16* eh = sEh + r * EST;
        __nv_bfloat16* el = sEl + r * EST;
        float mx = -3.4e38f;
        for (int i = 0; i < 32; i++) {
            int k = i * 32 + l;
            float s = __bfloat162float(eh[k]) + __bfloat162float(el[k]);
            if (mrow[k] == 0) s = -1e10f;
            mx = fmaxf(mx, s);
        }
        #pragma unroll
        for (int o = 16; o > 0; o >>= 1) mx = fmaxf(mx, __shfl_xor_sync(0xffffffffu, mx, o));
        float sum = 0.f;
        for (int i = 0; i < 32; i++) {
            int k = i * 32 + l;
            float s = __bfloat162float(eh[k]) + __bfloat162float(el[k]);
            if (mrow[k] == 0) s = -1e10f;
            float e = __expf(s - mx);
            sum += e;
            __nv_bfloat16 hh = __float2bfloat16(e);
            eh[k] = hh;
            el[k] = __float2bfloat16(e - __bfloat162float(hh));
        }
        #pragma unroll
        for (int o = 16; o > 0; o >>= 1) sum += __shfl_xor_sync(0xffffffffu, sum, o);
        float inv = 1.f / sum;
        if (l == 0) sInv[r] = inv;
        float* orow = attn_out + ((size_t)((b * NH + h) * SS + q0 + r)) * SS;
        for (int i = 0; i < 32; i++) {
            int k = i * 32 + l;
            float e = __bfloat162float(eh[k]) + __bfloat162float(el[k]);
            orow[k] = e * inv;
        }
    }

    // ---------- Phase C ----------
    const int dg = (w & 3) * 16;
    const int khalf = w >> 2;
    float cc[2][2][4];
    #pragma unroll
    for (int m = 0; m < 2; m++)
        #pragma unroll
        for (int nt = 0; nt < 2; nt++)
            #pragma unroll
            for (int q = 0; q < 4; q++) cc[m][nt][q] = 0.f;

    for (int ch = 0; ch < 8; ch++) {
        if (ch + 1 < 8) { issueKV(vhi, vlo, ch + 1); CP_COMMIT(); CP_WAIT1(); }
        else            { CP_WAIT0(); }
        __syncthreads();

        if ((ch >> 2) == khalf) {
            const uint32_t sb = uK0 + (uint32_t)((ch & 1) * STG_B);
            const int kc0 = ch * 128;
            #pragma unroll 4
            for (int ks = 0; ks < 8; ks++) {
                uint32_t ah2[2][4], al2[2][4], bh2[4], bl2[4];
                uint32_t ecol = (uint32_t)((kc0 + ks * 16 + (l >> 4) * 8) * 2);
                #pragma unroll
                for (int m = 0; m < 2; m++) {
                    uint32_t off = (uint32_t)(((m * 16 + (l & 15)) * EST) * 2) + ecol;
                    ldsm_x4(ah2[m], uEh + off);
                    ldsm_x4(al2[m], uEl + off);
                }
                uint32_t voff = (uint32_t)(((ks * 16 + (l & 15)) * KVST + dg + (l >> 4) * 8) * 2);
                ldsm_x4_t(bh2, sb + voff);
                ldsm_x4_t(bl2, sb + 18432 + voff);
                #pragma unroll
                for (int m = 0; m < 2; m++) {
                    #pragma unroll
                    for (int nt = 0; nt < 2; nt++) {
                        mma16816(cc[m][nt], ah2[m], bh2[nt * 2], bh2[nt * 2 + 1]);
                        mma16816(cc[m][nt], ah2[m], bl2[nt * 2], bl2[nt * 2 + 1]);
                        mma16816(cc[m][nt], al2[m], bh2[nt * 2], bh2[nt * 2 + 1]);
                    }
                }
            }
        }
        __syncthreads();
    }

    if (w >= 4) {
        #pragma unroll
        for (int m = 0; m < 2; m++)
            #pragma unroll
            for (int nt = 0; nt < 2; nt++)
                #pragma unroll
                for (int v = 0; v < 4; v++) {
                    int row = m * 16 + (l >> 2) + (v >> 1) * 8;
                    int col = dg + nt * 8 + (l & 3) * 2 + (v & 1);
                    sPart[row * 64 + col] = cc[m][nt][v];
                }
    }
    __syncthreads();
    if (w < 4) {
        #pragma unroll
        for (int m = 0; m < 2; m++) {
            #pragma unroll
            for (int nt = 0; nt < 2; nt++) {
                #pragma unroll
                for (int hf = 0; hf < 2; hf++) {
                    int row = m * 16 + (l >> 2) + hf * 8;
                    int col = dg + nt * 8 + (l & 3) * 2;
                    float inv = sInv[row];
                    float x0 = (cc[m][nt][hf * 2 + 0] + sPart[row * 64 + col])     * inv;
                    float x1 = (cc[m][nt][hf * 2 + 1] + sPart[row * 64 + col + 1]) * inv;
                    size_t g = ((size_t)(b * SS + q0 + row)) * HID + h * HD + col;
                    *(__half2*)(xf + g) = __halves2half2(__float2half(x0), __float2half(x1));
                }
            }
        }
    }
}

// ================= launch =================
extern "C" void kernel_launch(void* const* d_in, const int* in_sizes, int n_in,
                              void* d_out, int out_size)
{
    const float* query = (const float*)d_in[0];
    const float* key_t = (const float*)d_in[1];
    const float* value = (const float*)d_in[2];
    const int*   mask  = (const int*)d_in[3];
    const float* Wq = (const float*)d_in[4];  const float* bq = (const float*)d_in[5];
    const float* Wk = (const float*)d_in[6];  const float* bk = (const float*)d_in[7];
    const float* Wv = (const float*)d_in[8];  const float* bv = (const float*)d_in[9];
    const float* Wo = (const float*)d_in[10]; const float* bo = (const float*)d_in[11];
    const float* W1 = (const float*)d_in[12]; const float* b1 = (const float*)d_in[13];
    const float* W2 = (const float*)d_in[14]; const float* b2 = (const float*)d_in[15];

    float* out       = (float*)d_out;
    float* out_gated = out;
    float* out_attn  = out + MH;

    float *F1;
    __nv_bfloat16 *shi, *slo, *w3hi, *w3lo, *phi, *plo;
    __half *xf, *cat, *wfo, *wf;
    cudaGetSymbolAddress((void**)&F1, g_f1);
    cudaGetSymbolAddress((void**)&shi, g_shi);
    cudaGetSymbolAddress((void**)&slo, g_slo);
    cudaGetSymbolAddress((void**)&w3hi, g_w3hi);
    cudaGetSymbolAddress((void**)&w3lo, g_w3lo);
    cudaGetSymbolAddress((void**)&phi, g_phi);
    cudaGetSymbolAddress((void**)&plo, g_plo);
    cudaGetSymbolAddress((void**)&xf, g_xf);
    cudaGetSymbolAddress((void**)&cat, g_cat);
    cudaGetSymbolAddress((void**)&wfo, g_wfo);
    cudaGetSymbolAddress((void**)&wf, g_wf);

    size_t gsmem = (size_t)2 * GSTAGE * 2;   // 147456 B
    size_t fsmem = (size_t)2 * FSTAGE * 2;   // 73728 B
    cudaFuncSetAttribute(gemm_bf16, cudaFuncAttributeMaxDynamicSharedMemorySize, (int)gsmem);
    cudaFuncSetAttribute(gemm_fp16, cudaFuncAttributeMaxDynamicSharedMemorySize, (int)fsmem);
    cudaFuncSetAttribute(attn_mma, cudaFuncAttributeMaxDynamicSharedMemorySize, ATTN_SMEM);

    const int actBlocks = (MROWS * HID / 4 + 255) / 256;
    dim3 wblk(32, 8);

    // --- QKV: batched splits + batched GEMM ---
    split_w3<<<dim3(HID / 32, HID / 32, 3), wblk>>>(Wq, Wk, Wv, w3hi, w3lo);
    split_qkv<<<dim3(actBlocks, 3), 256>>>(query, key_t, value, shi, slo);
    gemm_bf16<<<dim3(HID / 128, MROWS / 128, 3), 256, gsmem>>>(
        shi, slo, w3hi, w3lo, bq, bk, bv, phi, plo);

    // --- attention (pipelined) ---
    attn_mma<<<dim3(SS / 32, NH, BB), 256, ATTN_SMEM>>>(phi, plo, mask, out_attn, xf);

    // --- Wo (fp16) -> cat[:, 0:768] ; query -> cat[:, 768:1536] ---
    split_w_fp16<<<dim3(HID / 32, HID / 32), wblk>>>(Wo, HID, HID, wfo);
    conv_fp16<<<actBlocks, 256>>>(query, cat);
    gemm_fp16<<<dim3(HID / 128, MROWS / 128), 256, fsmem>>>(
        xf, HID, wfo, HID, bo, nullptr, nullptr, cat, 2 * HID, 2);

    // --- FFN (fp16, K=1536) ---
    split_wf2<<<dim3(HID / 32, 2 * HID / 32, 2), wblk>>>(W1, W2, wf);
    gemm_fp16<<<dim3(HID / 128, MROWS / 128), 256, fsmem>>>(
        cat, 2 * HID, wf, 2 * HID, b1, nullptr, F1, nullptr, 0, 0);
    gemm_fp16<<<dim3(HID / 128, MROWS / 128), 256, fsmem>>>(
        cat, 2 * HID, wf + (size_t)2 * HID * HID, 2 * HID, b2, F1, out_gated, nullptr, 0, 1);
}

// round 9
// speedup vs baseline: 5.1531x; 1.2041x over previous
#include <cuda_runtime.h>
#include <cuda_bf16.h>
#include <cuda_fp16.h>
#include <math.h>
#include <stdint.h>

#define BB 8
#define SS 1024
#define HID 768
#define NH 12
#define HD 64
#define MROWS (BB*SS)   // 8192
#define MH ((size_t)MROWS*HID)

// ---------------- scratch (device globals; no allocation allowed) ----------------
__device__ __align__(256) float g_f1 [(size_t)MROWS*HID];

__device__ __align__(256) __nv_bfloat16 g_shi[3*MH];
__device__ __align__(256) __nv_bfloat16 g_slo[3*MH];
__device__ __align__(256) __nv_bfloat16 g_w3hi[(size_t)3*HID*HID];
__device__ __align__(256) __nv_bfloat16 g_w3lo[(size_t)3*HID*HID];

__device__ __align__(256) __nv_bfloat16 g_phi[2*MH];       // projected Q,K (bf16 hi)
__device__ __align__(256) __nv_bfloat16 g_plo[2*MH];
__device__ __align__(256) __half g_vfhi[MH];               // projected V (fp16 hi/lo)
__device__ __align__(256) __half g_vflo[MH];

__device__ __align__(256) __half g_xf [MH];
__device__ __align__(256) __half g_cat[2*MH];
__device__ __align__(256) __half g_wfo[(size_t)HID*HID];
__device__ __align__(256) __half g_wf [(size_t)2*2*HID*HID];

// ================= helpers =================
__device__ __forceinline__ uint32_t smem_u32(const void* p) {
    uint32_t a;
    asm("{ .reg .u64 t; cvta.to.shared.u64 t, %1; cvt.u32.u64 %0, t; }" : "=r"(a) : "l"(p));
    return a;
}
__device__ __forceinline__ void ldsm_x4(uint32_t* r, uint32_t addr) {
    asm volatile("ldmatrix.sync.aligned.m8n8.x4.shared.b16 {%0,%1,%2,%3}, [%4];"
                 : "=r"(r[0]), "=r"(r[1]), "=r"(r[2]), "=r"(r[3]) : "r"(addr));
}
__device__ __forceinline__ void ldsm_x4_t(uint32_t* r, uint32_t addr) {
    asm volatile("ldmatrix.sync.aligned.m8n8.x4.trans.shared.b16 {%0,%1,%2,%3}, [%4];"
                 : "=r"(r[0]), "=r"(r[1]), "=r"(r[2]), "=r"(r[3]) : "r"(addr));
}
__device__ __forceinline__ void mma16816(float* c, const uint32_t* a, uint32_t b0, uint32_t b1) {
    asm volatile("mma.sync.aligned.m16n8k16.row.col.f32.bf16.bf16.f32 "
                 "{%0,%1,%2,%3}, {%4,%5,%6,%7}, {%8,%9}, {%0,%1,%2,%3};"
                 : "+f"(c[0]), "+f"(c[1]), "+f"(c[2]), "+f"(c[3])
                 : "r"(a[0]), "r"(a[1]), "r"(a[2]), "r"(a[3]), "r"(b0), "r"(b1));
}
__device__ __forceinline__ void mma16816h(float* c, const uint32_t* a, uint32_t b0, uint32_t b1) {
    asm volatile("mma.sync.aligned.m16n8k16.row.col.f32.f16.f16.f32 "
                 "{%0,%1,%2,%3}, {%4,%5,%6,%7}, {%8,%9}, {%0,%1,%2,%3};"
                 : "+f"(c[0]), "+f"(c[1]), "+f"(c[2]), "+f"(c[3])
                 : "r"(a[0]), "r"(a[1]), "r"(a[2]), "r"(a[3]), "r"(b0), "r"(b1));
}
__device__ __forceinline__ void cp16(uint32_t dst, const void* src) {
    asm volatile("cp.async.cg.shared.global [%0], [%1], 16;" :: "r"(dst), "l"(src));
}
#define CP_COMMIT() asm volatile("cp.async.commit_group;" ::: "memory")
#define CP_WAIT1()  asm volatile("cp.async.wait_group 1;" ::: "memory")
#define CP_WAIT0()  asm volatile("cp.async.wait_group 0;" ::: "memory")

// ================= split / convert kernels =================
__global__ void split_qkv(const float* __restrict__ s0, const float* __restrict__ s1,
                          const float* __restrict__ s2,
                          __nv_bfloat16* __restrict__ hi, __nv_bfloat16* __restrict__ lo)
{
    const int z = blockIdx.y;
    const float* src = (z == 0) ? s0 : (z == 1) ? s1 : s2;
    __nv_bfloat16* H = hi + (size_t)z * MH;
    __nv_bfloat16* L = lo + (size_t)z * MH;
    size_t total = MH / 4;
    for (size_t i = (size_t)blockIdx.x * blockDim.x + threadIdx.x; i < total;
         i += (size_t)gridDim.x * blockDim.x) {
        size_t e = i * 4;
        float4 v = *(const float4*)(src + e);
        __nv_bfloat16 h0 = __float2bfloat16(v.x), h1 = __float2bfloat16(v.y);
        __nv_bfloat16 h2 = __float2bfloat16(v.z), h3 = __float2bfloat16(v.w);
        *(__nv_bfloat162*)(H + e)     = __nv_bfloat162(h0, h1);
        *(__nv_bfloat162*)(H + e + 2) = __nv_bfloat162(h2, h3);
        *(__nv_bfloat162*)(L + e)     = __nv_bfloat162(__float2bfloat16(v.x - __bfloat162float(h0)),
                                                       __float2bfloat16(v.y - __bfloat162float(h1)));
        *(__nv_bfloat162*)(L + e + 2) = __nv_bfloat162(__float2bfloat16(v.z - __bfloat162float(h2)),
                                                       __float2bfloat16(v.w - __bfloat162float(h3)));
    }
}

__global__ void split_w3(const float* __restrict__ W0, const float* __restrict__ W1_,
                         const float* __restrict__ W2_,
                         __nv_bfloat16* __restrict__ hi, __nv_bfloat16* __restrict__ lo)
{
    __shared__ float t[32][33];
    const int z = blockIdx.z;
    const float* W = (z == 0) ? W0 : (z == 1) ? W1_ : W2_;
    __nv_bfloat16* H = hi + (size_t)z * HID * HID;
    __nv_bfloat16* L = lo + (size_t)z * HID * HID;
    int n0 = blockIdx.x * 32, k0 = blockIdx.y * 32;
    int tx = threadIdx.x, ty = threadIdx.y;
    for (int j = ty; j < 32; j += 8)
        t[j][tx] = W[(size_t)(k0 + j) * HID + n0 + tx];
    __syncthreads();
    for (int j = ty; j < 32; j += 8) {
        float x = t[tx][j];
        __nv_bfloat16 h = __float2bfloat16(x);
        size_t d = (size_t)(n0 + j) * HID + k0 + tx;
        H[d] = h; L[d] = __float2bfloat16(x - __bfloat162float(h));
    }
}

__global__ void split_w_fp16(const float* __restrict__ W, int K, int N,
                             __half* __restrict__ out)
{
    __shared__ float t[32][33];
    int n0 = blockIdx.x * 32, k0 = blockIdx.y * 32;
    int tx = threadIdx.x, ty = threadIdx.y;
    for (int j = ty; j < 32; j += 8)
        t[j][tx] = W[(size_t)(k0 + j) * N + n0 + tx];
    __syncthreads();
    for (int j = ty; j < 32; j += 8)
        out[(size_t)(n0 + j) * K + k0 + tx] = __float2half(t[tx][j]);
}

__global__ void split_wf2(const float* __restrict__ Wa, const float* __restrict__ Wb,
                          __half* __restrict__ out)
{
    __shared__ float t[32][33];
    const int z = blockIdx.z;
    const float* W = (z == 0) ? Wa : Wb;
    __half* O = out + (size_t)z * 2 * HID * HID;
    int n0 = blockIdx.x * 32, k0 = blockIdx.y * 32;
    int tx = threadIdx.x, ty = threadIdx.y;
    for (int j = ty; j < 32; j += 8)
        t[j][tx] = W[(size_t)(k0 + j) * HID + n0 + tx];
    __syncthreads();
    for (int j = ty; j < 32; j += 8)
        O[(size_t)(n0 + j) * (2 * HID) + k0 + tx] = __float2half(t[tx][j]);
}

__global__ void conv_fp16(const float* __restrict__ src, __half* __restrict__ dst)
{
    size_t total = MH / 4;
    for (size_t i = (size_t)blockIdx.x * blockDim.x + threadIdx.x; i < total;
         i += (size_t)gridDim.x * blockDim.x) {
        size_t e = i * 4;
        int m = (int)(e / HID), c = (int)(e % HID);
        float4 v = *(const float4*)(src + e);
        size_t d = (size_t)m * (2 * HID) + HID + c;
        *(__half2*)(dst + d)     = __halves2half2(__float2half(v.x), __float2half(v.y));
        *(__half2*)(dst + d + 2) = __halves2half2(__float2half(v.z), __float2half(v.w));
    }
}

// ================= bf16x3 GEMM, batched over z (QKV) =================
// z 0/1 (Q,K): epilogue -> bf16 hi/lo ; z 2 (V): epilogue -> fp16 hi/lo
#define GSTRIDE 72
#define GBUF (128 * GSTRIDE)
#define GSTAGE (4 * GBUF)

__global__ __launch_bounds__(256) void gemm_bf16(
    const __nv_bfloat16* __restrict__ AhiB, const __nv_bfloat16* __restrict__ AloB,
    const __nv_bfloat16* __restrict__ BhiB, const __nv_bfloat16* __restrict__ BloB,
    const float* __restrict__ b0p, const float* __restrict__ b1p, const float* __restrict__ b2p,
    __nv_bfloat16* __restrict__ outHiB, __nv_bfloat16* __restrict__ outLoB,
    __half* __restrict__ vfHi, __half* __restrict__ vfLo)
{
    extern __shared__ __nv_bfloat16 smg[];
    const int tid = threadIdx.x;
    const int w = tid >> 5, l = tid & 31;
    const int z = blockIdx.z;
    const int m0 = blockIdx.y * 128;
    const int n0 = blockIdx.x * 128;
    const int wm = (w >> 2) * 64;
    const int wn = (w & 3) * 32;

    const __nv_bfloat16* Ahi = AhiB + (size_t)z * MH;
    const __nv_bfloat16* Alo = AloB + (size_t)z * MH;
    const __nv_bfloat16* Bhi = BhiB + (size_t)z * HID * HID;
    const __nv_bfloat16* Blo = BloB + (size_t)z * HID * HID;
    const float* bias = (z == 0) ? b0p : (z == 1) ? b1p : b2p;
    const float scale = (z == 0) ? 0.125f : 1.f;

    float c[4][4][4];
    #pragma unroll
    for (int i = 0; i < 4; i++)
        #pragma unroll
        for (int j = 0; j < 4; j++)
            #pragma unroll
            for (int q = 0; q < 4; q++) c[i][j][q] = 0.f;

    const uint32_t sbase = smem_u32(smg);
    const int aRow = wm + (l & 15), aKof = (l >> 4) * 8;
    const int bRow = wn + (l >> 4) * 8 + (l & 7), bKof = ((l >> 3) & 1) * 8;
    const int nChunks = HID >> 6;

    auto issue = [&](int ch) {
        const uint32_t dstBase = sbase + (uint32_t)((ch & 1) * GSTAGE * 2);
        const int k0 = ch << 6;
        #pragma unroll
        for (int i = 0; i < 4; i++) {
            int t = tid + i * 256;
            int row = t >> 3, c8 = (t & 7) * 8;
            uint32_t d = dstBase + (uint32_t)((row * GSTRIDE + c8) * 2);
            size_t ga = (size_t)(m0 + row) * HID + k0 + c8;
            size_t gb = (size_t)(n0 + row) * HID + k0 + c8;
            cp16(d,                Ahi + ga);
            cp16(d + GBUF * 2,     Alo + ga);
            cp16(d + 2 * GBUF * 2, Bhi + gb);
            cp16(d + 3 * GBUF * 2, Blo + gb);
        }
    };

    issue(0); CP_COMMIT();
    for (int ch = 0; ch < nChunks; ch++) {
        if (ch + 1 < nChunks) { issue(ch + 1); CP_COMMIT(); CP_WAIT1(); }
        else                  { CP_WAIT0(); }
        __syncthreads();

        const uint32_t sb = sbase + (uint32_t)((ch & 1) * GSTAGE * 2);
        const uint32_t aHiB2 = sb + (uint32_t)((aRow * GSTRIDE + aKof) * 2);
        const uint32_t aLoB2 = aHiB2 + GBUF * 2;
        const uint32_t bHiB2 = sb + 2 * GBUF * 2 + (uint32_t)((bRow * GSTRIDE + bKof) * 2);
        const uint32_t bLoB2 = bHiB2 + GBUF * 2;

        #pragma unroll
        for (int ks = 0; ks < 4; ks++) {
            const uint32_t kb = (uint32_t)(ks * 16 * 2);
            uint32_t ah[4][4], al[4][4], bh[2][4], bl[2][4];
            #pragma unroll
            for (int mi = 0; mi < 4; mi++) {
                ldsm_x4(ah[mi], aHiB2 + (uint32_t)(mi * 16 * GSTRIDE * 2) + kb);
                ldsm_x4(al[mi], aLoB2 + (uint32_t)(mi * 16 * GSTRIDE * 2) + kb);
            }
            #pragma unroll
            for (int p = 0; p < 2; p++) {
                ldsm_x4(bh[p], bHiB2 + (uint32_t)(p * 16 * GSTRIDE * 2) + kb);
                ldsm_x4(bl[p], bLoB2 + (uint32_t)(p * 16 * GSTRIDE * 2) + kb);
            }
            #pragma unroll
            for (int mi = 0; mi < 4; mi++) {
                #pragma unroll
                for (int nj = 0; nj < 4; nj++) {
                    const int p = nj >> 1, s = (nj & 1) * 2;
                    mma16816(c[mi][nj], ah[mi], bh[p][s], bh[p][s + 1]);
                    mma16816(c[mi][nj], ah[mi], bl[p][s], bl[p][s + 1]);
                    mma16816(c[mi][nj], al[mi], bh[p][s], bh[p][s + 1]);
                }
            }
        }
        __syncthreads();
    }

    #pragma unroll
    for (int mi = 0; mi < 4; mi++) {
        int r0 = m0 + wm + mi * 16 + (l >> 2);
        #pragma unroll
        for (int nj = 0; nj < 4; nj++) {
            int col = n0 + wn + nj * 8 + (l & 3) * 2;
            float b0 = bias[col], b1 = bias[col + 1];
            #pragma unroll
            for (int half = 0; half < 2; half++) {
                int r = r0 + half * 8;
                float v0 = (c[mi][nj][half * 2 + 0] + b0) * scale;
                float v1 = (c[mi][nj][half * 2 + 1] + b1) * scale;
                size_t g = (size_t)r * HID + col;
                if (z == 2) {
                    __half h0 = __float2half(v0);
                    __half h1 = __float2half(v1);
                    *(__half2*)(vfHi + g) = __halves2half2(h0, h1);
                    *(__half2*)(vfLo + g) = __halves2half2(
                        __float2half(v0 - __half2float(h0)),
                        __float2half(v1 - __half2float(h1)));
                } else {
                    __nv_bfloat16 h0 = __float2bfloat16(v0);
                    __nv_bfloat16 h1 = __float2bfloat16(v1);
                    __nv_bfloat16* oh = outHiB + (size_t)z * MH;
                    __nv_bfloat16* ol = outLoB + (size_t)z * MH;
                    *(__nv_bfloat162*)(oh + g) = __nv_bfloat162(h0, h1);
                    *(__nv_bfloat162*)(ol + g) = __nv_bfloat162(
                        __float2bfloat16(v0 - __bfloat162float(h0)),
                        __float2bfloat16(v1 - __bfloat162float(h1)));
                }
            }
        }
    }
}

// ================= fp16 single-term GEMM (cp.async pipeline) =================
#define FSTAGE (2 * GBUF)

__global__ __launch_bounds__(256) void gemm_fp16(
    const __half* __restrict__ A, int lda, const __half* __restrict__ B,
    int Kdim, const float* __restrict__ bias, const float* __restrict__ prev,
    float* __restrict__ Cf, __half* __restrict__ Ch, int ldch, int mode)
{
    extern __shared__ __half smh[];
    const int tid = threadIdx.x;
    const int w = tid >> 5, l = tid & 31;
    const int m0 = blockIdx.y * 128;
    const int n0 = blockIdx.x * 128;
    const int wm = (w >> 2) * 64;
    const int wn = (w & 3) * 32;

    float c[4][4][4];
    #pragma unroll
    for (int i = 0; i < 4; i++)
        #pragma unroll
        for (int j = 0; j < 4; j++)
            #pragma unroll
            for (int q = 0; q < 4; q++) c[i][j][q] = 0.f;

    const uint32_t sbase = smem_u32(smh);
    const int aRow = wm + (l & 15), aKof = (l >> 4) * 8;
    const int bRow = wn + (l >> 4) * 8 + (l & 7), bKof = ((l >> 3) & 1) * 8;
    const int nChunks = Kdim >> 6;

    auto issue = [&](int ch) {
        const uint32_t dstBase = sbase + (uint32_t)((ch & 1) * FSTAGE * 2);
        const int k0 = ch << 6;
        #pragma unroll
        for (int i = 0; i < 4; i++) {
            int t = tid + i * 256;
            int row = t >> 3, c8 = (t & 7) * 8;
            uint32_t d = dstBase + (uint32_t)((row * GSTRIDE + c8) * 2);
            cp16(d,            A + (size_t)(m0 + row) * lda  + k0 + c8);
            cp16(d + GBUF * 2, B + (size_t)(n0 + row) * Kdim + k0 + c8);
        }
    };

    issue(0); CP_COMMIT();
    for (int ch = 0; ch < nChunks; ch++) {
        if (ch + 1 < nChunks) { issue(ch + 1); CP_COMMIT(); CP_WAIT1(); }
        else                  { CP_WAIT0(); }
        __syncthreads();

        const uint32_t sb = sbase + (uint32_t)((ch & 1) * FSTAGE * 2);
        const uint32_t aB = sb + (uint32_t)((aRow * GSTRIDE + aKof) * 2);
        const uint32_t bB = sb + GBUF * 2 + (uint32_t)((bRow * GSTRIDE + bKof) * 2);

        #pragma unroll
        for (int ks = 0; ks < 4; ks++) {
            const uint32_t kb = (uint32_t)(ks * 16 * 2);
            uint32_t ah[4][4], bh[2][4];
            #pragma unroll
            for (int mi = 0; mi < 4; mi++)
                ldsm_x4(ah[mi], aB + (uint32_t)(mi * 16 * GSTRIDE * 2) + kb);
            #pragma unroll
            for (int p = 0; p < 2; p++)
                ldsm_x4(bh[p], bB + (uint32_t)(p * 16 * GSTRIDE * 2) + kb);
            #pragma unroll
            for (int mi = 0; mi < 4; mi++) {
                #pragma unroll
                for (int nj = 0; nj < 4; nj++) {
                    const int p = nj >> 1, s = (nj & 1) * 2;
                    mma16816h(c[mi][nj], ah[mi], bh[p][s], bh[p][s + 1]);
                }
            }
        }
        __syncthreads();
    }

    #pragma unroll
    for (int mi = 0; mi < 4; mi++) {
        int r0 = m0 + wm + mi * 16 + (l >> 2);
        #pragma unroll
        for (int nj = 0; nj < 4; nj++) {
            int col = n0 + wn + nj * 8 + (l & 3) * 2;
            float b0 = bias[col], b1 = bias[col + 1];
            #pragma unroll
            for (int half = 0; half < 2; half++) {
                int r = r0 + half * 8;
                float v0 = c[mi][nj][half * 2 + 0] + b0;
                float v1 = c[mi][nj][half * 2 + 1] + b1;
                if (mode == 2) {
                    *(__half2*)(Ch + (size_t)r * ldch + col) =
                        __halves2half2(__float2half(v0), __float2half(v1));
                } else {
                    if (mode == 1) {
                        float g0 = prev[(size_t)r * HID + col];
                        float g1 = prev[(size_t)r * HID + col + 1];
                        v0 *= 1.f / (1.f + __expf(-g0));
                        v1 *= 1.f / (1.f + __expf(-g1));
                    }
                    *(float2*)(Cf + (size_t)r * HID + col) = make_float2(v0, v1);
                }
            }
        }
    }
}

// ================= tensor-core attention v2: 512 threads, fused exp, fp16 e =================
// smem bytes:
//   sQ  hi [0,4608) lo [4608,9216)
//   K/V stages: 2 x 73728 at [9216, 156672)   (each: hi 36864 + lo 36864; 256 keys x 72)
//   sE  [156672, 222720)  : 32 x 1032 fp16 (unnormalized e)
//   sMask [222720, 226816): 1024 int
//   sInv  [226816, 226944): 32 float
//   sPart overlays K region during final reduction
#define EST 1032
#define KVST 72
#define ASTG 73728
#define ATTN_SMEM 226944

__global__ __launch_bounds__(512) void attn_mma(
    const __nv_bfloat16* __restrict__ phi, const __nv_bfloat16* __restrict__ plo,
    const __half* __restrict__ vfhi, const __half* __restrict__ vflo,
    const int* __restrict__ mask, float* __restrict__ attn_out,
    __half* __restrict__ xf)
{
    extern __shared__ char sab[];
    __nv_bfloat16* sQ = (__nv_bfloat16*)(sab);
    __half* sE    = (__half*)(sab + 156672);
    int*   sMask = (int*)(sab + 222720);
    float* sInv  = (float*)(sab + 226816);
    float* sPart = (float*)(sab + 9216);

    const int tid = threadIdx.x, w = tid >> 5, l = tid & 31;
    const int q0 = blockIdx.x * 32, h = blockIdx.y, b = blockIdx.z;

    const __nv_bfloat16* qhi = phi;
    const __nv_bfloat16* qlo = plo;
    const __nv_bfloat16* khi = phi + MH;
    const __nv_bfloat16* klo = plo + MH;

    const uint32_t uQh = smem_u32(sab);
    const uint32_t uQl = uQh + 4608;
    const uint32_t uK0 = uQh + 9216;
    const uint32_t uE  = uQh + 156672;

    // load Q tile hi/lo
    {
        int t = tid & 255, part = tid >> 8;
        int r = t >> 3, c8 = (t & 7) * 8;
        const __nv_bfloat16* src = part ? qlo : qhi;
        size_t g = ((size_t)(b * SS + q0 + r)) * HID + h * HD + c8;
        *(uint4*)(sQ + part * 2304 + r * KVST + c8) = *(const uint4*)(src + g);
    }
    for (int k = tid; k < SS; k += 512) sMask[k] = mask[b * SS + k];

    const uint32_t aLaneOff = (uint32_t)(((l & 15) * KVST + (l >> 4) * 8) * 2);
    const int bRowL = (l >> 4) * 8 + (l & 7);
    const int bKofL = ((l >> 3) & 1) * 8;

    // issue one 256-key chunk (hi+lo) into stage st (raw byte copy; works for bf16 or fp16 src)
    auto issueKV = [&](const void* srcHi, const void* srcLo, int chunk, int st) {
        const uint32_t dst = uK0 + (uint32_t)(st * ASTG);
        const int r0 = chunk * 256;
        #pragma unroll
        for (int i = 0; i < 4; i++) {
            int t = tid + i * 512;
            int row = t >> 3, c8 = (t & 7) * 8;
            uint32_t d = dst + (uint32_t)((row * KVST + c8) * 2);
            size_t g = ((size_t)(b * SS + r0 + row)) * HID + h * HD + c8;
            cp16(d,         (const __half*)srcHi + g);
            cp16(d + 36864, (const __half*)srcLo + g);
        }
    };

    // ---------- Phase A: e = mask * exp(Q K^T) -> sE (fp16) ----------
    issueKV(khi, klo, 0, 0); CP_COMMIT();
    for (int ch = 0; ch < 4; ch++) {
        if (ch < 3) issueKV(khi, klo, ch + 1, (ch + 1) & 1);
        else        issueKV(vfhi, vflo, 0, 0);     // prefetch V chunk 0
        CP_COMMIT(); CP_WAIT1();
        __syncthreads();

        const uint32_t sb = uK0 + (uint32_t)((ch & 1) * ASTG);
        const int kc0 = ch * 256;

        float c[2][2][4];
        #pragma unroll
        for (int m = 0; m < 2; m++)
            #pragma unroll
            for (int nj = 0; nj < 2; nj++)
                #pragma unroll
                for (int q = 0; q < 4; q++) c[m][nj][q] = 0.f;

        #pragma unroll
        for (int ks = 0; ks < 4; ks++) {
            uint32_t ah[2][4], al[2][4], bh[4], bl[4];
            #pragma unroll
            for (int m = 0; m < 2; m++) {
                uint32_t off = (uint32_t)((m * 16 * KVST + ks * 16) * 2) + aLaneOff;
                ldsm_x4(ah[m], uQh + off);
                ldsm_x4(al[m], uQl + off);
            }
            {
                uint32_t off = (uint32_t)(((w * 16 + bRowL) * KVST + ks * 16 + bKofL) * 2);
                ldsm_x4(bh, sb + off);
                ldsm_x4(bl, sb + 36864 + off);
            }
            #pragma unroll
            for (int m = 0; m < 2; m++) {
                #pragma unroll
                for (int nj = 0; nj < 2; nj++) {
                    const int s = nj * 2;
                    mma16816(c[m][nj], ah[m], bh[s], bh[s + 1]);
                    mma16816(c[m][nj], ah[m], bl[s], bl[s + 1]);
                    mma16816(c[m][nj], al[m], bh[s], bh[s + 1]);
                }
            }
        }
        // epilogue: mask + exp (clamped for fp16 range safety) + fp16 store
        #pragma unroll
        for (int m = 0; m < 2; m++) {
            #pragma unroll
            for (int nj = 0; nj < 2; nj++) {
                int kcol = kc0 + w * 16 + nj * 8 + (l & 3) * 2;
                int mk0 = sMask[kcol], mk1 = sMask[kcol + 1];
                #pragma unroll
                for (int hf = 0; hf < 2; hf++) {
                    int row = m * 16 + (l >> 2) + hf * 8;
                    float e0 = mk0 ? __expf(fminf(c[m][nj][hf * 2 + 0], 11.f)) : 0.f;
                    float e1 = mk1 ? __expf(fminf(c[m][nj][hf * 2 + 1], 11.f)) : 0.f;
                    *(__half2*)(sE + row * EST + kcol) =
                        __halves2half2(__float2half(e0), __float2half(e1));
                }
            }
        }
        __syncthreads();
    }

    // ---------- Phase B: row sums + prob write (single smem pass; V0 landing meanwhile) ----------
    #pragma unroll
    for (int r = w * 2; r < w * 2 + 2; r++) {
        const __half* eh = sE + r * EST;
        uint32_t buf[16];
        float sum = 0.f;
        #pragma unroll
        for (int i = 0; i < 16; i++) {
            buf[i] = *(const uint32_t*)(eh + i * 64 + l * 2);
            __half2 v = *(__half2*)&buf[i];
            sum += __half2float(v.x) + __half2float(v.y);
        }
        #pragma unroll
        for (int o = 16; o > 0; o >>= 1) sum += __shfl_xor_sync(0xffffffffu, sum, o);
        float inv = 1.f / sum;
        if (l == 0) sInv[r] = inv;
        float* orow = attn_out + ((size_t)((b * NH + h) * SS + q0 + r)) * SS;
        #pragma unroll
        for (int i = 0; i < 16; i++) {
            __half2 v = *(__half2*)&buf[i];
            *(float2*)(orow + i * 64 + l * 2) =
                make_float2(__half2float(v.x) * inv, __half2float(v.y) * inv);
        }
    }

    // ---------- Phase C: x = (e @ V) * inv ; warp w -> d-group (w&3), k-quarter (w>>2) ----------
    const int dg = (w & 3) * 16;
    const int kq = w >> 2;
    float cc[2][2][4];
    #pragma unroll
    for (int m = 0; m < 2; m++)
        #pragma unroll
        for (int nt = 0; nt < 2; nt++)
            #pragma unroll
            for (int q = 0; q < 4; q++) cc[m][nt][q] = 0.f;

    for (int ch = 0; ch < 4; ch++) {
        if (ch < 3) { issueKV(vfhi, vflo, ch + 1, (ch + 1) & 1); CP_COMMIT(); CP_WAIT1(); }
        else        { CP_WAIT0(); }
        __syncthreads();

        const uint32_t sb = uK0 + (uint32_t)((ch & 1) * ASTG);
        const int kc0 = ch * 256 + kq * 64;
        #pragma unroll
        for (int ks = 0; ks < 4; ks++) {
            uint32_t ah2[2][4], bh2[4], bl2[4];
            uint32_t ecol = (uint32_t)((kc0 + ks * 16 + (l >> 4) * 8) * 2);
            #pragma unroll
            for (int m = 0; m < 2; m++)
                ldsm_x4(ah2[m], uE + (uint32_t)(((m * 16 + (l & 15)) * EST) * 2) + ecol);
            uint32_t voff = (uint32_t)(((kq * 64 + ks * 16 + (l & 15)) * KVST + dg + (l >> 4) * 8) * 2);
            ldsm_x4_t(bh2, sb + voff);
            ldsm_x4_t(bl2, sb + 36864 + voff);
            #pragma unroll
            for (int m = 0; m < 2; m++) {
                #pragma unroll
                for (int nt = 0; nt < 2; nt++) {
                    mma16816h(cc[m][nt], ah2[m], bh2[nt * 2], bh2[nt * 2 + 1]);
                    mma16816h(cc[m][nt], ah2[m], bl2[nt * 2], bl2[nt * 2 + 1]);
                }
            }
        }
        __syncthreads();
    }

    // 4-way k-quarter reduction through smem (overlays K/V stages)
    if (kq > 0) {
        float* dst = sPart + (kq - 1) * 2048;
        #pragma unroll
        for (int m = 0; m < 2; m++)
            #pragma unroll
            for (int nt = 0; nt < 2; nt++)
                #pragma unroll
                for (int v = 0; v < 4; v++) {
                    int row = m * 16 + (l >> 2) + ((v >> 1) & 1) * 8;
                    int col = dg + nt * 8 + (l & 3) * 2 + (v & 1);
                    dst[row * 64 + col] = cc[m][nt][v];
                }
    }
    __syncthreads();
    if (kq == 0) {
        #pragma unroll
        for (int m = 0; m < 2; m++) {
            #pragma unroll
            for (int nt = 0; nt < 2; nt++) {
                #pragma unroll
                for (int hf = 0; hf < 2; hf++) {
                    int row = m * 16 + (l >> 2) + hf * 8;
                    int col = dg + nt * 8 + (l & 3) * 2;
                    float inv = sInv[row];
                    float x0 = cc[m][nt][hf * 2 + 0];
                    float x1 = cc[m][nt][hf * 2 + 1];
                    #pragma unroll
                    for (int p = 0; p < 3; p++) {
                        x0 += sPart[p * 2048 + row * 64 + col];
                        x1 += sPart[p * 2048 + row * 64 + col + 1];
                    }
                    x0 *= inv; x1 *= inv;
                    size_t g = ((size_t)(b * SS + q0 + row)) * HID + h * HD + col;
                    *(__half2*)(xf + g) = __halves2half2(__float2half(x0), __float2half(x1));
                }
            }
        }
    }
}

// ================= launch =================
extern "C" void kernel_launch(void* const* d_in, const int* in_sizes, int n_in,
                              void* d_out, int out_size)
{
    const float* query = (const float*)d_in[0];
    const float* key_t = (const float*)d_in[1];
    const float* value = (const float*)d_in[2];
    const int*   mask  = (const int*)d_in[3];
    const float* Wq = (const float*)d_in[4];  const float* bq = (const float*)d_in[5];
    const float* Wk = (const float*)d_in[6];  const float* bk = (const float*)d_in[7];
    const float* Wv = (const float*)d_in[8];  const float* bv = (const float*)d_in[9];
    const float* Wo = (const float*)d_in[10]; const float* bo = (const float*)d_in[11];
    const float* W1 = (const float*)d_in[12]; const float* b1 = (const float*)d_in[13];
    const float* W2 = (const float*)d_in[14]; const float* b2 = (const float*)d_in[15];

    float* out       = (float*)d_out;
    float* out_gated = out;
    float* out_attn  = out + MH;

    float *F1;
    __nv_bfloat16 *shi, *slo, *w3hi, *w3lo, *phi, *plo;
    __half *vfhi, *vflo, *xf, *cat, *wfo, *wf;
    cudaGetSymbolAddress((void**)&F1, g_f1);
    cudaGetSymbolAddress((void**)&shi, g_shi);
    cudaGetSymbolAddress((void**)&slo, g_slo);
    cudaGetSymbolAddress((void**)&w3hi, g_w3hi);
    cudaGetSymbolAddress((void**)&w3lo, g_w3lo);
    cudaGetSymbolAddress((void**)&phi, g_phi);
    cudaGetSymbolAddress((void**)&plo, g_plo);
    cudaGetSymbolAddress((void**)&vfhi, g_vfhi);
    cudaGetSymbolAddress((void**)&vflo, g_vflo);
    cudaGetSymbolAddress((void**)&xf, g_xf);
    cudaGetSymbolAddress((void**)&cat, g_cat);
    cudaGetSymbolAddress((void**)&wfo, g_wfo);
    cudaGetSymbolAddress((void**)&wf, g_wf);

    size_t gsmem = (size_t)2 * GSTAGE * 2;   // 147456 B
    size_t fsmem = (size_t)2 * FSTAGE * 2;   // 73728 B
    cudaFuncSetAttribute(gemm_bf16, cudaFuncAttributeMaxDynamicSharedMemorySize, (int)gsmem);
    cudaFuncSetAttribute(gemm_fp16, cudaFuncAttributeMaxDynamicSharedMemorySize, (int)fsmem);
    cudaFuncSetAttribute(attn_mma, cudaFuncAttributeMaxDynamicSharedMemorySize, ATTN_SMEM);

    const int actBlocks = (MROWS * HID / 4 + 255) / 256;
    dim3 wblk(32, 8);

    // --- QKV: batched splits + batched GEMM (Q,K -> bf16 hi/lo ; V -> fp16 hi/lo) ---
    split_w3<<<dim3(HID / 32, HID / 32, 3), wblk>>>(Wq, Wk, Wv, w3hi, w3lo);
    split_qkv<<<dim3(actBlocks, 3), 256>>>(query, key_t, value, shi, slo);
    gemm_bf16<<<dim3(HID / 128, MROWS / 128, 3), 256, gsmem>>>(
        shi, slo, w3hi, w3lo, bq, bk, bv, phi, plo, vfhi, vflo);

    // --- attention (512 threads, fused exp, fp16 e) ---
    attn_mma<<<dim3(SS / 32, NH, BB), 512, ATTN_SMEM>>>(
        phi, plo, vfhi, vflo, mask, out_attn, xf);

    // --- Wo (fp16) -> cat[:, 0:768] ; query -> cat[:, 768:1536] ---
    split_w_fp16<<<dim3(HID / 32, HID / 32), wblk>>>(Wo, HID, HID, wfo);
    conv_fp16<<<actBlocks, 256>>>(query, cat);
    gemm_fp16<<<dim3(HID / 128, MROWS / 128), 256, fsmem>>>(
        xf, HID, wfo, HID, bo, nullptr, nullptr, cat, 2 * HID, 2);

    // --- FFN (fp16, K=1536) ---
    split_wf2<<<dim3(HID / 32, 2 * HID / 32, 2), wblk>>>(W1, W2, wf);
    gemm_fp16<<<dim3(HID / 128, MROWS / 128), 256, fsmem>>>(
        cat, 2 * HID, wf, 2 * HID, b1, nullptr, F1, nullptr, 0, 0);
    gemm_fp16<<<dim3(HID / 128, MROWS / 128), 256, fsmem>>>(
        cat, 2 * HID, wf + (size_t)2 * HID * HID, 2 * HID, b2, F1, out_gated, nullptr, 0, 1);
}

// round 10
// speedup vs baseline: 6.3373x; 1.2298x over previous
#include <cuda_runtime.h>
#include <cuda_bf16.h>
#include <cuda_fp16.h>
#include <math.h>
#include <stdint.h>

#define BB 8
#define SS 1024
#define HID 768
#define NH 12
#define HD 64
#define MROWS (BB*SS)   // 8192
#define MH ((size_t)MROWS*HID)

// ---------------- scratch (device globals; no allocation allowed) ----------------
__device__ __align__(256) float g_f1 [(size_t)MROWS*HID];

__device__ __align__(256) __nv_bfloat16 g_shi[MH];              // value split hi
__device__ __align__(256) __nv_bfloat16 g_slo[MH];
__device__ __align__(256) __nv_bfloat16 g_w3hi[(size_t)HID*HID];// Wv split
__device__ __align__(256) __nv_bfloat16 g_w3lo[(size_t)HID*HID];

__device__ __align__(256) __half g_vfhi[MH];                    // projected V (fp16 hi/lo)
__device__ __align__(256) __half g_vflo[MH];
__device__ __align__(256) __half g_qf [MH];                     // projected Q (fp16, prescaled)
__device__ __align__(256) __half g_kpf[MH];                     // projected K (fp16)
__device__ __align__(256) __half g_kf [MH];                     // raw key fp16

__device__ __align__(256) __half g_xf [MH];
__device__ __align__(256) __half g_cat[2*MH];
__device__ __align__(256) __half g_wqk[(size_t)2*HID*HID];      // Wq,Wk fp16 [N][K]
__device__ __align__(256) __half g_wfo[(size_t)HID*HID];
__device__ __align__(256) __half g_wf [(size_t)2*2*HID*HID];

// ================= helpers =================
__device__ __forceinline__ uint32_t smem_u32(const void* p) {
    uint32_t a;
    asm("{ .reg .u64 t; cvta.to.shared.u64 t, %1; cvt.u32.u64 %0, t; }" : "=r"(a) : "l"(p));
    return a;
}
__device__ __forceinline__ void ldsm_x4(uint32_t* r, uint32_t addr) {
    asm volatile("ldmatrix.sync.aligned.m8n8.x4.shared.b16 {%0,%1,%2,%3}, [%4];"
                 : "=r"(r[0]), "=r"(r[1]), "=r"(r[2]), "=r"(r[3]) : "r"(addr));
}
__device__ __forceinline__ void ldsm_x4_t(uint32_t* r, uint32_t addr) {
    asm volatile("ldmatrix.sync.aligned.m8n8.x4.trans.shared.b16 {%0,%1,%2,%3}, [%4];"
                 : "=r"(r[0]), "=r"(r[1]), "=r"(r[2]), "=r"(r[3]) : "r"(addr));
}
__device__ __forceinline__ void mma16816(float* c, const uint32_t* a, uint32_t b0, uint32_t b1) {
    asm volatile("mma.sync.aligned.m16n8k16.row.col.f32.bf16.bf16.f32 "
                 "{%0,%1,%2,%3}, {%4,%5,%6,%7}, {%8,%9}, {%0,%1,%2,%3};"
                 : "+f"(c[0]), "+f"(c[1]), "+f"(c[2]), "+f"(c[3])
                 : "r"(a[0]), "r"(a[1]), "r"(a[2]), "r"(a[3]), "r"(b0), "r"(b1));
}
__device__ __forceinline__ void mma16816h(float* c, const uint32_t* a, uint32_t b0, uint32_t b1) {
    asm volatile("mma.sync.aligned.m16n8k16.row.col.f32.f16.f16.f32 "
                 "{%0,%1,%2,%3}, {%4,%5,%6,%7}, {%8,%9}, {%0,%1,%2,%3};"
                 : "+f"(c[0]), "+f"(c[1]), "+f"(c[2]), "+f"(c[3])
                 : "r"(a[0]), "r"(a[1]), "r"(a[2]), "r"(a[3]), "r"(b0), "r"(b1));
}
__device__ __forceinline__ void cp16(uint32_t dst, const void* src) {
    asm volatile("cp.async.cg.shared.global [%0], [%1], 16;" :: "r"(dst), "l"(src));
}
#define CP_COMMIT() asm volatile("cp.async.commit_group;" ::: "memory")
#define CP_WAIT1()  asm volatile("cp.async.wait_group 1;" ::: "memory")
#define CP_WAIT0()  asm volatile("cp.async.wait_group 0;" ::: "memory")

// ================= split / convert kernels =================
// value -> bf16 hi/lo
__global__ void split_v(const float* __restrict__ src,
                        __nv_bfloat16* __restrict__ hi, __nv_bfloat16* __restrict__ lo)
{
    size_t total = MH / 4;
    for (size_t i = (size_t)blockIdx.x * blockDim.x + threadIdx.x; i < total;
         i += (size_t)gridDim.x * blockDim.x) {
        size_t e = i * 4;
        float4 v = *(const float4*)(src + e);
        __nv_bfloat16 h0 = __float2bfloat16(v.x), h1 = __float2bfloat16(v.y);
        __nv_bfloat16 h2 = __float2bfloat16(v.z), h3 = __float2bfloat16(v.w);
        *(__nv_bfloat162*)(hi + e)     = __nv_bfloat162(h0, h1);
        *(__nv_bfloat162*)(hi + e + 2) = __nv_bfloat162(h2, h3);
        *(__nv_bfloat162*)(lo + e)     = __nv_bfloat162(__float2bfloat16(v.x - __bfloat162float(h0)),
                                                        __float2bfloat16(v.y - __bfloat162float(h1)));
        *(__nv_bfloat162*)(lo + e + 2) = __nv_bfloat162(__float2bfloat16(v.z - __bfloat162float(h2)),
                                                        __float2bfloat16(v.w - __bfloat162float(h3)));
    }
}

// Wv -> bf16 hi/lo [N][K]
__global__ void split_wv(const float* __restrict__ W,
                         __nv_bfloat16* __restrict__ hi, __nv_bfloat16* __restrict__ lo)
{
    __shared__ float t[32][33];
    int n0 = blockIdx.x * 32, k0 = blockIdx.y * 32;
    int tx = threadIdx.x, ty = threadIdx.y;
    for (int j = ty; j < 32; j += 8)
        t[j][tx] = W[(size_t)(k0 + j) * HID + n0 + tx];
    __syncthreads();
    for (int j = ty; j < 32; j += 8) {
        float x = t[tx][j];
        __nv_bfloat16 h = __float2bfloat16(x);
        size_t d = (size_t)(n0 + j) * HID + k0 + tx;
        hi[d] = h; lo[d] = __float2bfloat16(x - __bfloat162float(h));
    }
}

// Wq/Wk -> fp16 [N][K], batched z
__global__ void split_wqk(const float* __restrict__ Wa, const float* __restrict__ Wb,
                          __half* __restrict__ out)
{
    __shared__ float t[32][33];
    const int z = blockIdx.z;
    const float* W = (z == 0) ? Wa : Wb;
    __half* O = out + (size_t)z * HID * HID;
    int n0 = blockIdx.x * 32, k0 = blockIdx.y * 32;
    int tx = threadIdx.x, ty = threadIdx.y;
    for (int j = ty; j < 32; j += 8)
        t[j][tx] = W[(size_t)(k0 + j) * HID + n0 + tx];
    __syncthreads();
    for (int j = ty; j < 32; j += 8)
        O[(size_t)(n0 + j) * HID + k0 + tx] = __float2half(t[tx][j]);
}

__global__ void split_w_fp16(const float* __restrict__ W, int K, int N,
                             __half* __restrict__ out)
{
    __shared__ float t[32][33];
    int n0 = blockIdx.x * 32, k0 = blockIdx.y * 32;
    int tx = threadIdx.x, ty = threadIdx.y;
    for (int j = ty; j < 32; j += 8)
        t[j][tx] = W[(size_t)(k0 + j) * N + n0 + tx];
    __syncthreads();
    for (int j = ty; j < 32; j += 8)
        out[(size_t)(n0 + j) * K + k0 + tx] = __float2half(t[tx][j]);
}

__global__ void split_wf2(const float* __restrict__ Wa, const float* __restrict__ Wb,
                          __half* __restrict__ out)
{
    __shared__ float t[32][33];
    const int z = blockIdx.z;
    const float* W = (z == 0) ? Wa : Wb;
    __half* O = out + (size_t)z * 2 * HID * HID;
    int n0 = blockIdx.x * 32, k0 = blockIdx.y * 32;
    int tx = threadIdx.x, ty = threadIdx.y;
    for (int j = ty; j < 32; j += 8)
        t[j][tx] = W[(size_t)(k0 + j) * HID + n0 + tx];
    __syncthreads();
    for (int j = ty; j < 32; j += 8)
        O[(size_t)(n0 + j) * (2 * HID) + k0 + tx] = __float2half(t[tx][j]);
}

// query -> cat[:,768:1536) fp16 ; key -> kf fp16 (batched z)
__global__ void conv2(const float* __restrict__ q, const float* __restrict__ k,
                      __half* __restrict__ cat, __half* __restrict__ kf)
{
    const int z = blockIdx.y;
    const float* src = z ? k : q;
    size_t total = MH / 4;
    for (size_t i = (size_t)blockIdx.x * blockDim.x + threadIdx.x; i < total;
         i += (size_t)gridDim.x * blockDim.x) {
        size_t e = i * 4;
        int m = (int)(e / HID), c = (int)(e % HID);
        float4 v = *(const float4*)(src + e);
        __half* dst = z ? (kf + (size_t)m * HID + c)
                        : (cat + (size_t)m * (2 * HID) + HID + c);
        *(__half2*)(dst)     = __halves2half2(__float2half(v.x), __float2half(v.y));
        *(__half2*)(dst + 2) = __halves2half2(__float2half(v.z), __float2half(v.w));
    }
}

// ================= bf16x3 GEMM (V projection only), epilogue -> fp16 hi/lo =================
#define GSTRIDE 72
#define GBUF (128 * GSTRIDE)
#define GSTAGE (4 * GBUF)

__global__ __launch_bounds__(256) void gemm_v(
    const __nv_bfloat16* __restrict__ Ahi, const __nv_bfloat16* __restrict__ Alo,
    const __nv_bfloat16* __restrict__ Bhi, const __nv_bfloat16* __restrict__ Blo,
    const float* __restrict__ bias,
    __half* __restrict__ vfHi, __half* __restrict__ vfLo)
{
    extern __shared__ __nv_bfloat16 smg[];
    const int tid = threadIdx.x;
    const int w = tid >> 5, l = tid & 31;
    const int m0 = blockIdx.y * 128;
    const int n0 = blockIdx.x * 128;
    const int wm = (w >> 2) * 64;
    const int wn = (w & 3) * 32;

    float c[4][4][4];
    #pragma unroll
    for (int i = 0; i < 4; i++)
        #pragma unroll
        for (int j = 0; j < 4; j++)
            #pragma unroll
            for (int q = 0; q < 4; q++) c[i][j][q] = 0.f;

    const uint32_t sbase = smem_u32(smg);
    const int aRow = wm + (l & 15), aKof = (l >> 4) * 8;
    const int bRow = wn + (l >> 4) * 8 + (l & 7), bKof = ((l >> 3) & 1) * 8;
    const int nChunks = HID >> 6;

    auto issue = [&](int ch) {
        const uint32_t dstBase = sbase + (uint32_t)((ch & 1) * GSTAGE * 2);
        const int k0 = ch << 6;
        #pragma unroll
        for (int i = 0; i < 4; i++) {
            int t = tid + i * 256;
            int row = t >> 3, c8 = (t & 7) * 8;
            uint32_t d = dstBase + (uint32_t)((row * GSTRIDE + c8) * 2);
            size_t ga = (size_t)(m0 + row) * HID + k0 + c8;
            size_t gb = (size_t)(n0 + row) * HID + k0 + c8;
            cp16(d,                Ahi + ga);
            cp16(d + GBUF * 2,     Alo + ga);
            cp16(d + 2 * GBUF * 2, Bhi + gb);
            cp16(d + 3 * GBUF * 2, Blo + gb);
        }
    };

    issue(0); CP_COMMIT();
    for (int ch = 0; ch < nChunks; ch++) {
        CP_WAIT0();
        __syncthreads();
        if (ch + 1 < nChunks) { issue(ch + 1); CP_COMMIT(); }

        const uint32_t sb = sbase + (uint32_t)((ch & 1) * GSTAGE * 2);
        const uint32_t aHiB2 = sb + (uint32_t)((aRow * GSTRIDE + aKof) * 2);
        const uint32_t aLoB2 = aHiB2 + GBUF * 2;
        const uint32_t bHiB2 = sb + 2 * GBUF * 2 + (uint32_t)((bRow * GSTRIDE + bKof) * 2);
        const uint32_t bLoB2 = bHiB2 + GBUF * 2;

        #pragma unroll
        for (int ks = 0; ks < 4; ks++) {
            const uint32_t kb = (uint32_t)(ks * 16 * 2);
            uint32_t ah[4][4], al[4][4], bh[2][4], bl[2][4];
            #pragma unroll
            for (int mi = 0; mi < 4; mi++) {
                ldsm_x4(ah[mi], aHiB2 + (uint32_t)(mi * 16 * GSTRIDE * 2) + kb);
                ldsm_x4(al[mi], aLoB2 + (uint32_t)(mi * 16 * GSTRIDE * 2) + kb);
            }
            #pragma unroll
            for (int p = 0; p < 2; p++) {
                ldsm_x4(bh[p], bHiB2 + (uint32_t)(p * 16 * GSTRIDE * 2) + kb);
                ldsm_x4(bl[p], bLoB2 + (uint32_t)(p * 16 * GSTRIDE * 2) + kb);
            }
            #pragma unroll
            for (int mi = 0; mi < 4; mi++) {
                #pragma unroll
                for (int nj = 0; nj < 4; nj++) {
                    const int p = nj >> 1, s = (nj & 1) * 2;
                    mma16816(c[mi][nj], ah[mi], bh[p][s], bh[p][s + 1]);
                    mma16816(c[mi][nj], ah[mi], bl[p][s], bl[p][s + 1]);
                    mma16816(c[mi][nj], al[mi], bh[p][s], bh[p][s + 1]);
                }
            }
        }
        __syncthreads();
    }

    #pragma unroll
    for (int mi = 0; mi < 4; mi++) {
        int r0 = m0 + wm + mi * 16 + (l >> 2);
        #pragma unroll
        for (int nj = 0; nj < 4; nj++) {
            int col = n0 + wn + nj * 8 + (l & 3) * 2;
            float b0 = bias[col], b1 = bias[col + 1];
            #pragma unroll
            for (int half = 0; half < 2; half++) {
                int r = r0 + half * 8;
                float v0 = c[mi][nj][half * 2 + 0] + b0;
                float v1 = c[mi][nj][half * 2 + 1] + b1;
                size_t g = (size_t)r * HID + col;
                __half h0 = __float2half(v0);
                __half h1 = __float2half(v1);
                *(__half2*)(vfHi + g) = __halves2half2(h0, h1);
                *(__half2*)(vfLo + g) = __halves2half2(
                    __float2half(v0 - __half2float(h0)),
                    __float2half(v1 - __half2float(h1)));
            }
        }
    }
}

// ================= fp16 single-term Q/K projection GEMM (batched z) =================
#define FSTAGE (2 * GBUF)

__global__ __launch_bounds__(256) void gemm_qk(
    const __half* __restrict__ A0, const __half* __restrict__ A1,
    const __half* __restrict__ Bw,
    const float* __restrict__ bias0, const float* __restrict__ bias1,
    __half* __restrict__ out0, __half* __restrict__ out1)
{
    extern __shared__ __half smh[];
    const int tid = threadIdx.x;
    const int w = tid >> 5, l = tid & 31;
    const int z = blockIdx.z;
    const int m0 = blockIdx.y * 128;
    const int n0 = blockIdx.x * 128;
    const int wm = (w >> 2) * 64;
    const int wn = (w & 3) * 32;

    const __half* A = z ? A1 : A0;
    const int lda = z ? HID : 2 * HID;
    const __half* B = Bw + (size_t)z * HID * HID;
    const float* bias = z ? bias1 : bias0;
    const float scale = z ? 1.f : 0.125f;
    __half* out = z ? out1 : out0;

    float c[4][4][4];
    #pragma unroll
    for (int i = 0; i < 4; i++)
        #pragma unroll
        for (int j = 0; j < 4; j++)
            #pragma unroll
            for (int q = 0; q < 4; q++) c[i][j][q] = 0.f;

    const uint32_t sbase = smem_u32(smh);
    const int aRow = wm + (l & 15), aKof = (l >> 4) * 8;
    const int bRow = wn + (l >> 4) * 8 + (l & 7), bKof = ((l >> 3) & 1) * 8;
    const int nChunks = HID >> 6;

    auto issue = [&](int ch) {
        const uint32_t dstBase = sbase + (uint32_t)((ch & 1) * FSTAGE * 2);
        const int k0 = ch << 6;
        #pragma unroll
        for (int i = 0; i < 4; i++) {
            int t = tid + i * 256;
            int row = t >> 3, c8 = (t & 7) * 8;
            uint32_t d = dstBase + (uint32_t)((row * GSTRIDE + c8) * 2);
            cp16(d,            A + (size_t)(m0 + row) * lda + k0 + c8);
            cp16(d + GBUF * 2, B + (size_t)(n0 + row) * HID + k0 + c8);
        }
    };

    issue(0); CP_COMMIT();
    for (int ch = 0; ch < nChunks; ch++) {
        CP_WAIT0();
        __syncthreads();
        if (ch + 1 < nChunks) { issue(ch + 1); CP_COMMIT(); }

        const uint32_t sb = sbase + (uint32_t)((ch & 1) * FSTAGE * 2);
        const uint32_t aB = sb + (uint32_t)((aRow * GSTRIDE + aKof) * 2);
        const uint32_t bB = sb + GBUF * 2 + (uint32_t)((bRow * GSTRIDE + bKof) * 2);

        #pragma unroll
        for (int ks = 0; ks < 4; ks++) {
            const uint32_t kb = (uint32_t)(ks * 16 * 2);
            uint32_t ah[4][4], bh[2][4];
            #pragma unroll
            for (int mi = 0; mi < 4; mi++)
                ldsm_x4(ah[mi], aB + (uint32_t)(mi * 16 * GSTRIDE * 2) + kb);
            #pragma unroll
            for (int p = 0; p < 2; p++)
                ldsm_x4(bh[p], bB + (uint32_t)(p * 16 * GSTRIDE * 2) + kb);
            #pragma unroll
            for (int mi = 0; mi < 4; mi++) {
                #pragma unroll
                for (int nj = 0; nj < 4; nj++) {
                    const int p = nj >> 1, s = (nj & 1) * 2;
                    mma16816h(c[mi][nj], ah[mi], bh[p][s], bh[p][s + 1]);
                }
            }
        }
        __syncthreads();
    }

    #pragma unroll
    for (int mi = 0; mi < 4; mi++) {
        int r0 = m0 + wm + mi * 16 + (l >> 2);
        #pragma unroll
        for (int nj = 0; nj < 4; nj++) {
            int col = n0 + wn + nj * 8 + (l & 3) * 2;
            float b0 = bias[col], b1 = bias[col + 1];
            #pragma unroll
            for (int half = 0; half < 2; half++) {
                int r = r0 + half * 8;
                float v0 = (c[mi][nj][half * 2 + 0] + b0) * scale;
                float v1 = (c[mi][nj][half * 2 + 1] + b1) * scale;
                *(__half2*)(out + (size_t)r * HID + col) =
                    __halves2half2(__float2half(v0), __float2half(v1));
            }
        }
    }
}

// ================= fp16 single-term GEMM (Wo / FFN) =================
__global__ __launch_bounds__(256) void gemm_fp16(
    const __half* __restrict__ A, int lda, const __half* __restrict__ B,
    int Kdim, const float* __restrict__ bias, const float* __restrict__ prev,
    float* __restrict__ Cf, __half* __restrict__ Ch, int ldch, int mode)
{
    extern __shared__ __half smh[];
    const int tid = threadIdx.x;
    const int w = tid >> 5, l = tid & 31;
    const int m0 = blockIdx.y * 128;
    const int n0 = blockIdx.x * 128;
    const int wm = (w >> 2) * 64;
    const int wn = (w & 3) * 32;

    float c[4][4][4];
    #pragma unroll
    for (int i = 0; i < 4; i++)
        #pragma unroll
        for (int j = 0; j < 4; j++)
            #pragma unroll
            for (int q = 0; q < 4; q++) c[i][j][q] = 0.f;

    const uint32_t sbase = smem_u32(smh);
    const int aRow = wm + (l & 15), aKof = (l >> 4) * 8;
    const int bRow = wn + (l >> 4) * 8 + (l & 7), bKof = ((l >> 3) & 1) * 8;
    const int nChunks = Kdim >> 6;

    auto issue = [&](int ch) {
        const uint32_t dstBase = sbase + (uint32_t)((ch & 1) * FSTAGE * 2);
        const int k0 = ch << 6;
        #pragma unroll
        for (int i = 0; i < 4; i++) {
            int t = tid + i * 256;
            int row = t >> 3, c8 = (t & 7) * 8;
            uint32_t d = dstBase + (uint32_t)((row * GSTRIDE + c8) * 2);
            cp16(d,            A + (size_t)(m0 + row) * lda  + k0 + c8);
            cp16(d + GBUF * 2, B + (size_t)(n0 + row) * Kdim + k0 + c8);
        }
    };

    issue(0); CP_COMMIT();
    for (int ch = 0; ch < nChunks; ch++) {
        CP_WAIT0();
        __syncthreads();
        if (ch + 1 < nChunks) { issue(ch + 1); CP_COMMIT(); }

        const uint32_t sb = sbase + (uint32_t)((ch & 1) * FSTAGE * 2);
        const uint32_t aB = sb + (uint32_t)((aRow * GSTRIDE + aKof) * 2);
        const uint32_t bB = sb + GBUF * 2 + (uint32_t)((bRow * GSTRIDE + bKof) * 2);

        #pragma unroll
        for (int ks = 0; ks < 4; ks++) {
            const uint32_t kb = (uint32_t)(ks * 16 * 2);
            uint32_t ah[4][4], bh[2][4];
            #pragma unroll
            for (int mi = 0; mi < 4; mi++)
                ldsm_x4(ah[mi], aB + (uint32_t)(mi * 16 * GSTRIDE * 2) + kb);
            #pragma unroll
            for (int p = 0; p < 2; p++)
                ldsm_x4(bh[p], bB + (uint32_t)(p * 16 * GSTRIDE * 2) + kb);
            #pragma unroll
            for (int mi = 0; mi < 4; mi++) {
                #pragma unroll
                for (int nj = 0; nj < 4; nj++) {
                    const int p = nj >> 1, s = (nj & 1) * 2;
                    mma16816h(c[mi][nj], ah[mi], bh[p][s], bh[p][s + 1]);
                }
            }
        }
        __syncthreads();
    }

    #pragma unroll
    for (int mi = 0; mi < 4; mi++) {
        int r0 = m0 + wm + mi * 16 + (l >> 2);
        #pragma unroll
        for (int nj = 0; nj < 4; nj++) {
            int col = n0 + wn + nj * 8 + (l & 3) * 2;
            float b0 = bias[col], b1 = bias[col + 1];
            #pragma unroll
            for (int half = 0; half < 2; half++) {
                int r = r0 + half * 8;
                float v0 = c[mi][nj][half * 2 + 0] + b0;
                float v1 = c[mi][nj][half * 2 + 1] + b1;
                if (mode == 2) {
                    *(__half2*)(Ch + (size_t)r * ldch + col) =
                        __halves2half2(__float2half(v0), __float2half(v1));
                } else {
                    if (mode == 1) {
                        float g0 = prev[(size_t)r * HID + col];
                        float g1 = prev[(size_t)r * HID + col + 1];
                        v0 *= 1.f / (1.f + __expf(-g0));
                        v1 *= 1.f / (1.f + __expf(-g1));
                    }
                    *(float2*)(Cf + (size_t)r * HID + col) = make_float2(v0, v1);
                }
            }
        }
    }
}

// ================= attention v3: fp16 Q/K single-term, fp16 e, fp16 hi/lo V =================
// smem bytes:
//   sQ  [0, 4608)                 : 32 x 72 fp16
//   stages 2 x 73728 [4608, 152064): K chunks 512x72 fp16 / V chunks 256x72 fp16 hi+lo
//   sE  [152064, 218112)          : 32 x 1032 fp16
//   sMask [218112, 222208)        : 1024 int
//   sInv  [222208, 222336)        : 32 float
//   sPart overlays stage0
#define EST 1032
#define KVST 72
#define ASTG 73728
#define ATTN_SMEM 222336

__global__ __launch_bounds__(512) void attn_mma(
    const __half* __restrict__ qf, const __half* __restrict__ kpf,
    const __half* __restrict__ vfhi, const __half* __restrict__ vflo,
    const int* __restrict__ mask, float* __restrict__ attn_out,
    __half* __restrict__ xf)
{
    extern __shared__ char sab[];
    __half* sQ = (__half*)(sab);
    __half* sE = (__half*)(sab + 152064);
    int*   sMask = (int*)(sab + 218112);
    float* sInv  = (float*)(sab + 222208);
    float* sPart = (float*)(sab + 4608);

    const int tid = threadIdx.x, w = tid >> 5, l = tid & 31;
    const int q0 = blockIdx.x * 32, h = blockIdx.y, b = blockIdx.z;

    const uint32_t uQ  = smem_u32(sab);
    const uint32_t uK0 = uQ + 4608;
    const uint32_t uE  = uQ + 152064;

    // load Q tile (fp16)
    if (tid < 256) {
        int r = tid >> 3, c8 = (tid & 7) * 8;
        size_t g = ((size_t)(b * SS + q0 + r)) * HID + h * HD + c8;
        *(uint4*)(sQ + r * KVST + c8) = *(const uint4*)(qf + g);
    }
    for (int k = tid; k < SS; k += 512) sMask[k] = mask[b * SS + k];

    const uint32_t aLaneOff = (uint32_t)(((l & 15) * KVST + (l >> 4) * 8) * 2);
    const int bRowL = (l >> 4) * 8 + (l & 7);
    const int bKofL = ((l >> 3) & 1) * 8;

    auto issueK = [&](int chunk, int st) {        // 512 keys, fp16 single
        const uint32_t dst = uK0 + (uint32_t)(st * ASTG);
        const int r0 = chunk * 512;
        #pragma unroll
        for (int i = 0; i < 8; i++) {
            int t = tid + i * 512;
            int row = t >> 3, c8 = (t & 7) * 8;
            uint32_t d = dst + (uint32_t)((row * KVST + c8) * 2);
            size_t g = ((size_t)(b * SS + r0 + row)) * HID + h * HD + c8;
            cp16(d, kpf + g);
        }
    };
    auto issueV = [&](int chunk, int st) {        // 256 keys, fp16 hi+lo
        const uint32_t dst = uK0 + (uint32_t)(st * ASTG);
        const int r0 = chunk * 256;
        #pragma unroll
        for (int i = 0; i < 4; i++) {
            int t = tid + i * 512;
            int row = t >> 3, c8 = (t & 7) * 8;
            uint32_t d = dst + (uint32_t)((row * KVST + c8) * 2);
            size_t g = ((size_t)(b * SS + r0 + row)) * HID + h * HD + c8;
            cp16(d,         vfhi + g);
            cp16(d + 36864, vflo + g);
        }
    };

    // ---------- Phase A: e = mask * exp(Q K^T) -> sE (fp16); 2 chunks x 512 keys ----------
    issueK(0, 0); CP_COMMIT();
    for (int ch = 0; ch < 2; ch++) {
        CP_WAIT0();
        __syncthreads();
        if (ch == 0) issueK(1, 1); else issueV(0, 0);
        CP_COMMIT();

        const uint32_t sb = uK0 + (uint32_t)((ch & 1) * ASTG);
        const int kc0 = ch * 512;

        float c[2][4][4];
        #pragma unroll
        for (int m = 0; m < 2; m++)
            #pragma unroll
            for (int nj = 0; nj < 4; nj++)
                #pragma unroll
                for (int q = 0; q < 4; q++) c[m][nj][q] = 0.f;

        #pragma unroll
        for (int ks = 0; ks < 4; ks++) {
            uint32_t ah[2][4], bh[2][4];
            #pragma unroll
            for (int m = 0; m < 2; m++)
                ldsm_x4(ah[m], uQ + (uint32_t)((m * 16 * KVST + ks * 16) * 2) + aLaneOff);
            #pragma unroll
            for (int p = 0; p < 2; p++)
                ldsm_x4(bh[p], sb + (uint32_t)(((w * 32 + p * 16 + bRowL) * KVST + ks * 16 + bKofL) * 2));
            #pragma unroll
            for (int m = 0; m < 2; m++) {
                #pragma unroll
                for (int nj = 0; nj < 4; nj++) {
                    const int p = nj >> 1, s = (nj & 1) * 2;
                    mma16816h(c[m][nj], ah[m], bh[p][s], bh[p][s + 1]);
                }
            }
        }
        // epilogue: mask + exp + fp16 store
        #pragma unroll
        for (int m = 0; m < 2; m++) {
            #pragma unroll
            for (int nj = 0; nj < 4; nj++) {
                int kcol = kc0 + w * 32 + nj * 8 + (l & 3) * 2;
                int mk0 = sMask[kcol], mk1 = sMask[kcol + 1];
                #pragma unroll
                for (int hf = 0; hf < 2; hf++) {
                    int row = m * 16 + (l >> 2) + hf * 8;
                    float e0 = mk0 ? __expf(fminf(c[m][nj][hf * 2 + 0], 11.f)) : 0.f;
                    float e1 = mk1 ? __expf(fminf(c[m][nj][hf * 2 + 1], 11.f)) : 0.f;
                    *(__half2*)(sE + row * EST + kcol) =
                        __halves2half2(__float2half(e0), __float2half(e1));
                }
            }
        }
    }
    __syncthreads();

    // ---------- Phase B: row sums + prob write (V0 in flight) ----------
    #pragma unroll
    for (int r = w * 2; r < w * 2 + 2; r++) {
        const __half* eh = sE + r * EST;
        uint32_t buf[16];
        float sum = 0.f;
        #pragma unroll
        for (int i = 0; i < 16; i++) {
            buf[i] = *(const uint32_t*)(eh + i * 64 + l * 2);
            __half2 v = *(__half2*)&buf[i];
            sum += __half2float(v.x) + __half2float(v.y);
        }
        #pragma unroll
        for (int o = 16; o > 0; o >>= 1) sum += __shfl_xor_sync(0xffffffffu, sum, o);
        float inv = 1.f / sum;
        if (l == 0) sInv[r] = inv;
        float* orow = attn_out + ((size_t)((b * NH + h) * SS + q0 + r)) * SS;
        #pragma unroll
        for (int i = 0; i < 16; i++) {
            __half2 v = *(__half2*)&buf[i];
            *(float2*)(orow + i * 64 + l * 2) =
                make_float2(__half2float(v.x) * inv, __half2float(v.y) * inv);
        }
    }

    // ---------- Phase C: x = (e @ V) * inv ; 4 chunks x 256 keys ----------
    const int dg = (w & 3) * 16;
    const int kq = w >> 2;
    float cc[2][2][4];
    #pragma unroll
    for (int m = 0; m < 2; m++)
        #pragma unroll
        for (int nt = 0; nt < 2; nt++)
            #pragma unroll
            for (int q = 0; q < 4; q++) cc[m][nt][q] = 0.f;

    for (int ch = 0; ch < 4; ch++) {
        CP_WAIT0();
        __syncthreads();
        if (ch < 3) { issueV(ch + 1, (ch + 1) & 1); CP_COMMIT(); }

        const uint32_t sb = uK0 + (uint32_t)((ch & 1) * ASTG);
        const int kc0 = ch * 256 + kq * 64;
        #pragma unroll
        for (int ks = 0; ks < 4; ks++) {
            uint32_t ah2[2][4], bh2[4], bl2[4];
            uint32_t ecol = (uint32_t)((kc0 + ks * 16 + (l >> 4) * 8) * 2);
            #pragma unroll
            for (int m = 0; m < 2; m++)
                ldsm_x4(ah2[m], uE + (uint32_t)(((m * 16 + (l & 15)) * EST) * 2) + ecol);
            uint32_t voff = (uint32_t)(((kq * 64 + ks * 16 + (l & 15)) * KVST + dg + (l >> 4) * 8) * 2);
            ldsm_x4_t(bh2, sb + voff);
            ldsm_x4_t(bl2, sb + 36864 + voff);
            #pragma unroll
            for (int m = 0; m < 2; m++) {
                #pragma unroll
                for (int nt = 0; nt < 2; nt++) {
                    mma16816h(cc[m][nt], ah2[m], bh2[nt * 2], bh2[nt * 2 + 1]);
                    mma16816h(cc[m][nt], ah2[m], bl2[nt * 2], bl2[nt * 2 + 1]);
                }
            }
        }
    }
    __syncthreads();

    // 4-way k-quarter reduction through smem (overlays stage region)
    if (kq > 0) {
        float* dst = sPart + (kq - 1) * 2048;
        #pragma unroll
        for (int m = 0; m < 2; m++)
            #pragma unroll
            for (int nt = 0; nt < 2; nt++)
                #pragma unroll
                for (int v = 0; v < 4; v++) {
                    int row = m * 16 + (l >> 2) + ((v >> 1) & 1) * 8;
                    int col = dg + nt * 8 + (l & 3) * 2 + (v & 1);
                    dst[row * 64 + col] = cc[m][nt][v];
                }
    }
    __syncthreads();
    if (kq == 0) {
        #pragma unroll
        for (int m = 0; m < 2; m++) {
            #pragma unroll
            for (int nt = 0; nt < 2; nt++) {
                #pragma unroll
                for (int hf = 0; hf < 2; hf++) {
                    int row = m * 16 + (l >> 2) + hf * 8;
                    int col = dg + nt * 8 + (l & 3) * 2;
                    float inv = sInv[row];
                    float x0 = cc[m][nt][hf * 2 + 0];
                    float x1 = cc[m][nt][hf * 2 + 1];
                    #pragma unroll
                    for (int p = 0; p < 3; p++) {
                        x0 += sPart[p * 2048 + row * 64 + col];
                        x1 += sPart[p * 2048 + row * 64 + col + 1];
                    }
                    x0 *= inv; x1 *= inv;
                    size_t g = ((size_t)(b * SS + q0 + row)) * HID + h * HD + col;
                    *(__half2*)(xf + g) = __halves2half2(__float2half(x0), __float2half(x1));
                }
            }
        }
    }
}

// ================= launch =================
extern "C" void kernel_launch(void* const* d_in, const int* in_sizes, int n_in,
                              void* d_out, int out_size)
{
    const float* query = (const float*)d_in[0];
    const float* key_t = (const float*)d_in[1];
    const float* value = (const float*)d_in[2];
    const int*   mask  = (const int*)d_in[3];
    const float* Wq = (const float*)d_in[4];  const float* bq = (const float*)d_in[5];
    const float* Wk = (const float*)d_in[6];  const float* bk = (const float*)d_in[7];
    const float* Wv = (const float*)d_in[8];  const float* bv = (const float*)d_in[9];
    const float* Wo = (const float*)d_in[10]; const float* bo = (const float*)d_in[11];
    const float* W1 = (const float*)d_in[12]; const float* b1 = (const float*)d_in[13];
    const float* W2 = (const float*)d_in[14]; const float* b2 = (const float*)d_in[15];

    float* out       = (float*)d_out;
    float* out_gated = out;
    float* out_attn  = out + MH;

    float *F1;
    __nv_bfloat16 *shi, *slo, *w3hi, *w3lo;
    __half *vfhi, *vflo, *qfp, *kpf, *kf, *xf, *cat, *wqk, *wfo, *wf;
    cudaGetSymbolAddress((void**)&F1, g_f1);
    cudaGetSymbolAddress((void**)&shi, g_shi);
    cudaGetSymbolAddress((void**)&slo, g_slo);
    cudaGetSymbolAddress((void**)&w3hi, g_w3hi);
    cudaGetSymbolAddress((void**)&w3lo, g_w3lo);
    cudaGetSymbolAddress((void**)&vfhi, g_vfhi);
    cudaGetSymbolAddress((void**)&vflo, g_vflo);
    cudaGetSymbolAddress((void**)&qfp, g_qf);
    cudaGetSymbolAddress((void**)&kpf, g_kpf);
    cudaGetSymbolAddress((void**)&kf, g_kf);
    cudaGetSymbolAddress((void**)&xf, g_xf);
    cudaGetSymbolAddress((void**)&cat, g_cat);
    cudaGetSymbolAddress((void**)&wqk, g_wqk);
    cudaGetSymbolAddress((void**)&wfo, g_wfo);
    cudaGetSymbolAddress((void**)&wf, g_wf);

    size_t gsmem = (size_t)2 * GSTAGE * 2;   // 147456 B
    size_t fsmem = (size_t)2 * FSTAGE * 2;   // 73728 B
    cudaFuncSetAttribute(gemm_v, cudaFuncAttributeMaxDynamicSharedMemorySize, (int)gsmem);
    cudaFuncSetAttribute(gemm_qk, cudaFuncAttributeMaxDynamicSharedMemorySize, (int)fsmem);
    cudaFuncSetAttribute(gemm_fp16, cudaFuncAttributeMaxDynamicSharedMemorySize, (int)fsmem);
    cudaFuncSetAttribute(attn_mma, cudaFuncAttributeMaxDynamicSharedMemorySize, ATTN_SMEM);

    const int actBlocks = (MROWS * HID / 4 + 255) / 256;
    dim3 wblk(32, 8);
    dim3 ggrid(HID / 128, MROWS / 128);      // (6, 64)

    // --- input conversions + weight splits ---
    conv2<<<dim3(actBlocks, 2), 256>>>(query, key_t, cat, kf);    // query->cat[,768:], key->kf
    split_wqk<<<dim3(HID / 32, HID / 32, 2), wblk>>>(Wq, Wk, wqk);
    split_v<<<actBlocks, 256>>>(value, shi, slo);
    split_wv<<<dim3(HID / 32, HID / 32), wblk>>>(Wv, w3hi, w3lo);

    // --- Q/K projections (fp16 single-term; Q pre-scaled 1/8) ---
    gemm_qk<<<dim3(HID / 128, MROWS / 128, 2), 256, fsmem>>>(
        cat + HID, kf, wqk, bq, bk, qfp, kpf);

    // --- V projection (bf16x3 -> fp16 hi/lo) ---
    gemm_v<<<ggrid, 256, gsmem>>>(shi, slo, w3hi, w3lo, bv, vfhi, vflo);

    // --- attention ---
    attn_mma<<<dim3(SS / 32, NH, BB), 512, ATTN_SMEM>>>(
        qfp, kpf, vfhi, vflo, mask, out_attn, xf);

    // --- Wo (fp16) -> cat[:, 0:768] ---
    split_w_fp16<<<dim3(HID / 32, HID / 32), wblk>>>(Wo, HID, HID, wfo);
    gemm_fp16<<<ggrid, 256, fsmem>>>(
        xf, HID, wfo, HID, bo, nullptr, nullptr, cat, 2 * HID, 2);

    // --- FFN (fp16, K=1536) ---
    split_wf2<<<dim3(HID / 32, 2 * HID / 32, 2), wblk>>>(W1, W2, wf);
    gemm_fp16<<<ggrid, 256, fsmem>>>(
        cat, 2 * HID, wf, 2 * HID, b1, nullptr, F1, nullptr, 0, 0);
    gemm_fp16<<<ggrid, 256, fsmem>>>(
        cat, 2 * HID, wf + (size_t)2 * HID * HID, 2 * HID, b2, F1, out_gated, nullptr, 0, 1);
}

// round 11
// speedup vs baseline: 7.6645x; 1.2094x over previous
#include <cuda_runtime.h>
#include <cuda_fp16.h>
#include <math.h>
#include <stdint.h>

#define BB 8
#define SS 1024
#define HID 768
#define NH 12
#define HD 64
#define MROWS (BB*SS)   // 8192
#define MH ((size_t)MROWS*HID)

// ---------------- scratch (device globals; no allocation allowed) ----------------
__device__ __align__(256) float g_f1 [(size_t)MROWS*HID];

__device__ __align__(256) __half g_kf [MH];                     // raw key fp16
__device__ __align__(256) __half g_vf [MH];                     // raw value fp16
__device__ __align__(256) __half g_qf [MH];                     // projected Q (fp16, prescaled)
__device__ __align__(256) __half g_kpf[MH];                     // projected K (fp16)
__device__ __align__(256) __half g_vpf[MH];                     // projected V (fp16)

__device__ __align__(256) __half g_xf [MH];
__device__ __align__(256) __half g_cat[2*MH];
__device__ __align__(256) __half g_wqk[(size_t)3*HID*HID];      // Wq,Wk,Wv fp16 [N][K]
__device__ __align__(256) __half g_wfo[(size_t)HID*HID];
__device__ __align__(256) __half g_wf [(size_t)2*2*HID*HID];

// ================= helpers =================
__device__ __forceinline__ uint32_t smem_u32(const void* p) {
    uint32_t a;
    asm("{ .reg .u64 t; cvta.to.shared.u64 t, %1; cvt.u32.u64 %0, t; }" : "=r"(a) : "l"(p));
    return a;
}
__device__ __forceinline__ void ldsm_x4(uint32_t* r, uint32_t addr) {
    asm volatile("ldmatrix.sync.aligned.m8n8.x4.shared.b16 {%0,%1,%2,%3}, [%4];"
                 : "=r"(r[0]), "=r"(r[1]), "=r"(r[2]), "=r"(r[3]) : "r"(addr));
}
__device__ __forceinline__ void ldsm_x4_t(uint32_t* r, uint32_t addr) {
    asm volatile("ldmatrix.sync.aligned.m8n8.x4.trans.shared.b16 {%0,%1,%2,%3}, [%4];"
                 : "=r"(r[0]), "=r"(r[1]), "=r"(r[2]), "=r"(r[3]) : "r"(addr));
}
__device__ __forceinline__ void mma16816h(float* c, const uint32_t* a, uint32_t b0, uint32_t b1) {
    asm volatile("mma.sync.aligned.m16n8k16.row.col.f32.f16.f16.f32 "
                 "{%0,%1,%2,%3}, {%4,%5,%6,%7}, {%8,%9}, {%0,%1,%2,%3};"
                 : "+f"(c[0]), "+f"(c[1]), "+f"(c[2]), "+f"(c[3])
                 : "r"(a[0]), "r"(a[1]), "r"(a[2]), "r"(a[3]), "r"(b0), "r"(b1));
}
__device__ __forceinline__ void cp16(uint32_t dst, const void* src) {
    asm volatile("cp.async.cg.shared.global [%0], [%1], 16;" :: "r"(dst), "l"(src));
}
#define CP_COMMIT() asm volatile("cp.async.commit_group;" ::: "memory")
#define CP_WAIT0()  asm volatile("cp.async.wait_group 0;" ::: "memory")

// ================= convert / weight-split kernels =================
// z=0: query -> cat[:,768:1536) ; z=1: key -> kf ; z=2: value -> vf
__global__ void conv3(const float* __restrict__ q, const float* __restrict__ k,
                      const float* __restrict__ v,
                      __half* __restrict__ cat, __half* __restrict__ kf,
                      __half* __restrict__ vf)
{
    const int z = blockIdx.y;
    const float* src = (z == 0) ? q : (z == 1) ? k : v;
    size_t total = MH / 4;
    for (size_t i = (size_t)blockIdx.x * blockDim.x + threadIdx.x; i < total;
         i += (size_t)gridDim.x * blockDim.x) {
        size_t e = i * 4;
        int m = (int)(e / HID), c = (int)(e % HID);
        float4 x = *(const float4*)(src + e);
        __half* dst = (z == 0) ? (cat + (size_t)m * (2 * HID) + HID + c)
                    : (z == 1) ? (kf + e) : (vf + e);
        *(__half2*)(dst)     = __halves2half2(__float2half(x.x), __float2half(x.y));
        *(__half2*)(dst + 2) = __halves2half2(__float2half(x.z), __float2half(x.w));
    }
}

// Wq/Wk/Wv -> fp16 [N][K], batched z
__global__ void split_wqk3(const float* __restrict__ Wa, const float* __restrict__ Wb,
                           const float* __restrict__ Wc, __half* __restrict__ out)
{
    __shared__ float t[32][33];
    const int z = blockIdx.z;
    const float* W = (z == 0) ? Wa : (z == 1) ? Wb : Wc;
    __half* O = out + (size_t)z * HID * HID;
    int n0 = blockIdx.x * 32, k0 = blockIdx.y * 32;
    int tx = threadIdx.x, ty = threadIdx.y;
    for (int j = ty; j < 32; j += 8)
        t[j][tx] = W[(size_t)(k0 + j) * HID + n0 + tx];
    __syncthreads();
    for (int j = ty; j < 32; j += 8)
        O[(size_t)(n0 + j) * HID + k0 + tx] = __float2half(t[tx][j]);
}

__global__ void split_w_fp16(const float* __restrict__ W, int K, int N,
                             __half* __restrict__ out)
{
    __shared__ float t[32][33];
    int n0 = blockIdx.x * 32, k0 = blockIdx.y * 32;
    int tx = threadIdx.x, ty = threadIdx.y;
    for (int j = ty; j < 32; j += 8)
        t[j][tx] = W[(size_t)(k0 + j) * N + n0 + tx];
    __syncthreads();
    for (int j = ty; j < 32; j += 8)
        out[(size_t)(n0 + j) * K + k0 + tx] = __float2half(t[tx][j]);
}

__global__ void split_wf2(const float* __restrict__ Wa, const float* __restrict__ Wb,
                          __half* __restrict__ out)
{
    __shared__ float t[32][33];
    const int z = blockIdx.z;
    const float* W = (z == 0) ? Wa : Wb;
    __half* O = out + (size_t)z * 2 * HID * HID;
    int n0 = blockIdx.x * 32, k0 = blockIdx.y * 32;
    int tx = threadIdx.x, ty = threadIdx.y;
    for (int j = ty; j < 32; j += 8)
        t[j][tx] = W[(size_t)(k0 + j) * HID + n0 + tx];
    __syncthreads();
    for (int j = ty; j < 32; j += 8)
        O[(size_t)(n0 + j) * (2 * HID) + k0 + tx] = __float2half(t[tx][j]);
}

// ================= fp16 QKV projection GEMM (batched z = 0,1,2) =================
#define GSTRIDE 72
#define GBUF (128 * GSTRIDE)
#define FSTAGE (2 * GBUF)

__global__ __launch_bounds__(256) void gemm_qkv(
    const __half* __restrict__ Aq, const __half* __restrict__ Ak,
    const __half* __restrict__ Av, const __half* __restrict__ Bw,
    const float* __restrict__ bq, const float* __restrict__ bk,
    const float* __restrict__ bv,
    __half* __restrict__ oq, __half* __restrict__ ok, __half* __restrict__ ov)
{
    extern __shared__ __half smh[];
    const int tid = threadIdx.x;
    const int w = tid >> 5, l = tid & 31;
    const int z = blockIdx.z;
    const int m0 = blockIdx.y * 128;
    const int n0 = blockIdx.x * 128;
    const int wm = (w >> 2) * 64;
    const int wn = (w & 3) * 32;

    const __half* A = (z == 0) ? Aq : (z == 1) ? Ak : Av;
    const int lda = (z == 0) ? 2 * HID : HID;
    const __half* B = Bw + (size_t)z * HID * HID;
    const float* bias = (z == 0) ? bq : (z == 1) ? bk : bv;
    const float scale = (z == 0) ? 0.125f : 1.f;
    __half* out = (z == 0) ? oq : (z == 1) ? ok : ov;

    float c[4][4][4];
    #pragma unroll
    for (int i = 0; i < 4; i++)
        #pragma unroll
        for (int j = 0; j < 4; j++)
            #pragma unroll
            for (int q = 0; q < 4; q++) c[i][j][q] = 0.f;

    const uint32_t sbase = smem_u32(smh);
    const int aRow = wm + (l & 15), aKof = (l >> 4) * 8;
    const int bRow = wn + (l >> 4) * 8 + (l & 7), bKof = ((l >> 3) & 1) * 8;
    const int nChunks = HID >> 6;

    auto issue = [&](int ch) {
        const uint32_t dstBase = sbase + (uint32_t)((ch & 1) * FSTAGE * 2);
        const int k0 = ch << 6;
        #pragma unroll
        for (int i = 0; i < 4; i++) {
            int t = tid + i * 256;
            int row = t >> 3, c8 = (t & 7) * 8;
            uint32_t d = dstBase + (uint32_t)((row * GSTRIDE + c8) * 2);
            cp16(d,            A + (size_t)(m0 + row) * lda + k0 + c8);
            cp16(d + GBUF * 2, B + (size_t)(n0 + row) * HID + k0 + c8);
        }
    };

    issue(0); CP_COMMIT();
    for (int ch = 0; ch < nChunks; ch++) {
        CP_WAIT0();
        __syncthreads();
        if (ch + 1 < nChunks) { issue(ch + 1); CP_COMMIT(); }

        const uint32_t sb = sbase + (uint32_t)((ch & 1) * FSTAGE * 2);
        const uint32_t aB = sb + (uint32_t)((aRow * GSTRIDE + aKof) * 2);
        const uint32_t bB = sb + GBUF * 2 + (uint32_t)((bRow * GSTRIDE + bKof) * 2);

        #pragma unroll
        for (int ks = 0; ks < 4; ks++) {
            const uint32_t kb = (uint32_t)(ks * 16 * 2);
            uint32_t ah[4][4], bh[2][4];
            #pragma unroll
            for (int mi = 0; mi < 4; mi++)
                ldsm_x4(ah[mi], aB + (uint32_t)(mi * 16 * GSTRIDE * 2) + kb);
            #pragma unroll
            for (int p = 0; p < 2; p++)
                ldsm_x4(bh[p], bB + (uint32_t)(p * 16 * GSTRIDE * 2) + kb);
            #pragma unroll
            for (int mi = 0; mi < 4; mi++) {
                #pragma unroll
                for (int nj = 0; nj < 4; nj++) {
                    const int p = nj >> 1, s = (nj & 1) * 2;
                    mma16816h(c[mi][nj], ah[mi], bh[p][s], bh[p][s + 1]);
                }
            }
        }
        __syncthreads();
    }

    #pragma unroll
    for (int mi = 0; mi < 4; mi++) {
        int r0 = m0 + wm + mi * 16 + (l >> 2);
        #pragma unroll
        for (int nj = 0; nj < 4; nj++) {
            int col = n0 + wn + nj * 8 + (l & 3) * 2;
            float b0 = bias[col], b1 = bias[col + 1];
            #pragma unroll
            for (int half = 0; half < 2; half++) {
                int r = r0 + half * 8;
                float v0 = (c[mi][nj][half * 2 + 0] + b0) * scale;
                float v1 = (c[mi][nj][half * 2 + 1] + b1) * scale;
                *(__half2*)(out + (size_t)r * HID + col) =
                    __halves2half2(__float2half(v0), __float2half(v1));
            }
        }
    }
}

// ================= fp16 single-term GEMM (Wo / FFN) =================
__global__ __launch_bounds__(256) void gemm_fp16(
    const __half* __restrict__ A, int lda, const __half* __restrict__ B,
    int Kdim, const float* __restrict__ bias, const float* __restrict__ prev,
    float* __restrict__ Cf, __half* __restrict__ Ch, int ldch, int mode)
{
    extern __shared__ __half smh[];
    const int tid = threadIdx.x;
    const int w = tid >> 5, l = tid & 31;
    const int m0 = blockIdx.y * 128;
    const int n0 = blockIdx.x * 128;
    const int wm = (w >> 2) * 64;
    const int wn = (w & 3) * 32;

    float c[4][4][4];
    #pragma unroll
    for (int i = 0; i < 4; i++)
        #pragma unroll
        for (int j = 0; j < 4; j++)
            #pragma unroll
            for (int q = 0; q < 4; q++) c[i][j][q] = 0.f;

    const uint32_t sbase = smem_u32(smh);
    const int aRow = wm + (l & 15), aKof = (l >> 4) * 8;
    const int bRow = wn + (l >> 4) * 8 + (l & 7), bKof = ((l >> 3) & 1) * 8;
    const int nChunks = Kdim >> 6;

    auto issue = [&](int ch) {
        const uint32_t dstBase = sbase + (uint32_t)((ch & 1) * FSTAGE * 2);
        const int k0 = ch << 6;
        #pragma unroll
        for (int i = 0; i < 4; i++) {
            int t = tid + i * 256;
            int row = t >> 3, c8 = (t & 7) * 8;
            uint32_t d = dstBase + (uint32_t)((row * GSTRIDE + c8) * 2);
            cp16(d,            A + (size_t)(m0 + row) * lda  + k0 + c8);
            cp16(d + GBUF * 2, B + (size_t)(n0 + row) * Kdim + k0 + c8);
        }
    };

    issue(0); CP_COMMIT();
    for (int ch = 0; ch < nChunks; ch++) {
        CP_WAIT0();
        __syncthreads();
        if (ch + 1 < nChunks) { issue(ch + 1); CP_COMMIT(); }

        const uint32_t sb = sbase + (uint32_t)((ch & 1) * FSTAGE * 2);
        const uint32_t aB = sb + (uint32_t)((aRow * GSTRIDE + aKof) * 2);
        const uint32_t bB = sb + GBUF * 2 + (uint32_t)((bRow * GSTRIDE + bKof) * 2);

        #pragma unroll
        for (int ks = 0; ks < 4; ks++) {
            const uint32_t kb = (uint32_t)(ks * 16 * 2);
            uint32_t ah[4][4], bh[2][4];
            #pragma unroll
            for (int mi = 0; mi < 4; mi++)
                ldsm_x4(ah[mi], aB + (uint32_t)(mi * 16 * GSTRIDE * 2) + kb);
            #pragma unroll
            for (int p = 0; p < 2; p++)
                ldsm_x4(bh[p], bB + (uint32_t)(p * 16 * GSTRIDE * 2) + kb);
            #pragma unroll
            for (int mi = 0; mi < 4; mi++) {
                #pragma unroll
                for (int nj = 0; nj < 4; nj++) {
                    const int p = nj >> 1, s = (nj & 1) * 2;
                    mma16816h(c[mi][nj], ah[mi], bh[p][s], bh[p][s + 1]);
                }
            }
        }
        __syncthreads();
    }

    #pragma unroll
    for (int mi = 0; mi < 4; mi++) {
        int r0 = m0 + wm + mi * 16 + (l >> 2);
        #pragma unroll
        for (int nj = 0; nj < 4; nj++) {
            int col = n0 + wn + nj * 8 + (l & 3) * 2;
            float b0 = bias[col], b1 = bias[col + 1];
            #pragma unroll
            for (int half = 0; half < 2; half++) {
                int r = r0 + half * 8;
                float v0 = c[mi][nj][half * 2 + 0] + b0;
                float v1 = c[mi][nj][half * 2 + 1] + b1;
                if (mode == 2) {
                    *(__half2*)(Ch + (size_t)r * ldch + col) =
                        __halves2half2(__float2half(v0), __float2half(v1));
                } else {
                    if (mode == 1) {
                        float g0 = prev[(size_t)r * HID + col];
                        float g1 = prev[(size_t)r * HID + col + 1];
                        v0 *= 1.f / (1.f + __expf(-g0));
                        v1 *= 1.f / (1.f + __expf(-g1));
                    }
                    *(float2*)(Cf + (size_t)r * HID + col) = make_float2(v0, v1);
                }
            }
        }
    }
}

// ================= attention v4: all-fp16 single-term =================
// smem bytes:
//   sQ  [0, 4608)                 : 32 x 72 fp16
//   stages 2 x 73728 [4608, 152064): 512 keys x 72 fp16 (K or V)
//   sE  [152064, 218112)          : 32 x 1032 fp16
//   sMask [218112, 222208)        : 1024 int
//   sInv  [222208, 222336)        : 32 float
//   sPart overlays stage0
#define EST 1032
#define KVST 72
#define ASTG 73728
#define ATTN_SMEM 222336

__global__ __launch_bounds__(512) void attn_mma(
    const __half* __restrict__ qf, const __half* __restrict__ kpf,
    const __half* __restrict__ vpf,
    const int* __restrict__ mask, float* __restrict__ attn_out,
    __half* __restrict__ xf)
{
    extern __shared__ char sab[];
    __half* sQ = (__half*)(sab);
    __half* sE = (__half*)(sab + 152064);
    int*   sMask = (int*)(sab + 218112);
    float* sInv  = (float*)(sab + 222208);
    float* sPart = (float*)(sab + 4608);

    const int tid = threadIdx.x, w = tid >> 5, l = tid & 31;
    const int q0 = blockIdx.x * 32, h = blockIdx.y, b = blockIdx.z;

    const uint32_t uQ  = smem_u32(sab);
    const uint32_t uK0 = uQ + 4608;
    const uint32_t uE  = uQ + 152064;

    // load Q tile (fp16)
    if (tid < 256) {
        int r = tid >> 3, c8 = (tid & 7) * 8;
        size_t g = ((size_t)(b * SS + q0 + r)) * HID + h * HD + c8;
        *(uint4*)(sQ + r * KVST + c8) = *(const uint4*)(qf + g);
    }
    for (int k = tid; k < SS; k += 512) sMask[k] = mask[b * SS + k];

    const uint32_t aLaneOff = (uint32_t)(((l & 15) * KVST + (l >> 4) * 8) * 2);
    const int bRowL = (l >> 4) * 8 + (l & 7);
    const int bKofL = ((l >> 3) & 1) * 8;

    // issue one 512-key fp16 chunk into stage st
    auto issueX = [&](const __half* src, int chunk, int st) {
        const uint32_t dst = uK0 + (uint32_t)(st * ASTG);
        const int r0 = chunk * 512;
        #pragma unroll
        for (int i = 0; i < 8; i++) {
            int t = tid + i * 512;
            int row = t >> 3, c8 = (t & 7) * 8;
            uint32_t d = dst + (uint32_t)((row * KVST + c8) * 2);
            size_t g = ((size_t)(b * SS + r0 + row)) * HID + h * HD + c8;
            cp16(d, src + g);
        }
    };

    // ---------- Phase A: e = mask * exp(Q K^T) -> sE (fp16); 2 chunks x 512 keys ----------
    issueX(kpf, 0, 0); CP_COMMIT();
    for (int ch = 0; ch < 2; ch++) {
        CP_WAIT0();
        __syncthreads();
        if (ch == 0) issueX(kpf, 1, 1); else issueX(vpf, 0, 0);
        CP_COMMIT();

        const uint32_t sb = uK0 + (uint32_t)((ch & 1) * ASTG);
        const int kc0 = ch * 512;

        float c[2][4][4];
        #pragma unroll
        for (int m = 0; m < 2; m++)
            #pragma unroll
            for (int nj = 0; nj < 4; nj++)
                #pragma unroll
                for (int q = 0; q < 4; q++) c[m][nj][q] = 0.f;

        #pragma unroll
        for (int ks = 0; ks < 4; ks++) {
            uint32_t ah[2][4], bh[2][4];
            #pragma unroll
            for (int m = 0; m < 2; m++)
                ldsm_x4(ah[m], uQ + (uint32_t)((m * 16 * KVST + ks * 16) * 2) + aLaneOff);
            #pragma unroll
            for (int p = 0; p < 2; p++)
                ldsm_x4(bh[p], sb + (uint32_t)(((w * 32 + p * 16 + bRowL) * KVST + ks * 16 + bKofL) * 2));
            #pragma unroll
            for (int m = 0; m < 2; m++) {
                #pragma unroll
                for (int nj = 0; nj < 4; nj++) {
                    const int p = nj >> 1, s = (nj & 1) * 2;
                    mma16816h(c[m][nj], ah[m], bh[p][s], bh[p][s + 1]);
                }
            }
        }
        // epilogue: mask + exp + fp16 store
        #pragma unroll
        for (int m = 0; m < 2; m++) {
            #pragma unroll
            for (int nj = 0; nj < 4; nj++) {
                int kcol = kc0 + w * 32 + nj * 8 + (l & 3) * 2;
                int mk0 = sMask[kcol], mk1 = sMask[kcol + 1];
                #pragma unroll
                for (int hf = 0; hf < 2; hf++) {
                    int row = m * 16 + (l >> 2) + hf * 8;
                    float e0 = mk0 ? __expf(fminf(c[m][nj][hf * 2 + 0], 11.f)) : 0.f;
                    float e1 = mk1 ? __expf(fminf(c[m][nj][hf * 2 + 1], 11.f)) : 0.f;
                    *(__half2*)(sE + row * EST + kcol) =
                        __halves2half2(__float2half(e0), __float2half(e1));
                }
            }
        }
    }
    __syncthreads();

    // ---------- Phase B: row sums + prob write (V0 in flight) ----------
    #pragma unroll
    for (int r = w * 2; r < w * 2 + 2; r++) {
        const __half* eh = sE + r * EST;
        uint32_t buf[16];
        float sum = 0.f;
        #pragma unroll
        for (int i = 0; i < 16; i++) {
            buf[i] = *(const uint32_t*)(eh + i * 64 + l * 2);
            __half2 v = *(__half2*)&buf[i];
            sum += __half2float(v.x) + __half2float(v.y);
        }
        #pragma unroll
        for (int o = 16; o > 0; o >>= 1) sum += __shfl_xor_sync(0xffffffffu, sum, o);
        float inv = 1.f / sum;
        if (l == 0) sInv[r] = inv;
        float* orow = attn_out + ((size_t)((b * NH + h) * SS + q0 + r)) * SS;
        #pragma unroll
        for (int i = 0; i < 16; i++) {
            __half2 v = *(__half2*)&buf[i];
            *(float2*)(orow + i * 64 + l * 2) =
                make_float2(__half2float(v.x) * inv, __half2float(v.y) * inv);
        }
    }

    // ---------- Phase C: x = (e @ V) * inv ; 2 chunks x 512 keys, single term ----------
    const int dg = (w & 3) * 16;
    const int kq = w >> 2;   // quarter of 512 keys => 128 keys (8 ksteps)
    float cc[2][2][4];
    #pragma unroll
    for (int m = 0; m < 2; m++)
        #pragma unroll
        for (int nt = 0; nt < 2; nt++)
            #pragma unroll
            for (int q = 0; q < 4; q++) cc[m][nt][q] = 0.f;

    for (int ch = 0; ch < 2; ch++) {
        CP_WAIT0();
        __syncthreads();
        if (ch == 0) { issueX(vpf, 1, 1); CP_COMMIT(); }

        const uint32_t sb = uK0 + (uint32_t)((ch & 1) * ASTG);
        const int kbase = ch * 512 + kq * 128;
        #pragma unroll
        for (int ks = 0; ks < 8; ks++) {
            uint32_t ah2[2][4], bh2[4];
            uint32_t ecol = (uint32_t)((kbase + ks * 16 + (l >> 4) * 8) * 2);
            #pragma unroll
            for (int m = 0; m < 2; m++)
                ldsm_x4(ah2[m], uE + (uint32_t)(((m * 16 + (l & 15)) * EST) * 2) + ecol);
            uint32_t voff = (uint32_t)(((kq * 128 + ks * 16 + (l & 15)) * KVST + dg + (l >> 4) * 8) * 2);
            ldsm_x4_t(bh2, sb + voff);
            #pragma unroll
            for (int m = 0; m < 2; m++) {
                #pragma unroll
                for (int nt = 0; nt < 2; nt++)
                    mma16816h(cc[m][nt], ah2[m], bh2[nt * 2], bh2[nt * 2 + 1]);
            }
        }
    }
    __syncthreads();

    // 4-way k-quarter reduction through smem (overlays stage region)
    if (kq > 0) {
        float* dst = sPart + (kq - 1) * 2048;
        #pragma unroll
        for (int m = 0; m < 2; m++)
            #pragma unroll
            for (int nt = 0; nt < 2; nt++)
                #pragma unroll
                for (int v = 0; v < 4; v++) {
                    int row = m * 16 + (l >> 2) + ((v >> 1) & 1) * 8;
                    int col = dg + nt * 8 + (l & 3) * 2 + (v & 1);
                    dst[row * 64 + col] = cc[m][nt][v];
                }
    }
    __syncthreads();
    if (kq == 0) {
        #pragma unroll
        for (int m = 0; m < 2; m++) {
            #pragma unroll
            for (int nt = 0; nt < 2; nt++) {
                #pragma unroll
                for (int hf = 0; hf < 2; hf++) {
                    int row = m * 16 + (l >> 2) + hf * 8;
                    int col = dg + nt * 8 + (l & 3) * 2;
                    float inv = sInv[row];
                    float x0 = cc[m][nt][hf * 2 + 0];
                    float x1 = cc[m][nt][hf * 2 + 1];
                    #pragma unroll
                    for (int p = 0; p < 3; p++) {
                        x0 += sPart[p * 2048 + row * 64 + col];
                        x1 += sPart[p * 2048 + row * 64 + col + 1];
                    }
                    x0 *= inv; x1 *= inv;
                    size_t g = ((size_t)(b * SS + q0 + row)) * HID + h * HD + col;
                    *(__half2*)(xf + g) = __halves2half2(__float2half(x0), __float2half(x1));
                }
            }
        }
    }
}

// ================= launch =================
extern "C" void kernel_launch(void* const* d_in, const int* in_sizes, int n_in,
                              void* d_out, int out_size)
{
    const float* query = (const float*)d_in[0];
    const float* key_t = (const float*)d_in[1];
    const float* value = (const float*)d_in[2];
    const int*   mask  = (const int*)d_in[3];
    const float* Wq = (const float*)d_in[4];  const float* bq = (const float*)d_in[5];
    const float* Wk = (const float*)d_in[6];  const float* bk = (const float*)d_in[7];
    const float* Wv = (const float*)d_in[8];  const float* bv = (const float*)d_in[9];
    const float* Wo = (const float*)d_in[10]; const float* bo = (const float*)d_in[11];
    const float* W1 = (const float*)d_in[12]; const float* b1 = (const float*)d_in[13];
    const float* W2 = (const float*)d_in[14]; const float* b2 = (const float*)d_in[15];

    float* out       = (float*)d_out;
    float* out_gated = out;
    float* out_attn  = out + MH;

    float *F1;
    __half *kf, *vf, *qfp, *kpf, *vpf, *xf, *cat, *wqk, *wfo, *wf;
    cudaGetSymbolAddress((void**)&F1, g_f1);
    cudaGetSymbolAddress((void**)&kf, g_kf);
    cudaGetSymbolAddress((void**)&vf, g_vf);
    cudaGetSymbolAddress((void**)&qfp, g_qf);
    cudaGetSymbolAddress((void**)&kpf, g_kpf);
    cudaGetSymbolAddress((void**)&vpf, g_vpf);
    cudaGetSymbolAddress((void**)&xf, g_xf);
    cudaGetSymbolAddress((void**)&cat, g_cat);
    cudaGetSymbolAddress((void**)&wqk, g_wqk);
    cudaGetSymbolAddress((void**)&wfo, g_wfo);
    cudaGetSymbolAddress((void**)&wf, g_wf);

    size_t fsmem = (size_t)2 * FSTAGE * 2;   // 73728 B
    cudaFuncSetAttribute(gemm_qkv, cudaFuncAttributeMaxDynamicSharedMemorySize, (int)fsmem);
    cudaFuncSetAttribute(gemm_fp16, cudaFuncAttributeMaxDynamicSharedMemorySize, (int)fsmem);
    cudaFuncSetAttribute(attn_mma, cudaFuncAttributeMaxDynamicSharedMemorySize, ATTN_SMEM);

    const int actBlocks = (MROWS * HID / 4 + 255) / 256;
    dim3 wblk(32, 8);
    dim3 ggrid(HID / 128, MROWS / 128);      // (6, 64)

    // --- input conversions + weight splits ---
    conv3<<<dim3(actBlocks, 3), 256>>>(query, key_t, value, cat, kf, vf);
    split_wqk3<<<dim3(HID / 32, HID / 32, 3), wblk>>>(Wq, Wk, Wv, wqk);

    // --- QKV projections (fp16 single-term; Q pre-scaled 1/8) ---
    gemm_qkv<<<dim3(HID / 128, MROWS / 128, 3), 256, fsmem>>>(
        cat + HID, kf, vf, wqk, bq, bk, bv, qfp, kpf, vpf);

    // --- attention ---
    attn_mma<<<dim3(SS / 32, NH, BB), 512, ATTN_SMEM>>>(
        qfp, kpf, vpf, mask, out_attn, xf);

    // --- Wo (fp16) -> cat[:, 0:768] ---
    split_w_fp16<<<dim3(HID / 32, HID / 32), wblk>>>(Wo, HID, HID, wfo);
    gemm_fp16<<<ggrid, 256, fsmem>>>(
        xf, HID, wfo, HID, bo, nullptr, nullptr, cat, 2 * HID, 2);

    // --- FFN (fp16, K=1536) ---
    split_wf2<<<dim3(HID / 32, 2 * HID / 32, 2), wblk>>>(W1, W2, wf);
    gemm_fp16<<<ggrid, 256, fsmem>>>(
        cat, 2 * HID, wf, 2 * HID, b1, nullptr, F1, nullptr, 0, 0);
    gemm_fp16<<<ggrid, 256, fsmem>>>(
        cat, 2 * HID, wf + (size_t)2 * HID * HID, 2 * HID, b2, F1, out_gated, nullptr, 0, 1);
}

// round 12
// speedup vs baseline: 8.3823x; 1.0936x over previous
#include <cuda_runtime.h>
#include <cuda_fp16.h>
#include <math.h>
#include <stdint.h>

#define BB 8
#define SS 1024
#define HID 768
#define NH 12
#define HD 64
#define MROWS (BB*SS)   // 8192
#define MH ((size_t)MROWS*HID)

// ---------------- scratch (device globals; no allocation allowed) ----------------
__device__ __align__(256) float g_f1 [(size_t)MROWS*HID];

__device__ __align__(256) __half g_kf [MH];                     // raw key fp16
__device__ __align__(256) __half g_vf [MH];                     // raw value fp16
__device__ __align__(256) __half g_qf [MH];                     // projected Q (fp16, prescaled)
__device__ __align__(256) __half g_kpf[MH];                     // projected K (fp16)
__device__ __align__(256) __half g_vpf[MH];                     // projected V (fp16)

__device__ __align__(256) __half g_xf [MH];
__device__ __align__(256) __half g_cat[2*MH];
__device__ __align__(256) __half g_wqk[(size_t)3*HID*HID];      // Wq,Wk,Wv fp16 [N][K]
__device__ __align__(256) __half g_wfo[(size_t)HID*HID];
__device__ __align__(256) __half g_wf [(size_t)2*2*HID*HID];

// ================= helpers =================
__device__ __forceinline__ uint32_t smem_u32(const void* p) {
    uint32_t a;
    asm("{ .reg .u64 t; cvta.to.shared.u64 t, %1; cvt.u32.u64 %0, t; }" : "=r"(a) : "l"(p));
    return a;
}
__device__ __forceinline__ void ldsm_x4(uint32_t* r, uint32_t addr) {
    asm volatile("ldmatrix.sync.aligned.m8n8.x4.shared.b16 {%0,%1,%2,%3}, [%4];"
                 : "=r"(r[0]), "=r"(r[1]), "=r"(r[2]), "=r"(r[3]) : "r"(addr));
}
__device__ __forceinline__ void ldsm_x4_t(uint32_t* r, uint32_t addr) {
    asm volatile("ldmatrix.sync.aligned.m8n8.x4.trans.shared.b16 {%0,%1,%2,%3}, [%4];"
                 : "=r"(r[0]), "=r"(r[1]), "=r"(r[2]), "=r"(r[3]) : "r"(addr));
}
__device__ __forceinline__ void mma16816h(float* c, const uint32_t* a, uint32_t b0, uint32_t b1) {
    asm volatile("mma.sync.aligned.m16n8k16.row.col.f32.f16.f16.f32 "
                 "{%0,%1,%2,%3}, {%4,%5,%6,%7}, {%8,%9}, {%0,%1,%2,%3};"
                 : "+f"(c[0]), "+f"(c[1]), "+f"(c[2]), "+f"(c[3])
                 : "r"(a[0]), "r"(a[1]), "r"(a[2]), "r"(a[3]), "r"(b0), "r"(b1));
}
__device__ __forceinline__ void cp16(uint32_t dst, const void* src) {
    asm volatile("cp.async.cg.shared.global [%0], [%1], 16;" :: "r"(dst), "l"(src));
}
#define CP_COMMIT() asm volatile("cp.async.commit_group;" ::: "memory")
#define CP_WAIT0()  asm volatile("cp.async.wait_group 0;" ::: "memory")

// ================= convert / weight-split kernels =================
__global__ void conv3(const float* __restrict__ q, const float* __restrict__ k,
                      const float* __restrict__ v,
                      __half* __restrict__ cat, __half* __restrict__ kf,
                      __half* __restrict__ vf)
{
    const int z = blockIdx.y;
    const float* src = (z == 0) ? q : (z == 1) ? k : v;
    size_t total = MH / 4;
    for (size_t i = (size_t)blockIdx.x * blockDim.x + threadIdx.x; i < total;
         i += (size_t)gridDim.x * blockDim.x) {
        size_t e = i * 4;
        int m = (int)(e / HID), c = (int)(e % HID);
        float4 x = *(const float4*)(src + e);
        __half* dst = (z == 0) ? (cat + (size_t)m * (2 * HID) + HID + c)
                    : (z == 1) ? (kf + e) : (vf + e);
        *(__half2*)(dst)     = __halves2half2(__float2half(x.x), __float2half(x.y));
        *(__half2*)(dst + 2) = __halves2half2(__float2half(x.z), __float2half(x.w));
    }
}

__global__ void split_wqk3(const float* __restrict__ Wa, const float* __restrict__ Wb,
                           const float* __restrict__ Wc, __half* __restrict__ out)
{
    __shared__ float t[32][33];
    const int z = blockIdx.z;
    const float* W = (z == 0) ? Wa : (z == 1) ? Wb : Wc;
    __half* O = out + (size_t)z * HID * HID;
    int n0 = blockIdx.x * 32, k0 = blockIdx.y * 32;
    int tx = threadIdx.x, ty = threadIdx.y;
    for (int j = ty; j < 32; j += 8)
        t[j][tx] = W[(size_t)(k0 + j) * HID + n0 + tx];
    __syncthreads();
    for (int j = ty; j < 32; j += 8)
        O[(size_t)(n0 + j) * HID + k0 + tx] = __float2half(t[tx][j]);
}

__global__ void split_w_fp16(const float* __restrict__ W, int K, int N,
                             __half* __restrict__ out)
{
    __shared__ float t[32][33];
    int n0 = blockIdx.x * 32, k0 = blockIdx.y * 32;
    int tx = threadIdx.x, ty = threadIdx.y;
    for (int j = ty; j < 32; j += 8)
        t[j][tx] = W[(size_t)(k0 + j) * N + n0 + tx];
    __syncthreads();
    for (int j = ty; j < 32; j += 8)
        out[(size_t)(n0 + j) * K + k0 + tx] = __float2half(t[tx][j]);
}

__global__ void split_wf2(const float* __restrict__ Wa, const float* __restrict__ Wb,
                          __half* __restrict__ out)
{
    __shared__ float t[32][33];
    const int z = blockIdx.z;
    const float* W = (z == 0) ? Wa : Wb;
    __half* O = out + (size_t)z * 2 * HID * HID;
    int n0 = blockIdx.x * 32, k0 = blockIdx.y * 32;
    int tx = threadIdx.x, ty = threadIdx.y;
    for (int j = ty; j < 32; j += 8)
        t[j][tx] = W[(size_t)(k0 + j) * HID + n0 + tx];
    __syncthreads();
    for (int j = ty; j < 32; j += 8)
        O[(size_t)(n0 + j) * (2 * HID) + k0 + tx] = __float2half(t[tx][j]);
}

// ================= fp16 QKV projection GEMM (batched z = 0,1,2) =================
#define GSTRIDE 72
#define GBUF (128 * GSTRIDE)
#define FSTAGE (2 * GBUF)

__global__ __launch_bounds__(256) void gemm_qkv(
    const __half* __restrict__ Aq, const __half* __restrict__ Ak,
    const __half* __restrict__ Av, const __half* __restrict__ Bw,
    const float* __restrict__ bq, const float* __restrict__ bk,
    const float* __restrict__ bv,
    __half* __restrict__ oq, __half* __restrict__ ok, __half* __restrict__ ov)
{
    extern __shared__ __half smh[];
    const int tid = threadIdx.x;
    const int w = tid >> 5, l = tid & 31;
    const int z = blockIdx.z;
    const int m0 = blockIdx.y * 128;
    const int n0 = blockIdx.x * 128;
    const int wm = (w >> 2) * 64;
    const int wn = (w & 3) * 32;

    const __half* A = (z == 0) ? Aq : (z == 1) ? Ak : Av;
    const int lda = (z == 0) ? 2 * HID : HID;
    const __half* B = Bw + (size_t)z * HID * HID;
    const float* bias = (z == 0) ? bq : (z == 1) ? bk : bv;
    const float scale = (z == 0) ? 0.125f : 1.f;
    __half* out = (z == 0) ? oq : (z == 1) ? ok : ov;

    float c[4][4][4];
    #pragma unroll
    for (int i = 0; i < 4; i++)
        #pragma unroll
        for (int j = 0; j < 4; j++)
            #pragma unroll
            for (int q = 0; q < 4; q++) c[i][j][q] = 0.f;

    const uint32_t sbase = smem_u32(smh);
    const int aRow = wm + (l & 15), aKof = (l >> 4) * 8;
    const int bRow = wn + (l >> 4) * 8 + (l & 7), bKof = ((l >> 3) & 1) * 8;
    const int nChunks = HID >> 6;

    auto issue = [&](int ch) {
        const uint32_t dstBase = sbase + (uint32_t)((ch & 1) * FSTAGE * 2);
        const int k0 = ch << 6;
        #pragma unroll
        for (int i = 0; i < 4; i++) {
            int t = tid + i * 256;
            int row = t >> 3, c8 = (t & 7) * 8;
            uint32_t d = dstBase + (uint32_t)((row * GSTRIDE + c8) * 2);
            cp16(d,            A + (size_t)(m0 + row) * lda + k0 + c8);
            cp16(d + GBUF * 2, B + (size_t)(n0 + row) * HID + k0 + c8);
        }
    };

    issue(0); CP_COMMIT();
    for (int ch = 0; ch < nChunks; ch++) {
        CP_WAIT0();
        __syncthreads();
        if (ch + 1 < nChunks) { issue(ch + 1); CP_COMMIT(); }

        const uint32_t sb = sbase + (uint32_t)((ch & 1) * FSTAGE * 2);
        const uint32_t aB = sb + (uint32_t)((aRow * GSTRIDE + aKof) * 2);
        const uint32_t bB = sb + GBUF * 2 + (uint32_t)((bRow * GSTRIDE + bKof) * 2);

        #pragma unroll
        for (int ks = 0; ks < 4; ks++) {
            const uint32_t kb = (uint32_t)(ks * 16 * 2);
            uint32_t ah[4][4], bh[2][4];
            #pragma unroll
            for (int mi = 0; mi < 4; mi++)
                ldsm_x4(ah[mi], aB + (uint32_t)(mi * 16 * GSTRIDE * 2) + kb);
            #pragma unroll
            for (int p = 0; p < 2; p++)
                ldsm_x4(bh[p], bB + (uint32_t)(p * 16 * GSTRIDE * 2) + kb);
            #pragma unroll
            for (int mi = 0; mi < 4; mi++) {
                #pragma unroll
                for (int nj = 0; nj < 4; nj++) {
                    const int p = nj >> 1, s = (nj & 1) * 2;
                    mma16816h(c[mi][nj], ah[mi], bh[p][s], bh[p][s + 1]);
                }
            }
        }
        __syncthreads();
    }

    #pragma unroll
    for (int mi = 0; mi < 4; mi++) {
        int r0 = m0 + wm + mi * 16 + (l >> 2);
        #pragma unroll
        for (int nj = 0; nj < 4; nj++) {
            int col = n0 + wn + nj * 8 + (l & 3) * 2;
            float b0 = bias[col], b1 = bias[col + 1];
            #pragma unroll
            for (int half = 0; half < 2; half++) {
                int r = r0 + half * 8;
                float v0 = (c[mi][nj][half * 2 + 0] + b0) * scale;
                float v1 = (c[mi][nj][half * 2 + 1] + b1) * scale;
                *(__half2*)(out + (size_t)r * HID + col) =
                    __halves2half2(__float2half(v0), __float2half(v1));
            }
        }
    }
}

// ================= fp16 single-term GEMM (Wo / FFN) =================
__global__ __launch_bounds__(256) void gemm_fp16(
    const __half* __restrict__ A, int lda, const __half* __restrict__ B,
    int Kdim, const float* __restrict__ bias, const float* __restrict__ prev,
    float* __restrict__ Cf, __half* __restrict__ Ch, int ldch, int mode)
{
    extern __shared__ __half smh[];
    const int tid = threadIdx.x;
    const int w = tid >> 5, l = tid & 31;
    const int m0 = blockIdx.y * 128;
    const int n0 = blockIdx.x * 128;
    const int wm = (w >> 2) * 64;
    const int wn = (w & 3) * 32;

    float c[4][4][4];
    #pragma unroll
    for (int i = 0; i < 4; i++)
        #pragma unroll
        for (int j = 0; j < 4; j++)
            #pragma unroll
            for (int q = 0; q < 4; q++) c[i][j][q] = 0.f;

    const uint32_t sbase = smem_u32(smh);
    const int aRow = wm + (l & 15), aKof = (l >> 4) * 8;
    const int bRow = wn + (l >> 4) * 8 + (l & 7), bKof = ((l >> 3) & 1) * 8;
    const int nChunks = Kdim >> 6;

    auto issue = [&](int ch) {
        const uint32_t dstBase = sbase + (uint32_t)((ch & 1) * FSTAGE * 2);
        const int k0 = ch << 6;
        #pragma unroll
        for (int i = 0; i < 4; i++) {
            int t = tid + i * 256;
            int row = t >> 3, c8 = (t & 7) * 8;
            uint32_t d = dstBase + (uint32_t)((row * GSTRIDE + c8) * 2);
            cp16(d,            A + (size_t)(m0 + row) * lda  + k0 + c8);
            cp16(d + GBUF * 2, B + (size_t)(n0 + row) * Kdim + k0 + c8);
        }
    };

    issue(0); CP_COMMIT();
    for (int ch = 0; ch < nChunks; ch++) {
        CP_WAIT0();
        __syncthreads();
        if (ch + 1 < nChunks) { issue(ch + 1); CP_COMMIT(); }

        const uint32_t sb = sbase + (uint32_t)((ch & 1) * FSTAGE * 2);
        const uint32_t aB = sb + (uint32_t)((aRow * GSTRIDE + aKof) * 2);
        const uint32_t bB = sb + GBUF * 2 + (uint32_t)((bRow * GSTRIDE + bKof) * 2);

        #pragma unroll
        for (int ks = 0; ks < 4; ks++) {
            const uint32_t kb = (uint32_t)(ks * 16 * 2);
            uint32_t ah[4][4], bh[2][4];
            #pragma unroll
            for (int mi = 0; mi < 4; mi++)
                ldsm_x4(ah[mi], aB + (uint32_t)(mi * 16 * GSTRIDE * 2) + kb);
            #pragma unroll
            for (int p = 0; p < 2; p++)
                ldsm_x4(bh[p], bB + (uint32_t)(p * 16 * GSTRIDE * 2) + kb);
            #pragma unroll
            for (int mi = 0; mi < 4; mi++) {
                #pragma unroll
                for (int nj = 0; nj < 4; nj++) {
                    const int p = nj >> 1, s = (nj & 1) * 2;
                    mma16816h(c[mi][nj], ah[mi], bh[p][s], bh[p][s + 1]);
                }
            }
        }
        __syncthreads();
    }

    #pragma unroll
    for (int mi = 0; mi < 4; mi++) {
        int r0 = m0 + wm + mi * 16 + (l >> 2);
        #pragma unroll
        for (int nj = 0; nj < 4; nj++) {
            int col = n0 + wn + nj * 8 + (l & 3) * 2;
            float b0 = bias[col], b1 = bias[col + 1];
            #pragma unroll
            for (int half = 0; half < 2; half++) {
                int r = r0 + half * 8;
                float v0 = c[mi][nj][half * 2 + 0] + b0;
                float v1 = c[mi][nj][half * 2 + 1] + b1;
                if (mode == 2) {
                    *(__half2*)(Ch + (size_t)r * ldch + col) =
                        __halves2half2(__float2half(v0), __float2half(v1));
                } else {
                    if (mode == 1) {
                        float g0 = prev[(size_t)r * HID + col];
                        float g1 = prev[(size_t)r * HID + col + 1];
                        v0 *= 1.f / (1.f + __expf(-g0));
                        v1 *= 1.f / (1.f + __expf(-g1));
                    }
                    *(float2*)(Cf + (size_t)r * HID + col) = make_float2(v0, v1);
                }
            }
        }
    }
}

// ================= attention v5: 64-query tiles, all-fp16 =================
// smem bytes:
//   sQ  [0, 9216)                 : 64 x 72 fp16
//   stages 2 x 36864 [9216, 82944): 256 keys x 72 fp16 (K or V)
//   sE  [82944, 215040)           : 64 x 1032 fp16
//   sMask [215040, 219136)        : 1024 int
//   sInv  [219136, 219392)        : 64 float
#define EST 1032
#define KVST 72
#define ASTG 36864
#define ATTN_SMEM 219392

__global__ __launch_bounds__(512) void attn_mma(
    const __half* __restrict__ qf, const __half* __restrict__ kpf,
    const __half* __restrict__ vpf,
    const int* __restrict__ mask, float* __restrict__ attn_out,
    __half* __restrict__ xf)
{
    extern __shared__ char sab[];
    __half* sQ = (__half*)(sab);
    __half* sE = (__half*)(sab + 82944);
    int*   sMask = (int*)(sab + 215040);
    float* sInv  = (float*)(sab + 219136);

    const int tid = threadIdx.x, w = tid >> 5, l = tid & 31;
    const int q0 = blockIdx.x * 64, h = blockIdx.y, b = blockIdx.z;

    const uint32_t uQ  = smem_u32(sab);
    const uint32_t uK0 = uQ + 9216;
    const uint32_t uE  = uQ + 82944;

    // load Q tile (64 x 64 fp16): 512 threads x 1 uint4
    {
        int r = tid >> 3, c8 = (tid & 7) * 8;
        size_t g = ((size_t)(b * SS + q0 + r)) * HID + h * HD + c8;
        *(uint4*)(sQ + r * KVST + c8) = *(const uint4*)(qf + g);
    }
    for (int k = tid; k < SS; k += 512) sMask[k] = mask[b * SS + k];

    const int mg = w & 3;           // 16-query row group
    const int kg = w >> 2;          // Phase A: 64-key group within chunk
    const int bRowL = (l >> 4) * 8 + (l & 7);
    const int bKofL = ((l >> 3) & 1) * 8;
    const uint32_t aLaneOff = (uint32_t)(((mg * 16 + (l & 15)) * KVST + (l >> 4) * 8) * 2);

    // issue one 256-key fp16 chunk into stage st
    auto issueX = [&](const __half* src, int chunk, int st) {
        const uint32_t dst = uK0 + (uint32_t)(st * ASTG);
        const int r0 = chunk * 256;
        #pragma unroll
        for (int i = 0; i < 4; i++) {
            int t = tid + i * 512;
            int row = t >> 3, c8 = (t & 7) * 8;
            uint32_t d = dst + (uint32_t)((row * KVST + c8) * 2);
            size_t g = ((size_t)(b * SS + r0 + row)) * HID + h * HD + c8;
            cp16(d, src + g);
        }
    };

    // ---------- Phase A: e = mask * exp(Q K^T) -> sE ; 4 chunks x 256 keys ----------
    issueX(kpf, 0, 0); CP_COMMIT();
    for (int ch = 0; ch < 4; ch++) {
        CP_WAIT0();
        __syncthreads();
        if (ch < 3) issueX(kpf, ch + 1, (ch + 1) & 1);
        else        issueX(vpf, 0, 0);     // prefetch V chunk 0
        CP_COMMIT();

        const uint32_t sb = uK0 + (uint32_t)((ch & 1) * ASTG);
        const int kc0 = ch * 256 + kg * 64;

        float acc[4][2][4];
        #pragma unroll
        for (int p = 0; p < 4; p++)
            #pragma unroll
            for (int t = 0; t < 2; t++)
                #pragma unroll
                for (int q = 0; q < 4; q++) acc[p][t][q] = 0.f;

        #pragma unroll
        for (int ks = 0; ks < 4; ks++) {
            uint32_t ah[4], bh[4][4];
            ldsm_x4(ah, uQ + aLaneOff + (uint32_t)(ks * 16 * 2));
            #pragma unroll
            for (int p = 0; p < 4; p++)
                ldsm_x4(bh[p], sb + (uint32_t)(((kg * 64 + p * 16 + bRowL) * KVST + ks * 16 + bKofL) * 2));
            #pragma unroll
            for (int p = 0; p < 4; p++) {
                #pragma unroll
                for (int t = 0; t < 2; t++)
                    mma16816h(acc[p][t], ah, bh[p][t * 2], bh[p][t * 2 + 1]);
            }
        }
        // epilogue: mask + exp + fp16 store
        #pragma unroll
        for (int p = 0; p < 4; p++) {
            #pragma unroll
            for (int t = 0; t < 2; t++) {
                int kcol = kc0 + p * 16 + t * 8 + (l & 3) * 2;
                int mk0 = sMask[kcol], mk1 = sMask[kcol + 1];
                #pragma unroll
                for (int hf = 0; hf < 2; hf++) {
                    int row = mg * 16 + (l >> 2) + hf * 8;
                    float e0 = mk0 ? __expf(fminf(acc[p][t][hf * 2 + 0], 11.f)) : 0.f;
                    float e1 = mk1 ? __expf(fminf(acc[p][t][hf * 2 + 1], 11.f)) : 0.f;
                    *(__half2*)(sE + row * EST + kcol) =
                        __halves2half2(__float2half(e0), __float2half(e1));
                }
            }
        }
    }
    __syncthreads();

    // ---------- Phase B: row sums + prob write (V0 in flight); 4 rows per warp ----------
    #pragma unroll
    for (int r = w * 4; r < w * 4 + 4; r++) {
        const __half* eh = sE + r * EST;
        uint32_t buf[16];
        float sum = 0.f;
        #pragma unroll
        for (int i = 0; i < 16; i++) {
            buf[i] = *(const uint32_t*)(eh + i * 64 + l * 2);
            __half2 v = *(__half2*)&buf[i];
            sum += __half2float(v.x) + __half2float(v.y);
        }
        #pragma unroll
        for (int o = 16; o > 0; o >>= 1) sum += __shfl_xor_sync(0xffffffffu, sum, o);
        float inv = 1.f / sum;
        if (l == 0) sInv[r] = inv;
        float* orow = attn_out + ((size_t)((b * NH + h) * SS + q0 + r)) * SS;
        #pragma unroll
        for (int i = 0; i < 16; i++) {
            __half2 v = *(__half2*)&buf[i];
            *(float2*)(orow + i * 64 + l * 2) =
                make_float2(__half2float(v.x) * inv, __half2float(v.y) * inv);
        }
    }

    // ---------- Phase C: x = (e @ V) * inv ; warp = (mg, dg); accumulates ALL keys ----------
    const int dg = (w >> 2) * 16;
    float cc[2][4];
    #pragma unroll
    for (int nt = 0; nt < 2; nt++)
        #pragma unroll
        for (int q = 0; q < 4; q++) cc[nt][q] = 0.f;

    for (int ch = 0; ch < 4; ch++) {
        CP_WAIT0();
        __syncthreads();
        if (ch < 3) { issueX(vpf, ch + 1, (ch + 1) & 1); CP_COMMIT(); }

        const uint32_t sb = uK0 + (uint32_t)((ch & 1) * ASTG);
        const int kbase = ch * 256;
        #pragma unroll
        for (int ks = 0; ks < 16; ks++) {
            uint32_t ah2[4], bh2[4];
            ldsm_x4(ah2, uE + (uint32_t)(((mg * 16 + (l & 15)) * EST + kbase + ks * 16 + (l >> 4) * 8) * 2));
            ldsm_x4_t(bh2, sb + (uint32_t)(((ks * 16 + (l & 15)) * KVST + dg + (l >> 4) * 8) * 2));
            mma16816h(cc[0], ah2, bh2[0], bh2[1]);
            mma16816h(cc[1], ah2, bh2[2], bh2[3]);
        }
    }

    // epilogue: direct write (no cross-warp reduction needed)
    #pragma unroll
    for (int nt = 0; nt < 2; nt++) {
        #pragma unroll
        for (int hf = 0; hf < 2; hf++) {
            int row = mg * 16 + (l >> 2) + hf * 8;
            int col = dg + nt * 8 + (l & 3) * 2;
            float inv = sInv[row];
            float x0 = cc[nt][hf * 2 + 0] * inv;
            float x1 = cc[nt][hf * 2 + 1] * inv;
            size_t g = ((size_t)(b * SS + q0 + row)) * HID + h * HD + col;
            *(__half2*)(xf + g) = __halves2half2(__float2half(x0), __float2half(x1));
        }
    }
}

// ================= launch =================
extern "C" void kernel_launch(void* const* d_in, const int* in_sizes, int n_in,
                              void* d_out, int out_size)
{
    const float* query = (const float*)d_in[0];
    const float* key_t = (const float*)d_in[1];
    const float* value = (const float*)d_in[2];
    const int*   mask  = (const int*)d_in[3];
    const float* Wq = (const float*)d_in[4];  const float* bq = (const float*)d_in[5];
    const float* Wk = (const float*)d_in[6];  const float* bk = (const float*)d_in[7];
    const float* Wv = (const float*)d_in[8];  const float* bv = (const float*)d_in[9];
    const float* Wo = (const float*)d_in[10]; const float* bo = (const float*)d_in[11];
    const float* W1 = (const float*)d_in[12]; const float* b1 = (const float*)d_in[13];
    const float* W2 = (const float*)d_in[14]; const float* b2 = (const float*)d_in[15];

    float* out       = (float*)d_out;
    float* out_gated = out;
    float* out_attn  = out + MH;

    float *F1;
    __half *kf, *vf, *qfp, *kpf, *vpf, *xf, *cat, *wqk, *wfo, *wf;
    cudaGetSymbolAddress((void**)&F1, g_f1);
    cudaGetSymbolAddress((void**)&kf, g_kf);
    cudaGetSymbolAddress((void**)&vf, g_vf);
    cudaGetSymbolAddress((void**)&qfp, g_qf);
    cudaGetSymbolAddress((void**)&kpf, g_kpf);
    cudaGetSymbolAddress((void**)&vpf, g_vpf);
    cudaGetSymbolAddress((void**)&xf, g_xf);
    cudaGetSymbolAddress((void**)&cat, g_cat);
    cudaGetSymbolAddress((void**)&wqk, g_wqk);
    cudaGetSymbolAddress((void**)&wfo, g_wfo);
    cudaGetSymbolAddress((void**)&wf, g_wf);

    size_t fsmem = (size_t)2 * FSTAGE * 2;   // 73728 B
    cudaFuncSetAttribute(gemm_qkv, cudaFuncAttributeMaxDynamicSharedMemorySize, (int)fsmem);
    cudaFuncSetAttribute(gemm_fp16, cudaFuncAttributeMaxDynamicSharedMemorySize, (int)fsmem);
    cudaFuncSetAttribute(attn_mma, cudaFuncAttributeMaxDynamicSharedMemorySize, ATTN_SMEM);

    const int actBlocks = (MROWS * HID / 4 + 255) / 256;
    dim3 wblk(32, 8);
    dim3 ggrid(HID / 128, MROWS / 128);      // (6, 64)

    // --- input conversions + weight splits ---
    conv3<<<dim3(actBlocks, 3), 256>>>(query, key_t, value, cat, kf, vf);
    split_wqk3<<<dim3(HID / 32, HID / 32, 3), wblk>>>(Wq, Wk, Wv, wqk);

    // --- QKV projections (fp16 single-term; Q pre-scaled 1/8) ---
    gemm_qkv<<<dim3(HID / 128, MROWS / 128, 3), 256, fsmem>>>(
        cat + HID, kf, vf, wqk, bq, bk, bv, qfp, kpf, vpf);

    // --- attention (64-query tiles) ---
    attn_mma<<<dim3(SS / 64, NH, BB), 512, ATTN_SMEM>>>(
        qfp, kpf, vpf, mask, out_attn, xf);

    // --- Wo (fp16) -> cat[:, 0:768] ---
    split_w_fp16<<<dim3(HID / 32, HID / 32), wblk>>>(Wo, HID, HID, wfo);
    gemm_fp16<<<ggrid, 256, fsmem>>>(
        xf, HID, wfo, HID, bo, nullptr, nullptr, cat, 2 * HID, 2);

    // --- FFN (fp16, K=1536) ---
    split_wf2<<<dim3(HID / 32, 2 * HID / 32, 2), wblk>>>(W1, W2, wf);
    gemm_fp16<<<ggrid, 256, fsmem>>>(
        cat, 2 * HID, wf, 2 * HID, b1, nullptr, F1, nullptr, 0, 0);
    gemm_fp16<<<ggrid, 256, fsmem>>>(
        cat, 2 * HID, wf + (size_t)2 * HID * HID, 2 * HID, b2, F1, out_gated, nullptr, 0, 1);
}

// round 13
// speedup vs baseline: 8.5716x; 1.0226x over previous
#include <cuda_runtime.h>
#include <cuda_fp16.h>
#include <math.h>
#include <stdint.h>

#define BB 8
#define SS 1024
#define HID 768
#define NH 12
#define HD 64
#define MROWS (BB*SS)   // 8192
#define MH ((size_t)MROWS*HID)

// ---------------- scratch (device globals; no allocation allowed) ----------------
__device__ __align__(256) __half g_kf [MH];                     // raw key fp16
__device__ __align__(256) __half g_vf [MH];                     // raw value fp16
__device__ __align__(256) __half g_qf [MH];                     // projected Q (fp16, prescaled)
__device__ __align__(256) __half g_kpf[MH];                     // projected K (fp16)
__device__ __align__(256) __half g_vpf[MH];                     // projected V (fp16)

__device__ __align__(256) __half g_xf [MH];
__device__ __align__(256) __half g_cat[2*MH];
__device__ __align__(256) __half g_wqk[(size_t)3*HID*HID];      // Wq,Wk,Wv fp16 [N][K]
__device__ __align__(256) __half g_wfo[(size_t)HID*HID];
__device__ __align__(256) __half g_wf [(size_t)2*2*HID*HID];    // W1,W2 fp16 [N][K]

// ================= helpers =================
__device__ __forceinline__ uint32_t smem_u32(const void* p) {
    uint32_t a;
    asm("{ .reg .u64 t; cvta.to.shared.u64 t, %1; cvt.u32.u64 %0, t; }" : "=r"(a) : "l"(p));
    return a;
}
__device__ __forceinline__ void ldsm_x4(uint32_t* r, uint32_t addr) {
    asm volatile("ldmatrix.sync.aligned.m8n8.x4.shared.b16 {%0,%1,%2,%3}, [%4];"
                 : "=r"(r[0]), "=r"(r[1]), "=r"(r[2]), "=r"(r[3]) : "r"(addr));
}
__device__ __forceinline__ void ldsm_x4_t(uint32_t* r, uint32_t addr) {
    asm volatile("ldmatrix.sync.aligned.m8n8.x4.trans.shared.b16 {%0,%1,%2,%3}, [%4];"
                 : "=r"(r[0]), "=r"(r[1]), "=r"(r[2]), "=r"(r[3]) : "r"(addr));
}
__device__ __forceinline__ void mma16816h(float* c, const uint32_t* a, uint32_t b0, uint32_t b1) {
    asm volatile("mma.sync.aligned.m16n8k16.row.col.f32.f16.f16.f32 "
                 "{%0,%1,%2,%3}, {%4,%5,%6,%7}, {%8,%9}, {%0,%1,%2,%3};"
                 : "+f"(c[0]), "+f"(c[1]), "+f"(c[2]), "+f"(c[3])
                 : "r"(a[0]), "r"(a[1]), "r"(a[2]), "r"(a[3]), "r"(b0), "r"(b1));
}
__device__ __forceinline__ void cp16(uint32_t dst, const void* src) {
    asm volatile("cp.async.cg.shared.global [%0], [%1], 16;" :: "r"(dst), "l"(src));
}
#define CP_COMMIT() asm volatile("cp.async.commit_group;" ::: "memory")
#define CP_WAIT0()  asm volatile("cp.async.wait_group 0;" ::: "memory")

// ================= convert / weight-split kernels =================
__global__ void conv3(const float* __restrict__ q, const float* __restrict__ k,
                      const float* __restrict__ v,
                      __half* __restrict__ cat, __half* __restrict__ kf,
                      __half* __restrict__ vf)
{
    const int z = blockIdx.y;
    const float* src = (z == 0) ? q : (z == 1) ? k : v;
    size_t total = MH / 4;
    for (size_t i = (size_t)blockIdx.x * blockDim.x + threadIdx.x; i < total;
         i += (size_t)gridDim.x * blockDim.x) {
        size_t e = i * 4;
        int m = (int)(e / HID), c = (int)(e % HID);
        float4 x = *(const float4*)(src + e);
        __half* dst = (z == 0) ? (cat + (size_t)m * (2 * HID) + HID + c)
                    : (z == 1) ? (kf + e) : (vf + e);
        *(__half2*)(dst)     = __halves2half2(__float2half(x.x), __float2half(x.y));
        *(__half2*)(dst + 2) = __halves2half2(__float2half(x.z), __float2half(x.w));
    }
}

__global__ void split_wqk3(const float* __restrict__ Wa, const float* __restrict__ Wb,
                           const float* __restrict__ Wc, __half* __restrict__ out)
{
    __shared__ float t[32][33];
    const int z = blockIdx.z;
    const float* W = (z == 0) ? Wa : (z == 1) ? Wb : Wc;
    __half* O = out + (size_t)z * HID * HID;
    int n0 = blockIdx.x * 32, k0 = blockIdx.y * 32;
    int tx = threadIdx.x, ty = threadIdx.y;
    for (int j = ty; j < 32; j += 8)
        t[j][tx] = W[(size_t)(k0 + j) * HID + n0 + tx];
    __syncthreads();
    for (int j = ty; j < 32; j += 8)
        O[(size_t)(n0 + j) * HID + k0 + tx] = __float2half(t[tx][j]);
}

__global__ void split_w_fp16(const float* __restrict__ W, int K, int N,
                             __half* __restrict__ out)
{
    __shared__ float t[32][33];
    int n0 = blockIdx.x * 32, k0 = blockIdx.y * 32;
    int tx = threadIdx.x, ty = threadIdx.y;
    for (int j = ty; j < 32; j += 8)
        t[j][tx] = W[(size_t)(k0 + j) * N + n0 + tx];
    __syncthreads();
    for (int j = ty; j < 32; j += 8)
        out[(size_t)(n0 + j) * K + k0 + tx] = __float2half(t[tx][j]);
}

__global__ void split_wf2(const float* __restrict__ Wa, const float* __restrict__ Wb,
                          __half* __restrict__ out)
{
    __shared__ float t[32][33];
    const int z = blockIdx.z;
    const float* W = (z == 0) ? Wa : Wb;
    __half* O = out + (size_t)z * 2 * HID * HID;
    int n0 = blockIdx.x * 32, k0 = blockIdx.y * 32;
    int tx = threadIdx.x, ty = threadIdx.y;
    for (int j = ty; j < 32; j += 8)
        t[j][tx] = W[(size_t)(k0 + j) * HID + n0 + tx];
    __syncthreads();
    for (int j = ty; j < 32; j += 8)
        O[(size_t)(n0 + j) * (2 * HID) + k0 + tx] = __float2half(t[tx][j]);
}

// ================= fp16 QKV projection GEMM (batched z = 0,1,2) =================
#define GSTRIDE 72
#define GBUF (128 * GSTRIDE)
#define FSTAGE (2 * GBUF)

__global__ __launch_bounds__(256) void gemm_qkv(
    const __half* __restrict__ Aq, const __half* __restrict__ Ak,
    const __half* __restrict__ Av, const __half* __restrict__ Bw,
    const float* __restrict__ bq, const float* __restrict__ bk,
    const float* __restrict__ bv,
    __half* __restrict__ oq, __half* __restrict__ ok, __half* __restrict__ ov)
{
    extern __shared__ __half smh[];
    const int tid = threadIdx.x;
    const int w = tid >> 5, l = tid & 31;
    const int z = blockIdx.z;
    const int m0 = blockIdx.y * 128;
    const int n0 = blockIdx.x * 128;
    const int wm = (w >> 2) * 64;
    const int wn = (w & 3) * 32;

    const __half* A = (z == 0) ? Aq : (z == 1) ? Ak : Av;
    const int lda = (z == 0) ? 2 * HID : HID;
    const __half* B = Bw + (size_t)z * HID * HID;
    const float* bias = (z == 0) ? bq : (z == 1) ? bk : bv;
    const float scale = (z == 0) ? 0.125f : 1.f;
    __half* out = (z == 0) ? oq : (z == 1) ? ok : ov;

    float c[4][4][4];
    #pragma unroll
    for (int i = 0; i < 4; i++)
        #pragma unroll
        for (int j = 0; j < 4; j++)
            #pragma unroll
            for (int q = 0; q < 4; q++) c[i][j][q] = 0.f;

    const uint32_t sbase = smem_u32(smh);
    const int aRow = wm + (l & 15), aKof = (l >> 4) * 8;
    const int bRow = wn + (l >> 4) * 8 + (l & 7), bKof = ((l >> 3) & 1) * 8;
    const int nChunks = HID >> 6;

    auto issue = [&](int ch) {
        const uint32_t dstBase = sbase + (uint32_t)((ch & 1) * FSTAGE * 2);
        const int k0 = ch << 6;
        #pragma unroll
        for (int i = 0; i < 4; i++) {
            int t = tid + i * 256;
            int row = t >> 3, c8 = (t & 7) * 8;
            uint32_t d = dstBase + (uint32_t)((row * GSTRIDE + c8) * 2);
            cp16(d,            A + (size_t)(m0 + row) * lda + k0 + c8);
            cp16(d + GBUF * 2, B + (size_t)(n0 + row) * HID + k0 + c8);
        }
    };

    issue(0); CP_COMMIT();
    for (int ch = 0; ch < nChunks; ch++) {
        CP_WAIT0();
        __syncthreads();
        if (ch + 1 < nChunks) { issue(ch + 1); CP_COMMIT(); }

        const uint32_t sb = sbase + (uint32_t)((ch & 1) * FSTAGE * 2);
        const uint32_t aB = sb + (uint32_t)((aRow * GSTRIDE + aKof) * 2);
        const uint32_t bB = sb + GBUF * 2 + (uint32_t)((bRow * GSTRIDE + bKof) * 2);

        #pragma unroll
        for (int ks = 0; ks < 4; ks++) {
            const uint32_t kb = (uint32_t)(ks * 16 * 2);
            uint32_t ah[4][4], bh[2][4];
            #pragma unroll
            for (int mi = 0; mi < 4; mi++)
                ldsm_x4(ah[mi], aB + (uint32_t)(mi * 16 * GSTRIDE * 2) + kb);
            #pragma unroll
            for (int p = 0; p < 2; p++)
                ldsm_x4(bh[p], bB + (uint32_t)(p * 16 * GSTRIDE * 2) + kb);
            #pragma unroll
            for (int mi = 0; mi < 4; mi++) {
                #pragma unroll
                for (int nj = 0; nj < 4; nj++) {
                    const int p = nj >> 1, s = (nj & 1) * 2;
                    mma16816h(c[mi][nj], ah[mi], bh[p][s], bh[p][s + 1]);
                }
            }
        }
        __syncthreads();
    }

    #pragma unroll
    for (int mi = 0; mi < 4; mi++) {
        int r0 = m0 + wm + mi * 16 + (l >> 2);
        #pragma unroll
        for (int nj = 0; nj < 4; nj++) {
            int col = n0 + wn + nj * 8 + (l & 3) * 2;
            float b0 = bias[col], b1 = bias[col + 1];
            #pragma unroll
            for (int half = 0; half < 2; half++) {
                int r = r0 + half * 8;
                float v0 = (c[mi][nj][half * 2 + 0] + b0) * scale;
                float v1 = (c[mi][nj][half * 2 + 1] + b1) * scale;
                *(__half2*)(out + (size_t)r * HID + col) =
                    __halves2half2(__float2half(v0), __float2half(v1));
            }
        }
    }
}

// ================= fp16 single-term GEMM (Wo) =================
__global__ __launch_bounds__(256) void gemm_fp16(
    const __half* __restrict__ A, int lda, const __half* __restrict__ B,
    int Kdim, const float* __restrict__ bias,
    __half* __restrict__ Ch, int ldch)
{
    extern __shared__ __half smh[];
    const int tid = threadIdx.x;
    const int w = tid >> 5, l = tid & 31;
    const int m0 = blockIdx.y * 128;
    const int n0 = blockIdx.x * 128;
    const int wm = (w >> 2) * 64;
    const int wn = (w & 3) * 32;

    float c[4][4][4];
    #pragma unroll
    for (int i = 0; i < 4; i++)
        #pragma unroll
        for (int j = 0; j < 4; j++)
            #pragma unroll
            for (int q = 0; q < 4; q++) c[i][j][q] = 0.f;

    const uint32_t sbase = smem_u32(smh);
    const int aRow = wm + (l & 15), aKof = (l >> 4) * 8;
    const int bRow = wn + (l >> 4) * 8 + (l & 7), bKof = ((l >> 3) & 1) * 8;
    const int nChunks = Kdim >> 6;

    auto issue = [&](int ch) {
        const uint32_t dstBase = sbase + (uint32_t)((ch & 1) * FSTAGE * 2);
        const int k0 = ch << 6;
        #pragma unroll
        for (int i = 0; i < 4; i++) {
            int t = tid + i * 256;
            int row = t >> 3, c8 = (t & 7) * 8;
            uint32_t d = dstBase + (uint32_t)((row * GSTRIDE + c8) * 2);
            cp16(d,            A + (size_t)(m0 + row) * lda  + k0 + c8);
            cp16(d + GBUF * 2, B + (size_t)(n0 + row) * Kdim + k0 + c8);
        }
    };

    issue(0); CP_COMMIT();
    for (int ch = 0; ch < nChunks; ch++) {
        CP_WAIT0();
        __syncthreads();
        if (ch + 1 < nChunks) { issue(ch + 1); CP_COMMIT(); }

        const uint32_t sb = sbase + (uint32_t)((ch & 1) * FSTAGE * 2);
        const uint32_t aB = sb + (uint32_t)((aRow * GSTRIDE + aKof) * 2);
        const uint32_t bB = sb + GBUF * 2 + (uint32_t)((bRow * GSTRIDE + bKof) * 2);

        #pragma unroll
        for (int ks = 0; ks < 4; ks++) {
            const uint32_t kb = (uint32_t)(ks * 16 * 2);
            uint32_t ah[4][4], bh[2][4];
            #pragma unroll
            for (int mi = 0; mi < 4; mi++)
                ldsm_x4(ah[mi], aB + (uint32_t)(mi * 16 * GSTRIDE * 2) + kb);
            #pragma unroll
            for (int p = 0; p < 2; p++)
                ldsm_x4(bh[p], bB + (uint32_t)(p * 16 * GSTRIDE * 2) + kb);
            #pragma unroll
            for (int mi = 0; mi < 4; mi++) {
                #pragma unroll
                for (int nj = 0; nj < 4; nj++) {
                    const int p = nj >> 1, s = (nj & 1) * 2;
                    mma16816h(c[mi][nj], ah[mi], bh[p][s], bh[p][s + 1]);
                }
            }
        }
        __syncthreads();
    }

    #pragma unroll
    for (int mi = 0; mi < 4; mi++) {
        int r0 = m0 + wm + mi * 16 + (l >> 2);
        #pragma unroll
        for (int nj = 0; nj < 4; nj++) {
            int col = n0 + wn + nj * 8 + (l & 3) * 2;
            float b0 = bias[col], b1 = bias[col + 1];
            #pragma unroll
            for (int half = 0; half < 2; half++) {
                int r = r0 + half * 8;
                float v0 = c[mi][nj][half * 2 + 0] + b0;
                float v1 = c[mi][nj][half * 2 + 1] + b1;
                *(__half2*)(Ch + (size_t)r * ldch + col) =
                    __halves2half2(__float2half(v0), __float2half(v1));
            }
        }
    }
}

// ================= fused FFN: out = sigmoid(cat@W1+b1) * (cat@W2+b2) =================
// smem: 2 stages x (A + B1 + B2) buffers of 128x72 fp16 each
#define E3STG (3 * GBUF)

__global__ __launch_bounds__(256) void gemm_ffn(
    const __half* __restrict__ A, const __half* __restrict__ B1,
    const __half* __restrict__ B2,
    const float* __restrict__ b1p, const float* __restrict__ b2p,
    float* __restrict__ Cf)
{
    extern __shared__ __half smh[];
    const int tid = threadIdx.x;
    const int w = tid >> 5, l = tid & 31;
    const int m0 = blockIdx.y * 128;
    const int n0 = blockIdx.x * 128;
    const int wm = (w >> 2) * 64;
    const int wn = (w & 3) * 32;
    const int Kdim = 2 * HID;

    float c1[4][4][4], c2[4][4][4];
    #pragma unroll
    for (int i = 0; i < 4; i++)
        #pragma unroll
        for (int j = 0; j < 4; j++)
            #pragma unroll
            for (int q = 0; q < 4; q++) { c1[i][j][q] = 0.f; c2[i][j][q] = 0.f; }

    const uint32_t sbase = smem_u32(smh);
    const int aRow = wm + (l & 15), aKof = (l >> 4) * 8;
    const int bRow = wn + (l >> 4) * 8 + (l & 7), bKof = ((l >> 3) & 1) * 8;
    const int nChunks = Kdim >> 6;   // 24

    auto issue = [&](int ch) {
        const uint32_t dstBase = sbase + (uint32_t)((ch & 1) * E3STG * 2);
        const int k0 = ch << 6;
        #pragma unroll
        for (int i = 0; i < 4; i++) {
            int t = tid + i * 256;
            int row = t >> 3, c8 = (t & 7) * 8;
            uint32_t d = dstBase + (uint32_t)((row * GSTRIDE + c8) * 2);
            cp16(d,                A  + (size_t)(m0 + row) * Kdim + k0 + c8);
            cp16(d + GBUF * 2,     B1 + (size_t)(n0 + row) * Kdim + k0 + c8);
            cp16(d + 2 * GBUF * 2, B2 + (size_t)(n0 + row) * Kdim + k0 + c8);
        }
    };

    issue(0); CP_COMMIT();
    for (int ch = 0; ch < nChunks; ch++) {
        CP_WAIT0();
        __syncthreads();
        if (ch + 1 < nChunks) { issue(ch + 1); CP_COMMIT(); }

        const uint32_t sb = sbase + (uint32_t)((ch & 1) * E3STG * 2);
        const uint32_t aB  = sb + (uint32_t)((aRow * GSTRIDE + aKof) * 2);
        const uint32_t b1B = sb + GBUF * 2 + (uint32_t)((bRow * GSTRIDE + bKof) * 2);
        const uint32_t b2B = b1B + GBUF * 2;

        #pragma unroll
        for (int ks = 0; ks < 4; ks++) {
            const uint32_t kb = (uint32_t)(ks * 16 * 2);
            uint32_t ah[4][4], bh1[2][4], bh2[2][4];
            #pragma unroll
            for (int mi = 0; mi < 4; mi++)
                ldsm_x4(ah[mi], aB + (uint32_t)(mi * 16 * GSTRIDE * 2) + kb);
            #pragma unroll
            for (int p = 0; p < 2; p++) {
                ldsm_x4(bh1[p], b1B + (uint32_t)(p * 16 * GSTRIDE * 2) + kb);
                ldsm_x4(bh2[p], b2B + (uint32_t)(p * 16 * GSTRIDE * 2) + kb);
            }
            #pragma unroll
            for (int mi = 0; mi < 4; mi++) {
                #pragma unroll
                for (int nj = 0; nj < 4; nj++) {
                    const int p = nj >> 1, s = (nj & 1) * 2;
                    mma16816h(c1[mi][nj], ah[mi], bh1[p][s], bh1[p][s + 1]);
                    mma16816h(c2[mi][nj], ah[mi], bh2[p][s], bh2[p][s + 1]);
                }
            }
        }
        __syncthreads();
    }

    #pragma unroll
    for (int mi = 0; mi < 4; mi++) {
        int r0 = m0 + wm + mi * 16 + (l >> 2);
        #pragma unroll
        for (int nj = 0; nj < 4; nj++) {
            int col = n0 + wn + nj * 8 + (l & 3) * 2;
            float bb1a = b1p[col], bb1b = b1p[col + 1];
            float bb2a = b2p[col], bb2b = b2p[col + 1];
            #pragma unroll
            for (int half = 0; half < 2; half++) {
                int r = r0 + half * 8;
                float g0 = c1[mi][nj][half * 2 + 0] + bb1a;
                float g1 = c1[mi][nj][half * 2 + 1] + bb1b;
                float v0 = c2[mi][nj][half * 2 + 0] + bb2a;
                float v1 = c2[mi][nj][half * 2 + 1] + bb2b;
                v0 *= 1.f / (1.f + __expf(-g0));
                v1 *= 1.f / (1.f + __expf(-g1));
                *(float2*)(Cf + (size_t)r * HID + col) = make_float2(v0, v1);
            }
        }
    }
}

// ================= attention v6: flash-style inline PV, 64-query tiles =================
// smem bytes:
//   sQ  [0, 9216)                 : 64 x 72 fp16
//   stages 2 x 36864 [9216, 82944): per stage: K 128x72 (18432) + V 128x72 (18432)
//   sE  [82944, 215040)           : 64 x 1032 fp16 (for prob output only)
//   sMask [215040, 219136)        : 1024 int
//   sInv  [219136, 219392)        : 64 float
//   sPart overlays stage region after main loop (3 x 64 x 64 floats = 49152 B)
#define EST 1032
#define KVST 72
#define CSTG 18432
#define ASTG 36864
#define ATTN_SMEM 219392

__global__ __launch_bounds__(512) void attn_mma(
    const __half* __restrict__ qf, const __half* __restrict__ kpf,
    const __half* __restrict__ vpf,
    const int* __restrict__ mask, float* __restrict__ attn_out,
    __half* __restrict__ xf)
{
    extern __shared__ char sab[];
    __half* sQ = (__half*)(sab);
    __half* sE = (__half*)(sab + 82944);
    int*   sMask = (int*)(sab + 215040);
    float* sInv  = (float*)(sab + 219136);
    float* sPart = (float*)(sab + 9216);

    const int tid = threadIdx.x, w = tid >> 5, l = tid & 31;
    const int q0 = blockIdx.x * 64, h = blockIdx.y, b = blockIdx.z;

    const uint32_t uQ  = smem_u32(sab);
    const uint32_t uK0 = uQ + 9216;

    // load Q tile (64 x 64 fp16)
    {
        int r = tid >> 3, c8 = (tid & 7) * 8;
        size_t g = ((size_t)(b * SS + q0 + r)) * HID + h * HD + c8;
        *(uint4*)(sQ + r * KVST + c8) = *(const uint4*)(qf + g);
    }
    for (int k = tid; k < SS; k += 512) sMask[k] = mask[b * SS + k];

    const int mg = w & 3;           // 16-query row group
    const int sub = w >> 2;         // 32-key slice within 128-key chunk
    const int bRowL = (l >> 4) * 8 + (l & 7);
    const int bKofL = ((l >> 3) & 1) * 8;
    const uint32_t aLaneOff = (uint32_t)(((mg * 16 + (l & 15)) * KVST + (l >> 4) * 8) * 2);

    // issue one 128-key chunk (K + V) into stage st
    auto issueKV = [&](int chunk, int st) {
        const uint32_t dst = uK0 + (uint32_t)(st * ASTG);
        const int r0 = chunk * 128;
        #pragma unroll
        for (int i = 0; i < 2; i++) {
            int t = tid + i * 512;
            int row = t >> 3, c8 = (t & 7) * 8;
            uint32_t d = dst + (uint32_t)((row * KVST + c8) * 2);
            size_t g = ((size_t)(b * SS + r0 + row)) * HID + h * HD + c8;
            cp16(d,        kpf + g);
            cp16(d + CSTG, vpf + g);
        }
    };

    // x accumulator: 16q x 64d per warp (this warp's key slice)
    float xa[8][4];
    #pragma unroll
    for (int j = 0; j < 8; j++)
        #pragma unroll
        for (int q = 0; q < 4; q++) xa[j][q] = 0.f;

    // ---------- main loop: 8 chunks x 128 keys; QK -> exp -> (sE store + inline PV) ----------
    issueKV(0, 0); CP_COMMIT();
    for (int ch = 0; ch < 8; ch++) {
        CP_WAIT0();
        __syncthreads();
        if (ch < 7) { issueKV(ch + 1, (ch + 1) & 1); CP_COMMIT(); }

        const uint32_t sbK = uK0 + (uint32_t)((ch & 1) * ASTG);
        const uint32_t sbV = sbK + CSTG;
        const int kw0 = ch * 128 + sub * 32;

        // --- QK^T for this warp's 16q x 32k slice ---
        float ea[2][2][4];
        #pragma unroll
        for (int p = 0; p < 2; p++)
            #pragma unroll
            for (int t = 0; t < 2; t++)
                #pragma unroll
                for (int q = 0; q < 4; q++) ea[p][t][q] = 0.f;

        #pragma unroll
        for (int ks = 0; ks < 4; ks++) {
            uint32_t ah[4], bk[2][4];
            ldsm_x4(ah, uQ + aLaneOff + (uint32_t)(ks * 16 * 2));
            #pragma unroll
            for (int p = 0; p < 2; p++)
                ldsm_x4(bk[p], sbK + (uint32_t)(((sub * 32 + p * 16 + bRowL) * KVST + ks * 16 + bKofL) * 2));
            #pragma unroll
            for (int p = 0; p < 2; p++) {
                #pragma unroll
                for (int t = 0; t < 2; t++)
                    mma16816h(ea[p][t], ah, bk[p][t * 2], bk[p][t * 2 + 1]);
            }
        }

        // --- epilogue: mask + exp; store to sE and pack A-fragments for PV ---
        uint32_t aF[2][4];
        #pragma unroll
        for (int p = 0; p < 2; p++) {
            #pragma unroll
            for (int t = 0; t < 2; t++) {
                int kcol = kw0 + p * 16 + t * 8 + (l & 3) * 2;
                int mk0 = sMask[kcol], mk1 = sMask[kcol + 1];
                #pragma unroll
                for (int hf = 0; hf < 2; hf++) {
                    int row = mg * 16 + (l >> 2) + hf * 8;
                    float e0 = mk0 ? __expf(fminf(ea[p][t][hf * 2 + 0], 11.f)) : 0.f;
                    float e1 = mk1 ? __expf(fminf(ea[p][t][hf * 2 + 1], 11.f)) : 0.f;
                    __half2 h2 = __halves2half2(__float2half(e0), __float2half(e1));
                    *(__half2*)(sE + row * EST + kcol) = h2;
                    aF[p][t * 2 + hf] = *(uint32_t*)&h2;
                }
            }
        }

        // --- inline PV: xa += e_chunk @ V_chunk (16q x 32k x 64d) ---
        #pragma unroll
        for (int p = 0; p < 2; p++) {
            #pragma unroll
            for (int dt = 0; dt < 4; dt++) {
                uint32_t bv[4];
                ldsm_x4_t(bv, sbV + (uint32_t)(((sub * 32 + p * 16 + (l & 15)) * KVST + dt * 16 + (l >> 4) * 8) * 2));
                mma16816h(xa[dt * 2 + 0], aF[p], bv[0], bv[1]);
                mma16816h(xa[dt * 2 + 1], aF[p], bv[2], bv[3]);
            }
        }
    }
    __syncthreads();

    // ---------- Phase B: row sums + prob write ----------
    #pragma unroll
    for (int r = w * 4; r < w * 4 + 4; r++) {
        const __half* eh = sE + r * EST;
        uint32_t buf[16];
        float sum = 0.f;
        #pragma unroll
        for (int i = 0; i < 16; i++) {
            buf[i] = *(const uint32_t*)(eh + i * 64 + l * 2);
            __half2 v = *(__half2*)&buf[i];
            sum += __half2float(v.x) + __half2float(v.y);
        }
        #pragma unroll
        for (int o = 16; o > 0; o >>= 1) sum += __shfl_xor_sync(0xffffffffu, sum, o);
        float inv = 1.f / sum;
        if (l == 0) sInv[r] = inv;
        float* orow = attn_out + ((size_t)((b * NH + h) * SS + q0 + r)) * SS;
        #pragma unroll
        for (int i = 0; i < 16; i++) {
            __half2 v = *(__half2*)&buf[i];
            *(float2*)(orow + i * 64 + l * 2) =
                make_float2(__half2float(v.x) * inv, __half2float(v.y) * inv);
        }
    }
    __syncthreads();

    // ---------- x reduction over 4 key-slices (sub) via smem overlay ----------
    if (sub > 0) {
        float* dst = sPart + (sub - 1) * 4096;
        #pragma unroll
        for (int j = 0; j < 8; j++)
            #pragma unroll
            for (int v = 0; v < 4; v++) {
                int row = mg * 16 + (l >> 2) + (v >> 1) * 8;
                int col = (j >> 1) * 16 + (j & 1) * 8 + (l & 3) * 2 + (v & 1);
                dst[row * 64 + col] = xa[j][v];
            }
    }
    __syncthreads();
    if (sub == 0) {
        #pragma unroll
        for (int j = 0; j < 8; j++) {
            #pragma unroll
            for (int hf = 0; hf < 2; hf++) {
                int row = mg * 16 + (l >> 2) + hf * 8;
                int col = (j >> 1) * 16 + (j & 1) * 8 + (l & 3) * 2;
                float inv = sInv[row];
                float x0 = xa[j][hf * 2 + 0];
                float x1 = xa[j][hf * 2 + 1];
                #pragma unroll
                for (int p = 0; p < 3; p++) {
                    x0 += sPart[p * 4096 + row * 64 + col];
                    x1 += sPart[p * 4096 + row * 64 + col + 1];
                }
                x0 *= inv; x1 *= inv;
                size_t g = ((size_t)(b * SS + q0 + row)) * HID + h * HD + col;
                *(__half2*)(xf + g) = __halves2half2(__float2half(x0), __float2half(x1));
            }
        }
    }
}

// ================= launch =================
extern "C" void kernel_launch(void* const* d_in, const int* in_sizes, int n_in,
                              void* d_out, int out_size)
{
    const float* query = (const float*)d_in[0];
    const float* key_t = (const float*)d_in[1];
    const float* value = (const float*)d_in[2];
    const int*   mask  = (const int*)d_in[3];
    const float* Wq = (const float*)d_in[4];  const float* bq = (const float*)d_in[5];
    const float* Wk = (const float*)d_in[6];  const float* bk = (const float*)d_in[7];
    const float* Wv = (const float*)d_in[8];  const float* bv = (const float*)d_in[9];
    const float* Wo = (const float*)d_in[10]; const float* bo = (const float*)d_in[11];
    const float* W1 = (const float*)d_in[12]; const float* b1 = (const float*)d_in[13];
    const float* W2 = (const float*)d_in[14]; const float* b2 = (const float*)d_in[15];

    float* out       = (float*)d_out;
    float* out_gated = out;
    float* out_attn  = out + MH;

    __half *kf, *vf, *qfp, *kpf, *vpf, *xf, *cat, *wqk, *wfo, *wf;
    cudaGetSymbolAddress((void**)&kf, g_kf);
    cudaGetSymbolAddress((void**)&vf, g_vf);
    cudaGetSymbolAddress((void**)&qfp, g_qf);
    cudaGetSymbolAddress((void**)&kpf, g_kpf);
    cudaGetSymbolAddress((void**)&vpf, g_vpf);
    cudaGetSymbolAddress((void**)&xf, g_xf);
    cudaGetSymbolAddress((void**)&cat, g_cat);
    cudaGetSymbolAddress((void**)&wqk, g_wqk);
    cudaGetSymbolAddress((void**)&wfo, g_wfo);
    cudaGetSymbolAddress((void**)&wf, g_wf);

    size_t fsmem = (size_t)2 * FSTAGE * 2;   // 73728 B
    size_t esmem = (size_t)2 * E3STG * 2;    // 110592 B
    cudaFuncSetAttribute(gemm_qkv, cudaFuncAttributeMaxDynamicSharedMemorySize, (int)fsmem);
    cudaFuncSetAttribute(gemm_fp16, cudaFuncAttributeMaxDynamicSharedMemorySize, (int)fsmem);
    cudaFuncSetAttribute(gemm_ffn, cudaFuncAttributeMaxDynamicSharedMemorySize, (int)esmem);
    cudaFuncSetAttribute(attn_mma, cudaFuncAttributeMaxDynamicSharedMemorySize, ATTN_SMEM);

    const int actBlocks = (MROWS * HID / 4 + 255) / 256;
    dim3 wblk(32, 8);
    dim3 ggrid(HID / 128, MROWS / 128);      // (6, 64)

    // --- input conversions + weight splits ---
    conv3<<<dim3(actBlocks, 3), 256>>>(query, key_t, value, cat, kf, vf);
    split_wqk3<<<dim3(HID / 32, HID / 32, 3), wblk>>>(Wq, Wk, Wv, wqk);

    // --- QKV projections (fp16 single-term; Q pre-scaled 1/8) ---
    gemm_qkv<<<dim3(HID / 128, MROWS / 128, 3), 256, fsmem>>>(
        cat + HID, kf, vf, wqk, bq, bk, bv, qfp, kpf, vpf);

    // --- attention (flash-style inline PV) ---
    attn_mma<<<dim3(SS / 64, NH, BB), 512, ATTN_SMEM>>>(
        qfp, kpf, vpf, mask, out_attn, xf);

    // --- Wo (fp16) -> cat[:, 0:768] ---
    split_w_fp16<<<dim3(HID / 32, HID / 32), wblk>>>(Wo, HID, HID, wfo);
    gemm_fp16<<<ggrid, 256, fsmem>>>(
        xf, HID, wfo, HID, bo, cat, 2 * HID);

    // --- fused FFN (fp16, K=1536): out = sigmoid(cat@W1+b1) * (cat@W2+b2) ---
    split_wf2<<<dim3(HID / 32, 2 * HID / 32, 2), wblk>>>(W1, W2, wf);
    gemm_ffn<<<ggrid, 256, esmem>>>(
        cat, wf, wf + (size_t)2 * HID * HID, b1, b2, out_gated);
}